// round 1
// baseline (speedup 1.0000x reference)
#include <cuda_runtime.h>
#include <math.h>

#define Bb    2
#define CIN   256
#define FF    512
#define COUT  256
#define NH    8
#define DH    64
#define NTOK  2048      // T*H*W
#define TB    128       // H*W  (time block == mask granularity)
#define Tt    16
#define INV_TEMP (1.0f/16.0f)
#define BN_EPS 1e-5f

// ---------------- scratch (device globals, no allocation) ----------------
__device__ float g_K [Bb*FF*NTOK];
__device__ float g_Q [Bb*FF*NTOK];
__device__ float g_V [Bb*FF*NTOK];
__device__ float g_Vo[Bb*FF*NTOK];
__device__ float g_y [Bb*COUT*NTOK];
__device__ float g_mean[COUT];
__device__ float g_istd[COUT];

// ---------------- generic tiled GEMM: C[b] = W(MxK) * X[b](KxN) ----------
// grid (N/64, M/64, B), block 256 (16x16), each thread 4x4 (strided frags)
template<int M, int N, int KD, bool EPI>
__global__ __launch_bounds__(256) void gemm_kernel(
    const float* __restrict__ W, const float* __restrict__ X,
    float* __restrict__ C, const float* __restrict__ bias,
    const float* __restrict__ skip)
{
    __shared__ float As[16*65];   // As[k*65+m], m in [0,64)
    __shared__ float Bs[16*64];   // Bs[k*64+n]

    const int b  = blockIdx.z;
    const float* Xb = X + (size_t)b*KD*N;
    float* Cb       = C + (size_t)b*M*N;
    const float* Sb = EPI ? (skip + (size_t)b*M*N) : nullptr;

    const int n0 = blockIdx.x*64, m0 = blockIdx.y*64;
    const int tx = threadIdx.x & 15, ty = threadIdx.x >> 4;

    float acc[4][4];
    #pragma unroll
    for (int i=0;i<4;i++)
        #pragma unroll
        for (int j=0;j<4;j++) acc[i][j]=0.f;

    for (int k0=0; k0<KD; k0+=16) {
        for (int idx=threadIdx.x; idx<1024; idx+=256) {
            int k = idx & 15, m = idx >> 4;
            As[k*65+m] = W[(size_t)(m0+m)*KD + k0 + k];
        }
        for (int idx=threadIdx.x; idx<1024; idx+=256) {
            int n = idx & 63, k = idx >> 6;
            Bs[k*64+n] = Xb[(size_t)(k0+k)*N + n0 + n];
        }
        __syncthreads();
        #pragma unroll
        for (int k=0;k<16;k++) {
            float a[4], bv[4];
            #pragma unroll
            for (int i=0;i<4;i++) a[i]  = As[k*65 + ty + 16*i];
            #pragma unroll
            for (int j=0;j<4;j++) bv[j] = Bs[k*64 + tx + 16*j];
            #pragma unroll
            for (int i=0;i<4;i++)
                #pragma unroll
                for (int j=0;j<4;j++) acc[i][j] = fmaf(a[i], bv[j], acc[i][j]);
        }
        __syncthreads();
    }

    #pragma unroll
    for (int i=0;i<4;i++) {
        int m = m0 + ty + 16*i;
        #pragma unroll
        for (int j=0;j<4;j++) {
            int n = n0 + tx + 16*j;
            float v = acc[i][j];
            if (EPI) {
                v += bias[m];
                v = fmaxf(v, 0.f);
                v += Sb[(size_t)m*N + n];
            }
            Cb[(size_t)m*N + n] = v;
        }
    }
}

// ---------------- attention: flash-style, block-causal at TB granularity --
// grid (Tt, NH, Bb), block 256. Tile of 128 key-rows i; loop j-tiles 0..it.
// S[r][c] = K_i . Q_j * (1/T);  softmax over c (online);  O[d][r] += P*V.
__global__ __launch_bounds__(256) void attn_kernel(
    const float* __restrict__ K, const float* __restrict__ Q,
    const float* __restrict__ V, float* __restrict__ Vo)
{
    extern __shared__ float sm[];
    float* Ks  = sm;                 // [128][65]
    float* Qs  = Ks  + 128*65;       // [128][65]
    float* Vs  = Qs  + 128*65;       // [64][128]
    float* Ssm = Vs  + 64*128;       // [128][129]
    float* red = Ssm + 128*129;      // [128][16]
    float* mrow= red + 128*16;       // [128]
    float* lrow= mrow+ 128;          // [128]
    float* arow= lrow+ 128;          // [128]

    const int it = blockIdx.x, h = blockIdx.y, b = blockIdx.z;
    const int i0 = it*TB;
    const size_t base = ((size_t)b*FF + (size_t)h*DH) * NTOK;

    const int tid = threadIdx.x;
    const int tx = tid & 15, ty = tid >> 4;

    // load K tile (scaled by 1/TEMP): Ks[r][d]
    for (int idx=tid; idx<TB*DH; idx+=256) {
        int d = idx >> 7, r = idx & 127;
        Ks[r*65+d] = K[base + (size_t)d*NTOK + i0 + r] * INV_TEMP;
    }
    if (tid < TB) { mrow[tid] = -INFINITY; lrow[tid] = 0.f; }

    float of[4][8];   // O[d=ty+16*dd][r=tx+16*rr]
    #pragma unroll
    for (int dd=0;dd<4;dd++)
        #pragma unroll
        for (int rr=0;rr<8;rr++) of[dd][rr]=0.f;

    for (int jt=0; jt<=it; jt++) {
        const int j0 = jt*TB;
        __syncthreads();   // protect Qs/Vs reuse + first-iter K/m/l init
        for (int idx=tid; idx<TB*DH; idx+=256) {
            int d = idx >> 7, c = idx & 127;
            Qs[c*65+d] = Q[base + (size_t)d*NTOK + j0 + c];
        }
        for (int idx=tid; idx<TB*DH; idx+=256) {
            int d = idx >> 7, c = idx & 127;
            Vs[d*128+c] = V[base + (size_t)d*NTOK + j0 + c];
        }
        __syncthreads();

        // S fragment: rows r=ty+16*rr, cols c=tx+16*cc
        float sf[8][8];
        #pragma unroll
        for (int rr=0;rr<8;rr++)
            #pragma unroll
            for (int cc=0;cc<8;cc++) sf[rr][cc]=0.f;
        #pragma unroll 4
        for (int d=0; d<DH; d++) {
            float kv[8], qv[8];
            #pragma unroll
            for (int rr=0;rr<8;rr++) kv[rr] = Ks[(ty+16*rr)*65 + d];
            #pragma unroll
            for (int cc=0;cc<8;cc++) qv[cc] = Qs[(tx+16*cc)*65 + d];
            #pragma unroll
            for (int rr=0;rr<8;rr++)
                #pragma unroll
                for (int cc=0;cc<8;cc++) sf[rr][cc] = fmaf(kv[rr], qv[cc], sf[rr][cc]);
        }

        // per-thread row max -> cross-tx reduce
        #pragma unroll
        for (int rr=0;rr<8;rr++) {
            float rm = sf[rr][0];
            #pragma unroll
            for (int cc=1;cc<8;cc++) rm = fmaxf(rm, sf[rr][cc]);
            red[(ty+16*rr)*16 + tx] = rm;
        }
        __syncthreads();
        if (tid < TB) {
            float tm = red[tid*16];
            #pragma unroll
            for (int t=1;t<16;t++) tm = fmaxf(tm, red[tid*16+t]);
            float mo = mrow[tid];
            float mn = fmaxf(mo, tm);
            arow[tid] = __expf(mo - mn);   // 0 when mo==-inf
            mrow[tid] = mn;
        }
        __syncthreads();

        // P = exp(S - m); store to Ssm; partial row sums; rescale O
        #pragma unroll
        for (int rr=0;rr<8;rr++) {
            int r = ty + 16*rr;
            float mn = mrow[r];
            float ps = 0.f;
            #pragma unroll
            for (int cc=0;cc<8;cc++) {
                float p = __expf(sf[rr][cc] - mn);
                Ssm[r*129 + tx + 16*cc] = p;
                ps += p;
            }
            red[r*16 + tx] = ps;
        }
        #pragma unroll
        for (int rr=0;rr<8;rr++) {
            float a = arow[tx + 16*rr];
            #pragma unroll
            for (int dd=0;dd<4;dd++) of[dd][rr] *= a;
        }
        __syncthreads();
        if (tid < TB) {
            float s = 0.f;
            #pragma unroll
            for (int t=0;t<16;t++) s += red[tid*16+t];
            lrow[tid] = lrow[tid]*arow[tid] + s;
        }

        // O[d][r] += sum_c P[r][c] * V[d][c]
        #pragma unroll 4
        for (int c=0;c<TB;c++) {
            float vv[4], pv[8];
            #pragma unroll
            for (int dd=0;dd<4;dd++) vv[dd] = Vs[(ty+16*dd)*128 + c];
            #pragma unroll
            for (int rr=0;rr<8;rr++) pv[rr] = Ssm[(tx+16*rr)*129 + c];
            #pragma unroll
            for (int dd=0;dd<4;dd++)
                #pragma unroll
                for (int rr=0;rr<8;rr++) of[dd][rr] = fmaf(vv[dd], pv[rr], of[dd][rr]);
        }
    }
    __syncthreads();

    float rinv[8];
    #pragma unroll
    for (int rr=0;rr<8;rr++) rinv[rr] = 1.0f / lrow[tx + 16*rr];
    #pragma unroll
    for (int dd=0;dd<4;dd++) {
        size_t row = base + (size_t)(ty+16*dd)*NTOK + i0;
        #pragma unroll
        for (int rr=0;rr<8;rr++)
            Vo[row + tx + 16*rr] = of[dd][rr] * rinv[rr];
    }
}

// ---------------- BN stats: one block per channel ----------------
__global__ __launch_bounds__(256) void bn_stats_kernel() {
    __shared__ float ss[256], sq[256];
    const int c = blockIdx.x;
    float s=0.f, q=0.f;
    for (int idx=threadIdx.x; idx<Bb*NTOK; idx+=256) {
        int bb = idx >> 11, n = idx & 2047;
        float v = g_y[((size_t)bb*COUT + c)*NTOK + n];
        s += v; q += v*v;
    }
    ss[threadIdx.x]=s; sq[threadIdx.x]=q;
    __syncthreads();
    for (int o=128;o>0;o>>=1) {
        if (threadIdx.x < o) { ss[threadIdx.x]+=ss[threadIdx.x+o]; sq[threadIdx.x]+=sq[threadIdx.x+o]; }
        __syncthreads();
    }
    if (threadIdx.x==0) {
        float mean = ss[0]/(float)(Bb*NTOK);
        float var  = sq[0]/(float)(Bb*NTOK) - mean*mean;
        g_mean[c] = mean;
        g_istd[c] = rsqrtf(var + BN_EPS);
    }
}

__global__ __launch_bounds__(256) void bn_apply_kernel(
    const float* __restrict__ gamma, const float* __restrict__ beta,
    float* __restrict__ out)
{
    int idx = blockIdx.x*256 + threadIdx.x;
    if (idx >= Bb*COUT*NTOK) return;
    int c = (idx >> 11) & (COUT-1);
    out[idx] = (g_y[idx] - g_mean[c]) * g_istd[c] * gamma[c] + beta[c];
}

// ---------------- launch ----------------
extern "C" void kernel_launch(void* const* d_in, const int* in_sizes, int n_in,
                              void* d_out, int out_size)
{
    const float* x     = (const float*)d_in[0];
    const float* WK    = (const float*)d_in[1];
    const float* WQ    = (const float*)d_in[2];
    const float* WV    = (const float*)d_in[3];
    const float* Wo    = (const float*)d_in[4];
    const float* bo    = (const float*)d_in[5];
    const float* gamma = (const float*)d_in[6];
    const float* beta  = (const float*)d_in[7];
    float* out = (float*)d_out;

    float *pK, *pQ, *pV, *pVo, *pY;
    cudaGetSymbolAddress((void**)&pK,  g_K);
    cudaGetSymbolAddress((void**)&pQ,  g_Q);
    cudaGetSymbolAddress((void**)&pV,  g_V);
    cudaGetSymbolAddress((void**)&pVo, g_Vo);
    cudaGetSymbolAddress((void**)&pY,  g_y);

    // QKV GEMMs: (512x256)*(256x2048) per batch
    dim3 gq(NTOK/64, FF/64, Bb);
    gemm_kernel<FF, NTOK, CIN, false><<<gq, 256>>>(WK, x, pK, nullptr, nullptr);
    gemm_kernel<FF, NTOK, CIN, false><<<gq, 256>>>(WQ, x, pQ, nullptr, nullptr);
    gemm_kernel<FF, NTOK, CIN, false><<<gq, 256>>>(WV, x, pV, nullptr, nullptr);

    // attention
    size_t smem = (size_t)(128*65*2 + 64*128 + 128*129 + 128*16 + 3*128) * sizeof(float);
    cudaFuncSetAttribute(attn_kernel, cudaFuncAttributeMaxDynamicSharedMemorySize, (int)smem);
    dim3 ga(Tt, NH, Bb);
    attn_kernel<<<ga, 256, smem>>>(pK, pQ, pV, pVo);

    // output projection + bias + relu + skip
    dim3 gp(NTOK/64, COUT/64, Bb);
    gemm_kernel<COUT, NTOK, FF, true><<<gp, 256>>>(Wo, pVo, pY, bo, x);

    // batchnorm
    bn_stats_kernel<<<COUT, 256>>>();
    bn_apply_kernel<<<(Bb*COUT*NTOK + 255)/256, 256>>>(gamma, beta, out);
}

// round 2
// speedup vs baseline: 1.7179x; 1.7179x over previous
#include <cuda_runtime.h>
#include <math.h>
#include <stdint.h>

#define Bb    2
#define CIN   256
#define FF    512
#define COUT  256
#define NH    8
#define DH    64
#define NTOK  2048      // T*H*W
#define TB    128       // H*W  (mask granularity)
#define Tt    16
#define JT    64        // attention j-tile
#define INV_TEMP (1.0f/16.0f)
#define BN_EPS 1e-5f

// ---------------- scratch ----------------
__device__ float g_K [Bb*FF*NTOK];
__device__ float g_Q [Bb*FF*NTOK];
__device__ float g_V [Bb*FF*NTOK];
__device__ float g_Vo[Bb*FF*NTOK];
__device__ float g_y [Bb*COUT*NTOK];
__device__ float g_mean[COUT];
__device__ float g_istd[COUT];

// ---------------- helpers ----------------
__device__ __forceinline__ uint32_t f2tf32(float x) {
    uint32_t r;
    asm("cvt.rna.tf32.f32 %0, %1;" : "=r"(r) : "f"(x));
    return r;
}
__device__ __forceinline__ void mma_tf32(float d[4],
    uint32_t a0, uint32_t a1, uint32_t a2, uint32_t a3,
    uint32_t b0, uint32_t b1)
{
    asm volatile(
      "mma.sync.aligned.m16n8k8.row.col.f32.tf32.tf32.f32 "
      "{%0,%1,%2,%3}, {%4,%5,%6,%7}, {%8,%9}, {%0,%1,%2,%3};"
      : "+f"(d[0]), "+f"(d[1]), "+f"(d[2]), "+f"(d[3])
      : "r"(a0), "r"(a1), "r"(a2), "r"(a3), "r"(b0), "r"(b1));
}

// ---------------- generic tiled GEMM: C[b] = W(MxK) * X[b](KxN) ----------
template<int M, int N, int KD, bool EPI>
__global__ __launch_bounds__(256) void gemm_kernel(
    const float* __restrict__ W, const float* __restrict__ X,
    float* __restrict__ C, const float* __restrict__ bias,
    const float* __restrict__ skip)
{
    __shared__ float As[16*65];
    __shared__ float Bs[16*64];

    const int b  = blockIdx.z;
    const float* Xb = X + (size_t)b*KD*N;
    float* Cb       = C + (size_t)b*M*N;
    const float* Sb = EPI ? (skip + (size_t)b*M*N) : nullptr;

    const int n0 = blockIdx.x*64, m0 = blockIdx.y*64;
    const int tx = threadIdx.x & 15, ty = threadIdx.x >> 4;

    float acc[4][4];
    #pragma unroll
    for (int i=0;i<4;i++)
        #pragma unroll
        for (int j=0;j<4;j++) acc[i][j]=0.f;

    for (int k0=0; k0<KD; k0+=16) {
        for (int idx=threadIdx.x; idx<1024; idx+=256) {
            int k = idx & 15, m = idx >> 4;
            As[k*65+m] = W[(size_t)(m0+m)*KD + k0 + k];
        }
        for (int idx=threadIdx.x; idx<1024; idx+=256) {
            int n = idx & 63, k = idx >> 6;
            Bs[k*64+n] = Xb[(size_t)(k0+k)*N + n0 + n];
        }
        __syncthreads();
        #pragma unroll
        for (int k=0;k<16;k++) {
            float a[4], bv[4];
            #pragma unroll
            for (int i=0;i<4;i++) a[i]  = As[k*65 + ty + 16*i];
            #pragma unroll
            for (int j=0;j<4;j++) bv[j] = Bs[k*64 + tx + 16*j];
            #pragma unroll
            for (int i=0;i<4;i++)
                #pragma unroll
                for (int j=0;j<4;j++) acc[i][j] = fmaf(a[i], bv[j], acc[i][j]);
        }
        __syncthreads();
    }

    #pragma unroll
    for (int i=0;i<4;i++) {
        int m = m0 + ty + 16*i;
        #pragma unroll
        for (int j=0;j<4;j++) {
            int n = n0 + tx + 16*j;
            float v = acc[i][j];
            if (EPI) {
                v += bias[m];
                v = fmaxf(v, 0.f);
                v += Sb[(size_t)m*N + n];
            }
            Cb[(size_t)m*N + n] = v;
        }
    }
}

// ---------------- attention: flash-style, tf32 mma, block-causal ---------
// grid (Tt, NH, Bb), 256 threads (8 warps). i-tile 128 (warp owns 16 rows),
// j-tile 64. Softmax state (m,l) in registers (rows owned per-quad).
// S[r][c] = K_r . Q_c / TEMP; online softmax over c; O[r][d] += P*V.
__global__ __launch_bounds__(256, 2) void attn_kernel(
    const float* __restrict__ K, const float* __restrict__ Q,
    const float* __restrict__ V, float* __restrict__ Vo)
{
    extern __shared__ float sm[];
    float* Ks = sm;                  // [128][68]  (tf32 bits, pre-scaled)
    float* Qs = Ks + 128*68;         // [64][68]   rows=c (query), cols=d
    float* Vs = Qs + 64*68;          // [64][68]   rows=d, cols=c
    float* Ps = Vs + 64*68;          // 8 x [16][68]
    uint32_t* Ksu = (uint32_t*)Ks;
    uint32_t* Qsu = (uint32_t*)Qs;
    uint32_t* Vsu = (uint32_t*)Vs;

    const int it = (Tt-1) - blockIdx.x;       // heavy blocks first (LPT)
    const int h  = blockIdx.y, b = blockIdx.z;
    const int i0 = it*TB;
    const size_t base = ((size_t)b*FF + (size_t)h*DH) * NTOK;

    const int tid  = threadIdx.x;
    const int w    = tid >> 5;
    const int lane = tid & 31;
    const int g    = lane >> 2;      // row within 8-group
    const int j    = lane & 3;

    float*    Pw  = Ps + w*16*68;
    uint32_t* Pwu = (uint32_t*)Pw;
    const int wrow = w*16;

    // K tile: Ks[r][d] = tf32(K * 1/TEMP)
    for (int idx = tid; idx < 128*DH; idx += 256) {
        int d = idx >> 7, r = idx & 127;
        Ks[r*68 + d] = __uint_as_float(
            f2tf32(K[base + (size_t)d*NTOK + i0 + r] * INV_TEMP));
    }

    float m0 = -INFINITY, m1 = -INFINITY, l0 = 0.f, l1 = 0.f;
    float o[8][4];
    #pragma unroll
    for (int nt=0; nt<8; nt++)
        #pragma unroll
        for (int e=0; e<4; e++) o[nt][e] = 0.f;

    const int njt = 2*(it+1);        // 64-wide tiles allowed by block mask
    for (int jt = 0; jt < njt; jt++) {
        const int j0 = jt*JT;
        __syncthreads();             // prev Qs/Vs reads done (also covers Ks load)
        for (int idx = tid; idx < JT*DH; idx += 256) {
            int d = idx >> 6, c = idx & 63;
            float q = Q[base + (size_t)d*NTOK + j0 + c];
            float v = V[base + (size_t)d*NTOK + j0 + c];
            Qs[c*68 + d] = __uint_as_float(f2tf32(q));
            Vs[d*68 + c] = __uint_as_float(f2tf32(v));
        }
        __syncthreads();

        // ---- S = K . Q  (m16n8k8 tf32) ----
        float sf[8][4];
        #pragma unroll
        for (int nt=0; nt<8; nt++)
            #pragma unroll
            for (int e=0; e<4; e++) sf[nt][e] = 0.f;

        #pragma unroll
        for (int k0=0; k0<DH; k0+=8) {
            uint32_t a0 = Ksu[(wrow + g    )*68 + k0 + j    ];
            uint32_t a1 = Ksu[(wrow + g + 8)*68 + k0 + j    ];
            uint32_t a2 = Ksu[(wrow + g    )*68 + k0 + j + 4];
            uint32_t a3 = Ksu[(wrow + g + 8)*68 + k0 + j + 4];
            #pragma unroll
            for (int nt=0; nt<8; nt++) {
                uint32_t b0 = Qsu[(nt*8 + g)*68 + k0 + j    ];
                uint32_t b1 = Qsu[(nt*8 + g)*68 + k0 + j + 4];
                mma_tf32(sf[nt], a0, a1, a2, a3, b0, b1);
            }
        }

        // ---- online softmax (rows g, g+8 of warp slab) ----
        float tm0 = -INFINITY, tm1 = -INFINITY;
        #pragma unroll
        for (int nt=0; nt<8; nt++) {
            tm0 = fmaxf(tm0, fmaxf(sf[nt][0], sf[nt][1]));
            tm1 = fmaxf(tm1, fmaxf(sf[nt][2], sf[nt][3]));
        }
        tm0 = fmaxf(tm0, __shfl_xor_sync(0xffffffffu, tm0, 1));
        tm0 = fmaxf(tm0, __shfl_xor_sync(0xffffffffu, tm0, 2));
        tm1 = fmaxf(tm1, __shfl_xor_sync(0xffffffffu, tm1, 1));
        tm1 = fmaxf(tm1, __shfl_xor_sync(0xffffffffu, tm1, 2));

        float mn0 = fmaxf(m0, tm0), mn1 = fmaxf(m1, tm1);
        float al0 = __expf(m0 - mn0), al1 = __expf(m1 - mn1);
        m0 = mn0; m1 = mn1;

        float s0 = 0.f, s1 = 0.f;
        #pragma unroll
        for (int nt=0; nt<8; nt++) {
            sf[nt][0] = __expf(sf[nt][0] - mn0);
            sf[nt][1] = __expf(sf[nt][1] - mn0);
            sf[nt][2] = __expf(sf[nt][2] - mn1);
            sf[nt][3] = __expf(sf[nt][3] - mn1);
            s0 += sf[nt][0] + sf[nt][1];
            s1 += sf[nt][2] + sf[nt][3];
        }
        s0 += __shfl_xor_sync(0xffffffffu, s0, 1);
        s0 += __shfl_xor_sync(0xffffffffu, s0, 2);
        s1 += __shfl_xor_sync(0xffffffffu, s1, 1);
        s1 += __shfl_xor_sync(0xffffffffu, s1, 2);
        l0 = l0*al0 + s0;
        l1 = l1*al1 + s1;

        #pragma unroll
        for (int nt=0; nt<8; nt++) {
            o[nt][0] *= al0; o[nt][1] *= al0;
            o[nt][2] *= al1; o[nt][3] *= al1;
        }

        // ---- stage P (tf32) in per-warp smem ----
        #pragma unroll
        for (int nt=0; nt<8; nt++) {
            float2 p01, p23;
            p01.x = __uint_as_float(f2tf32(sf[nt][0]));
            p01.y = __uint_as_float(f2tf32(sf[nt][1]));
            p23.x = __uint_as_float(f2tf32(sf[nt][2]));
            p23.y = __uint_as_float(f2tf32(sf[nt][3]));
            *(float2*)(Pw + (g    )*68 + nt*8 + 2*j) = p01;
            *(float2*)(Pw + (g + 8)*68 + nt*8 + 2*j) = p23;
        }
        __syncwarp();

        // ---- O += P . V  (k = c tokens, n = d) ----
        #pragma unroll
        for (int k0=0; k0<JT; k0+=8) {
            uint32_t a0 = Pwu[(g    )*68 + k0 + j    ];
            uint32_t a1 = Pwu[(g + 8)*68 + k0 + j    ];
            uint32_t a2 = Pwu[(g    )*68 + k0 + j + 4];
            uint32_t a3 = Pwu[(g + 8)*68 + k0 + j + 4];
            #pragma unroll
            for (int nt=0; nt<8; nt++) {
                uint32_t b0 = Vsu[(nt*8 + g)*68 + k0 + j    ];
                uint32_t b1 = Vsu[(nt*8 + g)*68 + k0 + j + 4];
                mma_tf32(o[nt], a0, a1, a2, a3, b0, b1);
            }
        }
        __syncwarp();   // protect Pw before next tile's overwrite
    }

    // ---- epilogue: O / l -> Vo[d][i] ----
    float inv0 = 1.0f / l0, inv1 = 1.0f / l1;
    const int r0 = i0 + wrow + g, r1 = r0 + 8;
    #pragma unroll
    for (int nt=0; nt<8; nt++) {
        int d0 = nt*8 + 2*j, d1 = d0 + 1;
        Vo[base + (size_t)d0*NTOK + r0] = o[nt][0]*inv0;
        Vo[base + (size_t)d1*NTOK + r0] = o[nt][1]*inv0;
        Vo[base + (size_t)d0*NTOK + r1] = o[nt][2]*inv1;
        Vo[base + (size_t)d1*NTOK + r1] = o[nt][3]*inv1;
    }
}

// ---------------- BN stats ----------------
__global__ __launch_bounds__(256) void bn_stats_kernel() {
    __shared__ float ss[256], sq[256];
    const int c = blockIdx.x;
    float s=0.f, q=0.f;
    for (int idx=threadIdx.x; idx<Bb*NTOK; idx+=256) {
        int bb = idx >> 11, n = idx & 2047;
        float v = g_y[((size_t)bb*COUT + c)*NTOK + n];
        s += v; q += v*v;
    }
    ss[threadIdx.x]=s; sq[threadIdx.x]=q;
    __syncthreads();
    for (int o=128;o>0;o>>=1) {
        if (threadIdx.x < o) { ss[threadIdx.x]+=ss[threadIdx.x+o]; sq[threadIdx.x]+=sq[threadIdx.x+o]; }
        __syncthreads();
    }
    if (threadIdx.x==0) {
        float mean = ss[0]/(float)(Bb*NTOK);
        float var  = sq[0]/(float)(Bb*NTOK) - mean*mean;
        g_mean[c] = mean;
        g_istd[c] = rsqrtf(var + BN_EPS);
    }
}

__global__ __launch_bounds__(256) void bn_apply_kernel(
    const float* __restrict__ gamma, const float* __restrict__ beta,
    float* __restrict__ out)
{
    int idx = blockIdx.x*256 + threadIdx.x;
    if (idx >= Bb*COUT*NTOK) return;
    int c = (idx >> 11) & (COUT-1);
    out[idx] = (g_y[idx] - g_mean[c]) * g_istd[c] * gamma[c] + beta[c];
}

// ---------------- launch ----------------
extern "C" void kernel_launch(void* const* d_in, const int* in_sizes, int n_in,
                              void* d_out, int out_size)
{
    const float* x     = (const float*)d_in[0];
    const float* WK    = (const float*)d_in[1];
    const float* WQ    = (const float*)d_in[2];
    const float* WV    = (const float*)d_in[3];
    const float* Wo    = (const float*)d_in[4];
    const float* bo    = (const float*)d_in[5];
    const float* gamma = (const float*)d_in[6];
    const float* beta  = (const float*)d_in[7];
    float* out = (float*)d_out;

    float *pK, *pQ, *pV, *pVo, *pY;
    cudaGetSymbolAddress((void**)&pK,  g_K);
    cudaGetSymbolAddress((void**)&pQ,  g_Q);
    cudaGetSymbolAddress((void**)&pV,  g_V);
    cudaGetSymbolAddress((void**)&pVo, g_Vo);
    cudaGetSymbolAddress((void**)&pY,  g_y);

    dim3 gq(NTOK/64, FF/64, Bb);
    gemm_kernel<FF, NTOK, CIN, false><<<gq, 256>>>(WK, x, pK, nullptr, nullptr);
    gemm_kernel<FF, NTOK, CIN, false><<<gq, 256>>>(WQ, x, pQ, nullptr, nullptr);
    gemm_kernel<FF, NTOK, CIN, false><<<gq, 256>>>(WV, x, pV, nullptr, nullptr);

    size_t smem = (size_t)(128*68 + 64*68 + 64*68 + 8*16*68) * sizeof(float);
    cudaFuncSetAttribute(attn_kernel, cudaFuncAttributeMaxDynamicSharedMemorySize, (int)smem);
    dim3 ga(Tt, NH, Bb);
    attn_kernel<<<ga, 256, smem>>>(pK, pQ, pV, pVo);

    dim3 gp(NTOK/64, COUT/64, Bb);
    gemm_kernel<COUT, NTOK, FF, true><<<gp, 256>>>(Wo, pVo, pY, bo, x);

    bn_stats_kernel<<<COUT, 256>>>();
    bn_apply_kernel<<<(Bb*COUT*NTOK + 255)/256, 256>>>(gamma, beta, out);
}

// round 3
// speedup vs baseline: 3.0515x; 1.7763x over previous
#include <cuda_runtime.h>
#include <math.h>
#include <stdint.h>

#define Bb    2
#define CIN   256
#define FF    512
#define COUT  256
#define NH    8
#define DH    64
#define NTOK  2048
#define TB    128
#define Tt    16
#define JT    64
#define INV_TEMP (1.0f/16.0f)
#define BN_EPS 1e-5f

// ---------------- scratch ----------------
__device__ float g_K [Bb*FF*NTOK];
__device__ float g_Q [Bb*FF*NTOK];
__device__ float g_V [Bb*FF*NTOK];
__device__ float g_Vo[Bb*FF*NTOK];
__device__ float g_y [Bb*COUT*NTOK];
__device__ float g_mean[COUT];
__device__ float g_istd[COUT];

// ---------------- helpers ----------------
__device__ __forceinline__ uint32_t f2tf32(float x) {
    uint32_t r;
    asm("cvt.rna.tf32.f32 %0, %1;" : "=r"(r) : "f"(x));
    return r;
}
__device__ __forceinline__ float tf(float x) { return __uint_as_float(f2tf32(x)); }

__device__ __forceinline__ void mma_tf32(float d[4],
    uint32_t a0, uint32_t a1, uint32_t a2, uint32_t a3,
    uint32_t b0, uint32_t b1)
{
    asm volatile(
      "mma.sync.aligned.m16n8k8.row.col.f32.tf32.tf32.f32 "
      "{%0,%1,%2,%3}, {%4,%5,%6,%7}, {%8,%9}, {%0,%1,%2,%3};"
      : "+f"(d[0]), "+f"(d[1]), "+f"(d[2]), "+f"(d[3])
      : "r"(a0), "r"(a1), "r"(a2), "r"(a3), "r"(b0), "r"(b1));
}

// ---------------- tf32 GEMM mainloop: tile 128(M) x 64(N), KC=32 ----------
// Ws[128][36] (A: conflict-free 4g+j), Xs[32][72] (B: conflict-free 8j+g).
template<int KD>
__device__ __forceinline__ void gemm_mainloop(
    const float* __restrict__ Wp,   // offset to (m0, 0), row stride KD
    const float* __restrict__ Xp,   // offset to (0, n0), row stride NTOK
    float sf[8][4], float* Ws, float* Xs,
    int tid, int wrow, int g, int j)
{
    uint32_t* Wu = (uint32_t*)Ws;
    uint32_t* Xu = (uint32_t*)Xs;
    for (int kc = 0; kc < KD; kc += 32) {
        __syncthreads();
        #pragma unroll
        for (int i = 0; i < 4; i++) {
            int id = tid + i*256;            // 0..1023
            int m = id >> 3, kq = (id & 7) * 4;
            float4 w4 = *(const float4*)(Wp + (size_t)m*KD + kc + kq);
            float* dst = Ws + m*36 + kq;
            dst[0]=tf(w4.x); dst[1]=tf(w4.y); dst[2]=tf(w4.z); dst[3]=tf(w4.w);
        }
        #pragma unroll
        for (int i = 0; i < 2; i++) {
            int id = tid + i*256;            // 0..511
            int k = id >> 4, n4 = (id & 15) * 4;
            float4 x4 = *(const float4*)(Xp + (size_t)(kc+k)*NTOK + n4);
            float4 xt; xt.x=tf(x4.x); xt.y=tf(x4.y); xt.z=tf(x4.z); xt.w=tf(x4.w);
            *(float4*)(Xs + k*72 + n4) = xt;
        }
        __syncthreads();
        #pragma unroll
        for (int k0 = 0; k0 < 32; k0 += 8) {
            uint32_t a0 = Wu[(wrow+g  )*36 + k0+j  ];
            uint32_t a1 = Wu[(wrow+g+8)*36 + k0+j  ];
            uint32_t a2 = Wu[(wrow+g  )*36 + k0+j+4];
            uint32_t a3 = Wu[(wrow+g+8)*36 + k0+j+4];
            #pragma unroll
            for (int nt = 0; nt < 8; nt++) {
                uint32_t b0 = Xu[(k0+j  )*72 + nt*8+g];
                uint32_t b1 = Xu[(k0+j+4)*72 + nt*8+g];
                mma_tf32(sf[nt], a0,a1,a2,a3, b0,b1);
            }
        }
    }
}

// ---------------- fused QKV GEMM: grid (32, 12, 2) ----------------
__global__ __launch_bounds__(256) void qkv_kernel(
    const float* __restrict__ WK, const float* __restrict__ WQ,
    const float* __restrict__ WV, const float* __restrict__ X,
    float* __restrict__ Ko, float* __restrict__ Qo, float* __restrict__ Vo)
{
    __shared__ float Ws[128*36];
    __shared__ float Xs[32*72];
    const int b = blockIdx.z, mb = blockIdx.y, n0 = blockIdx.x*64;
    const int sel = mb >> 2;
    const int m0  = (mb & 3) * 128;
    const float* W = sel==0 ? WK : (sel==1 ? WQ : WV);
    float*       C = sel==0 ? Ko : (sel==1 ? Qo : Vo);
    const float scale = sel==0 ? INV_TEMP : 1.f;

    const int tid = threadIdx.x, w = tid>>5, lane = tid&31;
    const int g = lane>>2, j = lane&3, wrow = w*16;

    float sf[8][4];
    #pragma unroll
    for (int nt=0;nt<8;nt++){ sf[nt][0]=sf[nt][1]=sf[nt][2]=sf[nt][3]=0.f; }

    gemm_mainloop<CIN>(W + (size_t)m0*CIN, X + (size_t)b*CIN*NTOK + n0,
                       sf, Ws, Xs, tid, wrow, g, j);

    const size_t cbase = (size_t)b*FF*NTOK;
    #pragma unroll
    for (int nt=0; nt<8; nt++) {
        int col = n0 + nt*8 + 2*j;
        float2 v0 = { sf[nt][0]*scale, sf[nt][1]*scale };
        float2 v1 = { sf[nt][2]*scale, sf[nt][3]*scale };
        *(float2*)(C + cbase + (size_t)(m0+wrow+g  )*NTOK + col) = v0;
        *(float2*)(C + cbase + (size_t)(m0+wrow+g+8)*NTOK + col) = v1;
    }
}

// ---------------- proj GEMM + bias + relu + skip: grid (32, 2, 2) --------
__global__ __launch_bounds__(256) void proj_kernel(
    const float* __restrict__ Wo, const float* __restrict__ Vi,
    const float* __restrict__ bias, const float* __restrict__ skip,
    float* __restrict__ Y)
{
    __shared__ float Ws[128*36];
    __shared__ float Xs[32*72];
    const int b = blockIdx.z, m0 = blockIdx.y*128, n0 = blockIdx.x*64;
    const int tid = threadIdx.x, w = tid>>5, lane = tid&31;
    const int g = lane>>2, j = lane&3, wrow = w*16;

    float sf[8][4];
    #pragma unroll
    for (int nt=0;nt<8;nt++){ sf[nt][0]=sf[nt][1]=sf[nt][2]=sf[nt][3]=0.f; }

    gemm_mainloop<FF>(Wo + (size_t)m0*FF, Vi + (size_t)b*FF*NTOK + n0,
                      sf, Ws, Xs, tid, wrow, g, j);

    const int row0 = m0 + wrow + g, row1 = row0 + 8;
    const float b0v = bias[row0], b1v = bias[row1];
    const size_t ybase = (size_t)b*COUT*NTOK;
    #pragma unroll
    for (int nt=0; nt<8; nt++) {
        int col = n0 + nt*8 + 2*j;
        float2 s0 = *(const float2*)(skip + ybase + (size_t)row0*NTOK + col);
        float2 s1 = *(const float2*)(skip + ybase + (size_t)row1*NTOK + col);
        float2 y0 = { fmaxf(sf[nt][0]+b0v,0.f)+s0.x, fmaxf(sf[nt][1]+b0v,0.f)+s0.y };
        float2 y1 = { fmaxf(sf[nt][2]+b1v,0.f)+s1.x, fmaxf(sf[nt][3]+b1v,0.f)+s1.y };
        *(float2*)(Y + ybase + (size_t)row0*NTOK + col) = y0;
        *(float2*)(Y + ybase + (size_t)row1*NTOK + col) = y1;
    }
}

// ---------------- attention ----------------
// grid (Tt, NH, Bb), 256 thr. S-phase: warp w owns rows wrow..wrow+15.
// O-phase (O^T = V.P^T): warp -> d-slab (w&3)*16, r-half (w>>2)*64.
__global__ __launch_bounds__(256, 2) void attn_kernel(
    const float* __restrict__ K, const float* __restrict__ Q,
    const float* __restrict__ V, float* __restrict__ Vo)
{
    extern __shared__ float sm[];
    float* Ks   = sm;                 // [128][72], col d ^ ((r>>2)&7)
    float* Qs   = Ks + 128*72;        // [64 d][72] cols c
    float* Vs   = Qs + 64*72;         // [64 d][68] cols c
    float* Ps   = Vs + 64*68;         // [128 r][68] cols c
    float* arow = Ps + 128*68;        // [128]
    float* lrow = arow + 128;         // [128]
    uint32_t* Ksu = (uint32_t*)Ks;
    uint32_t* Qsu = (uint32_t*)Qs;
    uint32_t* Vsu = (uint32_t*)Vs;
    uint32_t* Psu = (uint32_t*)Ps;

    const int it = (Tt-1) - blockIdx.x;      // LPT
    const int h  = blockIdx.y, b = blockIdx.z;
    const int i0 = it*TB;
    const size_t base = ((size_t)b*FF + (size_t)h*DH)*NTOK;

    const int tid = threadIdx.x, w = tid>>5, lane = tid&31;
    const int g = lane>>2, j = lane&3;
    const int wrow  = w*16;
    const int dslab = (w & 3) * 16;
    const int rh    = (w >> 2) * 64;

    // stage K (already scaled by 1/TEMP in GEMM): Ks[r][d^s], s=(r>>2)&7
    {
        int r4 = (tid & 31) * 4;
        int s  = (r4 >> 2) & 7;
        for (int d = tid >> 5; d < DH; d += 8) {
            float4 k4 = *(const float4*)(K + base + (size_t)d*NTOK + i0 + r4);
            int dc = d ^ s;
            Ks[(r4+0)*72 + dc] = tf(k4.x);
            Ks[(r4+1)*72 + dc] = tf(k4.y);
            Ks[(r4+2)*72 + dc] = tf(k4.z);
            Ks[(r4+3)*72 + dc] = tf(k4.w);
        }
    }

    const int sA = ((wrow+g  )>>2)&7;
    const int sB = ((wrow+g+8)>>2)&7;

    float m0 = -INFINITY, m1 = -INFINITY, l0 = 0.f, l1 = 0.f;
    float ot[8][4];
    #pragma unroll
    for (int nt=0;nt<8;nt++){ ot[nt][0]=ot[nt][1]=ot[nt][2]=ot[nt][3]=0.f; }

    const int njt = 2*(it+1);
    for (int jt = 0; jt < njt; jt++) {
        const int j0 = jt*JT;
        __syncthreads();
        // stage Q [d][c] stride 72, V [d][c] stride 68 (float4, natural)
        {
            int c4 = (tid & 15) * 4;
            for (int d = tid >> 4; d < DH; d += 16) {
                float4 q4 = *(const float4*)(Q + base + (size_t)d*NTOK + j0 + c4);
                float4 v4 = *(const float4*)(V + base + (size_t)d*NTOK + j0 + c4);
                float4 qt; qt.x=tf(q4.x); qt.y=tf(q4.y); qt.z=tf(q4.z); qt.w=tf(q4.w);
                float4 vt; vt.x=tf(v4.x); vt.y=tf(v4.y); vt.z=tf(v4.z); vt.w=tf(v4.w);
                *(float4*)(Qs + d*72 + c4) = qt;
                *(float4*)(Vs + d*68 + c4) = vt;
            }
        }
        __syncthreads();

        // ---- S = K.Q ----
        float sf[8][4];
        #pragma unroll
        for (int nt=0;nt<8;nt++){ sf[nt][0]=sf[nt][1]=sf[nt][2]=sf[nt][3]=0.f; }
        #pragma unroll
        for (int k0=0; k0<DH; k0+=8) {
            uint32_t a0 = Ksu[(wrow+g  )*72 + ((k0+j  ) ^ sA)];
            uint32_t a1 = Ksu[(wrow+g+8)*72 + ((k0+j  ) ^ sB)];
            uint32_t a2 = Ksu[(wrow+g  )*72 + ((k0+j+4) ^ sA)];
            uint32_t a3 = Ksu[(wrow+g+8)*72 + ((k0+j+4) ^ sB)];
            #pragma unroll
            for (int nt=0; nt<8; nt++) {
                uint32_t b0 = Qsu[(k0+j  )*72 + nt*8+g];
                uint32_t b1 = Qsu[(k0+j+4)*72 + nt*8+g];
                mma_tf32(sf[nt], a0,a1,a2,a3, b0,b1);
            }
        }

        // ---- online softmax (rows wrow+g, wrow+g+8) ----
        float tm0 = -INFINITY, tm1 = -INFINITY;
        #pragma unroll
        for (int nt=0; nt<8; nt++) {
            tm0 = fmaxf(tm0, fmaxf(sf[nt][0], sf[nt][1]));
            tm1 = fmaxf(tm1, fmaxf(sf[nt][2], sf[nt][3]));
        }
        tm0 = fmaxf(tm0, __shfl_xor_sync(0xffffffffu, tm0, 1));
        tm0 = fmaxf(tm0, __shfl_xor_sync(0xffffffffu, tm0, 2));
        tm1 = fmaxf(tm1, __shfl_xor_sync(0xffffffffu, tm1, 1));
        tm1 = fmaxf(tm1, __shfl_xor_sync(0xffffffffu, tm1, 2));
        float mn0 = fmaxf(m0, tm0), mn1 = fmaxf(m1, tm1);
        float al0 = __expf(m0 - mn0), al1 = __expf(m1 - mn1);
        m0 = mn0; m1 = mn1;

        float s0 = 0.f, s1 = 0.f;
        #pragma unroll
        for (int nt=0; nt<8; nt++) {
            sf[nt][0] = __expf(sf[nt][0] - mn0);
            sf[nt][1] = __expf(sf[nt][1] - mn0);
            sf[nt][2] = __expf(sf[nt][2] - mn1);
            sf[nt][3] = __expf(sf[nt][3] - mn1);
            s0 += sf[nt][0] + sf[nt][1];
            s1 += sf[nt][2] + sf[nt][3];
        }
        s0 += __shfl_xor_sync(0xffffffffu, s0, 1);
        s0 += __shfl_xor_sync(0xffffffffu, s0, 2);
        s1 += __shfl_xor_sync(0xffffffffu, s1, 1);
        s1 += __shfl_xor_sync(0xffffffffu, s1, 2);
        l0 = l0*al0 + s0;
        l1 = l1*al1 + s1;

        if (j == 0) { arow[wrow+g] = al0; arow[wrow+g+8] = al1; }
        #pragma unroll
        for (int nt=0; nt<8; nt++) {
            float2 p0 = { tf(sf[nt][0]), tf(sf[nt][1]) };
            float2 p1 = { tf(sf[nt][2]), tf(sf[nt][3]) };
            *(float2*)(Ps + (wrow+g  )*68 + nt*8 + 2*j) = p0;
            *(float2*)(Ps + (wrow+g+8)*68 + nt*8 + 2*j) = p1;
        }
        __syncthreads();

        // ---- O^T[d][r] += V.P^T : rescale then MMA ----
        #pragma unroll
        for (int nt=0; nt<8; nt++) {
            float2 al = *(const float2*)(arow + rh + nt*8 + 2*j);
            ot[nt][0]*=al.x; ot[nt][1]*=al.y;
            ot[nt][2]*=al.x; ot[nt][3]*=al.y;
        }
        #pragma unroll
        for (int k0=0; k0<JT; k0+=8) {
            uint32_t a0 = Vsu[(dslab+g  )*68 + k0+j  ];
            uint32_t a1 = Vsu[(dslab+g+8)*68 + k0+j  ];
            uint32_t a2 = Vsu[(dslab+g  )*68 + k0+j+4];
            uint32_t a3 = Vsu[(dslab+g+8)*68 + k0+j+4];
            #pragma unroll
            for (int nt=0; nt<8; nt++) {
                uint32_t b0 = Psu[(rh+nt*8+g)*68 + k0+j  ];
                uint32_t b1 = Psu[(rh+nt*8+g)*68 + k0+j+4];
                mma_tf32(ot[nt], a0,a1,a2,a3, b0,b1);
            }
        }
    }

    if (j == 0) { lrow[wrow+g] = l0; lrow[wrow+g+8] = l1; }
    __syncthreads();

    #pragma unroll
    for (int nt=0; nt<8; nt++) {
        float2 lv = *(const float2*)(lrow + rh + nt*8 + 2*j);
        float i0v = 1.f/lv.x, i1v = 1.f/lv.y;
        float2 o0 = { ot[nt][0]*i0v, ot[nt][1]*i1v };
        float2 o1 = { ot[nt][2]*i0v, ot[nt][3]*i1v };
        int col = i0 + rh + nt*8 + 2*j;
        *(float2*)(Vo + base + (size_t)(dslab+g  )*NTOK + col) = o0;
        *(float2*)(Vo + base + (size_t)(dslab+g+8)*NTOK + col) = o1;
    }
}

// ---------------- BN ----------------
__global__ __launch_bounds__(256) void bn_stats_kernel() {
    __shared__ float ss[256], sq[256];
    const int c = blockIdx.x;
    float s=0.f, q=0.f;
    for (int idx=threadIdx.x; idx<Bb*NTOK; idx+=256) {
        int bb = idx >> 11, n = idx & 2047;
        float v = g_y[((size_t)bb*COUT + c)*NTOK + n];
        s += v; q += v*v;
    }
    ss[threadIdx.x]=s; sq[threadIdx.x]=q;
    __syncthreads();
    for (int o=128;o>0;o>>=1) {
        if (threadIdx.x < o) { ss[threadIdx.x]+=ss[threadIdx.x+o]; sq[threadIdx.x]+=sq[threadIdx.x+o]; }
        __syncthreads();
    }
    if (threadIdx.x==0) {
        float mean = ss[0]/(float)(Bb*NTOK);
        float var  = sq[0]/(float)(Bb*NTOK) - mean*mean;
        g_mean[c] = mean;
        g_istd[c] = rsqrtf(var + BN_EPS);
    }
}

__global__ __launch_bounds__(256) void bn_apply_kernel(
    const float* __restrict__ gamma, const float* __restrict__ beta,
    float* __restrict__ out)
{
    int idx = blockIdx.x*256 + threadIdx.x;
    if (idx >= Bb*COUT*NTOK) return;
    int c = (idx >> 11) & (COUT-1);
    out[idx] = (g_y[idx] - g_mean[c]) * g_istd[c] * gamma[c] + beta[c];
}

// ---------------- launch ----------------
extern "C" void kernel_launch(void* const* d_in, const int* in_sizes, int n_in,
                              void* d_out, int out_size)
{
    const float* x     = (const float*)d_in[0];
    const float* WK    = (const float*)d_in[1];
    const float* WQ    = (const float*)d_in[2];
    const float* WV    = (const float*)d_in[3];
    const float* Wo    = (const float*)d_in[4];
    const float* bo    = (const float*)d_in[5];
    const float* gamma = (const float*)d_in[6];
    const float* beta  = (const float*)d_in[7];
    float* out = (float*)d_out;

    float *pK, *pQ, *pV, *pVo, *pY;
    cudaGetSymbolAddress((void**)&pK,  g_K);
    cudaGetSymbolAddress((void**)&pQ,  g_Q);
    cudaGetSymbolAddress((void**)&pV,  g_V);
    cudaGetSymbolAddress((void**)&pVo, g_Vo);
    cudaGetSymbolAddress((void**)&pY,  g_y);

    dim3 gq(NTOK/64, 12, Bb);
    qkv_kernel<<<gq, 256>>>(WK, WQ, WV, x, pK, pQ, pV);

    size_t smem = (size_t)(128*72 + 64*72 + 64*68 + 128*68 + 256) * sizeof(float);
    cudaFuncSetAttribute(attn_kernel, cudaFuncAttributeMaxDynamicSharedMemorySize, (int)smem);
    dim3 ga(Tt, NH, Bb);
    attn_kernel<<<ga, 256, smem>>>(pK, pQ, pV, pVo);

    dim3 gp(NTOK/64, COUT/128, Bb);
    proj_kernel<<<gp, 256>>>(Wo, pVo, bo, x, pY);

    bn_stats_kernel<<<COUT, 256>>>();
    bn_apply_kernel<<<(Bb*COUT*NTOK + 255)/256, 256>>>(gamma, beta, out);
}

// round 4
// speedup vs baseline: 5.0642x; 1.6595x over previous
#include <cuda_runtime.h>
#include <math.h>
#include <stdint.h>

#define Bb    2
#define CIN   256
#define FF    512
#define COUT  256
#define NH    8
#define DH    64
#define NTOK  2048
#define TB    128
#define Tt    16
#define INV_TEMP (1.0f/16.0f)
#define BN_EPS 1e-5f

// ---------------- scratch ----------------
__device__ float g_K [Bb*FF*NTOK];     // [b][f][n]  (K pre-scaled by 1/TEMP)
__device__ float g_Q [Bb*FF*NTOK];     // [b][f][n]
__device__ float g_V [Bb*FF*NTOK];     // [b][f][n]
__device__ float g_Vo[Bb*NTOK*FF];     // [b][n][f]
__device__ float g_y [Bb*COUT*NTOK];   // [b][c][n]
__device__ float g_ps[64*COUT];
__device__ float g_pq[64*COUT];
__device__ float g_mean[COUT];
__device__ float g_istd[COUT];

// ---------------- helpers ----------------
__device__ __forceinline__ uint32_t pack_bf16(float lo, float hi) {
    uint32_t r;
    asm("cvt.rn.bf16x2.f32 %0, %1, %2;" : "=r"(r) : "f"(hi), "f"(lo));
    return r;
}
__device__ __forceinline__ void mma_bf16(float d[4],
    uint32_t a0, uint32_t a1, uint32_t a2, uint32_t a3,
    uint32_t b0, uint32_t b1)
{
    asm volatile(
      "mma.sync.aligned.m16n8k16.row.col.f32.bf16.bf16.f32 "
      "{%0,%1,%2,%3}, {%4,%5,%6,%7}, {%8,%9}, {%0,%1,%2,%3};"
      : "+f"(d[0]), "+f"(d[1]), "+f"(d[2]), "+f"(d[3])
      : "r"(a0), "r"(a1), "r"(a2), "r"(a3), "r"(b0), "r"(b1));
}

// MMA over one staged k-chunk of 32: Ws[m][k2] stride 20, Xs[k2][n] stride 72
__device__ __forceinline__ void chunk_mma(
    const uint32_t* Wsu, const uint32_t* Xsu,
    float sf[8][4], int wrow, int g, int j)
{
    #pragma unroll
    for (int k02 = 0; k02 < 16; k02 += 8) {
        uint32_t a0 = Wsu[(wrow+g  )*20 + k02+j  ];
        uint32_t a1 = Wsu[(wrow+g+8)*20 + k02+j  ];
        uint32_t a2 = Wsu[(wrow+g  )*20 + k02+j+4];
        uint32_t a3 = Wsu[(wrow+g+8)*20 + k02+j+4];
        #pragma unroll
        for (int nt = 0; nt < 8; nt++) {
            uint32_t b0 = Xsu[(k02+j  )*72 + nt*8+g];
            uint32_t b1 = Xsu[(k02+j+4)*72 + nt*8+g];
            mma_bf16(sf[nt], a0,a1,a2,a3, b0,b1);
        }
    }
}
// A-stage: W[m][k] fp32 -> Ws packed pairs along k
__device__ __forceinline__ void stage_A(
    const float* __restrict__ Wp, int KD, int kc, uint32_t* Wsu, int tid)
{
    #pragma unroll
    for (int i = 0; i < 4; i++) {
        int id = tid + i*256;
        int m = id >> 3, kq = (id & 7) * 4;
        float4 w4 = *(const float4*)(Wp + (size_t)m*KD + kc + kq);
        Wsu[m*20 + (kq>>1)    ] = pack_bf16(w4.x, w4.y);
        Wsu[m*20 + (kq>>1) + 1] = pack_bf16(w4.z, w4.w);
    }
}

// ---------------- fused QKV GEMM: grid (32, 12, 2) ----------------
__global__ __launch_bounds__(256) void qkv_kernel(
    const float* __restrict__ WK, const float* __restrict__ WQ,
    const float* __restrict__ WV, const float* __restrict__ X,
    float* __restrict__ Ko, float* __restrict__ Qo, float* __restrict__ Vo)
{
    __shared__ uint32_t Wsu[128*20];
    __shared__ uint32_t Xsu[16*72];
    const int b = blockIdx.z, mb = blockIdx.y, n0 = blockIdx.x*64;
    const int sel = mb >> 2, m0 = (mb & 3)*128;
    const float* W = sel==0 ? WK : (sel==1 ? WQ : WV);
    float*       C = sel==0 ? Ko : (sel==1 ? Qo : Vo);
    const float scale = sel==0 ? INV_TEMP : 1.f;

    const int tid = threadIdx.x, w = tid>>5, lane = tid&31;
    const int g = lane>>2, j = lane&3, wrow = w*16;
    const float* Xp = X + (size_t)b*CIN*NTOK + n0;

    float sf[8][4];
    #pragma unroll
    for (int nt=0;nt<8;nt++){ sf[nt][0]=sf[nt][1]=sf[nt][2]=sf[nt][3]=0.f; }

    for (int kc = 0; kc < CIN; kc += 32) {
        __syncthreads();
        stage_A(W + (size_t)m0*CIN, CIN, kc, Wsu, tid);
        {   // X[k][n]: interleave rows 2k2,2k2+1
            int k2 = tid >> 4, n4 = (tid & 15) * 4;
            float4 xa = *(const float4*)(Xp + (size_t)(kc+2*k2  )*NTOK + n4);
            float4 xb = *(const float4*)(Xp + (size_t)(kc+2*k2+1)*NTOK + n4);
            uint4 o;
            o.x = pack_bf16(xa.x, xb.x); o.y = pack_bf16(xa.y, xb.y);
            o.z = pack_bf16(xa.z, xb.z); o.w = pack_bf16(xa.w, xb.w);
            *(uint4*)(Xsu + k2*72 + n4) = o;
        }
        __syncthreads();
        chunk_mma(Wsu, Xsu, sf, wrow, g, j);
    }

    const size_t cbase = (size_t)b*FF*NTOK;
    #pragma unroll
    for (int nt=0; nt<8; nt++) {
        int col = n0 + nt*8 + 2*j;
        float2 v0 = { sf[nt][0]*scale, sf[nt][1]*scale };
        float2 v1 = { sf[nt][2]*scale, sf[nt][3]*scale };
        *(float2*)(C + cbase + (size_t)(m0+wrow+g  )*NTOK + col) = v0;
        *(float2*)(C + cbase + (size_t)(m0+wrow+g+8)*NTOK + col) = v1;
    }
}

// ---------------- proj + bias + relu + skip + BN partials: grid (32,2,2) --
__global__ __launch_bounds__(256) void proj_kernel(
    const float* __restrict__ Wo, const float* __restrict__ Vi,  // Vi [b][n][f]
    const float* __restrict__ bias, const float* __restrict__ skip,
    float* __restrict__ Y)
{
    __shared__ uint32_t Wsu[128*20];
    __shared__ uint32_t Xsu[16*72];
    const int b = blockIdx.z, m0 = blockIdx.y*128, n0 = blockIdx.x*64;
    const int tid = threadIdx.x, w = tid>>5, lane = tid&31;
    const int g = lane>>2, j = lane&3, wrow = w*16;
    const float* Vp = Vi + (size_t)b*NTOK*FF + (size_t)n0*FF;

    float sf[8][4];
    #pragma unroll
    for (int nt=0;nt<8;nt++){ sf[nt][0]=sf[nt][1]=sf[nt][2]=sf[nt][3]=0.f; }

    for (int kc = 0; kc < FF; kc += 32) {
        __syncthreads();
        stage_A(Wo + (size_t)m0*FF, FF, kc, Wsu, tid);
        {   // Vi [n][f]: pairs along f contiguous
            int kq = (tid & 7) * 4;
            int n  = tid >> 3;
            #pragma unroll
            for (int i = 0; i < 2; i++, n += 32) {
                float4 xv = *(const float4*)(Vp + (size_t)n*FF + kc + kq);
                Xsu[(kq>>1)    *72 + n] = pack_bf16(xv.x, xv.y);
                Xsu[((kq>>1)+1)*72 + n] = pack_bf16(xv.z, xv.w);
            }
        }
        __syncthreads();
        chunk_mma(Wsu, Xsu, sf, wrow, g, j);
    }

    const int row0 = m0 + wrow + g, row1 = row0 + 8;
    const float b0v = bias[row0], b1v = bias[row1];
    const size_t ybase = (size_t)b*COUT*NTOK;
    float s0=0.f,q0=0.f,s1=0.f,q1=0.f;
    #pragma unroll
    for (int nt=0; nt<8; nt++) {
        int col = n0 + nt*8 + 2*j;
        float2 sk0 = *(const float2*)(skip + ybase + (size_t)row0*NTOK + col);
        float2 sk1 = *(const float2*)(skip + ybase + (size_t)row1*NTOK + col);
        float2 y0 = { fmaxf(sf[nt][0]+b0v,0.f)+sk0.x, fmaxf(sf[nt][1]+b0v,0.f)+sk0.y };
        float2 y1 = { fmaxf(sf[nt][2]+b1v,0.f)+sk1.x, fmaxf(sf[nt][3]+b1v,0.f)+sk1.y };
        *(float2*)(Y + ybase + (size_t)row0*NTOK + col) = y0;
        *(float2*)(Y + ybase + (size_t)row1*NTOK + col) = y1;
        s0 += y0.x + y0.y;  q0 += y0.x*y0.x + y0.y*y0.y;
        s1 += y1.x + y1.y;  q1 += y1.x*y1.x + y1.y*y1.y;
    }
    // reduce across j within quad (lanes g*4 + j)
    s0 += __shfl_xor_sync(0xffffffffu, s0, 1); s0 += __shfl_xor_sync(0xffffffffu, s0, 2);
    q0 += __shfl_xor_sync(0xffffffffu, q0, 1); q0 += __shfl_xor_sync(0xffffffffu, q0, 2);
    s1 += __shfl_xor_sync(0xffffffffu, s1, 1); s1 += __shfl_xor_sync(0xffffffffu, s1, 2);
    q1 += __shfl_xor_sync(0xffffffffu, q1, 1); q1 += __shfl_xor_sync(0xffffffffu, q1, 2);
    if (j == 0) {
        int part = b*32 + blockIdx.x;
        g_ps[part*COUT + row0] = s0;  g_pq[part*COUT + row0] = q0;
        g_ps[part*COUT + row1] = s1;  g_pq[part*COUT + row1] = q1;
    }
}

// ---------------- attention: bf16 mma, per-warp O = P.V ----------------
// grid (Tt, NH, Bb), 256 thr. Warp owns i-rows wrow..wrow+15 end-to-end.
// Stage Q,V for 128 cols at once; softmax in two 64-col register halves.
__global__ __launch_bounds__(256, 2) void attn_kernel(
    const float* __restrict__ K, const float* __restrict__ Q,
    const float* __restrict__ V, float* __restrict__ Vo)
{
    extern __shared__ uint32_t smu[];
    uint32_t* Ksu = smu;               // [128 r][36]  word = {K[2d2][r],K[2d2+1][r]}
    uint32_t* Qsu = Ksu + 128*36;      // [32 d2][136] word = {Q[2d2][c],Q[2d2+1][c]}
    uint32_t* Vsu = Qsu + 32*136;      // [64 d][68]   word = {V[d][2c2],V[d][2c2+1]}
    uint32_t* Psu = Vsu + 64*68;       // per warp [16 r][36]

    const int it = (Tt-1) - blockIdx.x;     // LPT
    const int h  = blockIdx.y, b = blockIdx.z;
    const int i0 = it*TB;
    const size_t base = ((size_t)b*FF + (size_t)h*DH)*NTOK;

    const int tid = threadIdx.x, w = tid>>5, lane = tid&31;
    const int g = lane>>2, j = lane&3, wrow = w*16;
    uint32_t* Pwu = Psu + w*16*36;

    // ---- stage K once (pre-scaled by 1/TEMP) ----
    {
        int r4 = (tid & 31) * 4;
        for (int d2 = tid>>5; d2 < 32; d2 += 8) {
            int d = 2*d2;
            float4 ka = *(const float4*)(K + base + (size_t)d    *NTOK + i0 + r4);
            float4 kb = *(const float4*)(K + base + (size_t)(d+1)*NTOK + i0 + r4);
            Ksu[(r4+0)*36 + d2] = pack_bf16(ka.x, kb.x);
            Ksu[(r4+1)*36 + d2] = pack_bf16(ka.y, kb.y);
            Ksu[(r4+2)*36 + d2] = pack_bf16(ka.z, kb.z);
            Ksu[(r4+3)*36 + d2] = pack_bf16(ka.w, kb.w);
        }
    }

    float m0 = -INFINITY, m1 = -INFINITY, l0 = 0.f, l1 = 0.f;
    float ot[8][4];
    #pragma unroll
    for (int nt=0;nt<8;nt++){ ot[nt][0]=ot[nt][1]=ot[nt][2]=ot[nt][3]=0.f; }

    for (int jt = 0; jt <= it; jt++) {
        const int j0 = jt*TB;
        __syncthreads();
        {   // stage Q (d-interleaved) + V (c-paired, natural)
            int c4 = (tid & 31) * 4;
            for (int d2 = tid>>5; d2 < 32; d2 += 8) {
                int d = 2*d2;
                float4 qa = *(const float4*)(Q + base + (size_t)d    *NTOK + j0 + c4);
                float4 qb = *(const float4*)(Q + base + (size_t)(d+1)*NTOK + j0 + c4);
                uint4 o;
                o.x = pack_bf16(qa.x, qb.x); o.y = pack_bf16(qa.y, qb.y);
                o.z = pack_bf16(qa.z, qb.z); o.w = pack_bf16(qa.w, qb.w);
                *(uint4*)(Qsu + d2*136 + c4) = o;
            }
            for (int d = tid>>5; d < 64; d += 8) {
                float4 v4 = *(const float4*)(V + base + (size_t)d*NTOK + j0 + c4);
                uint2 o;
                o.x = pack_bf16(v4.x, v4.y); o.y = pack_bf16(v4.z, v4.w);
                *(uint2*)(Vsu + d*68 + (c4>>1)) = o;
            }
        }
        __syncthreads();

        #pragma unroll
        for (int h2 = 0; h2 < 2; h2++) {
            const int ch = h2*64;     // column offset within staged tile
            // ---- S = K.Q over 64 cols ----
            float sf[8][4];
            #pragma unroll
            for (int nt=0;nt<8;nt++){ sf[nt][0]=sf[nt][1]=sf[nt][2]=sf[nt][3]=0.f; }
            #pragma unroll
            for (int k02 = 0; k02 < 32; k02 += 8) {
                uint32_t a0 = Ksu[(wrow+g  )*36 + k02+j  ];
                uint32_t a1 = Ksu[(wrow+g+8)*36 + k02+j  ];
                uint32_t a2 = Ksu[(wrow+g  )*36 + k02+j+4];
                uint32_t a3 = Ksu[(wrow+g+8)*36 + k02+j+4];
                #pragma unroll
                for (int nt = 0; nt < 8; nt++) {
                    uint32_t b0 = Qsu[(k02+j  )*136 + ch + nt*8+g];
                    uint32_t b1 = Qsu[(k02+j+4)*136 + ch + nt*8+g];
                    mma_bf16(sf[nt], a0,a1,a2,a3, b0,b1);
                }
            }
            // ---- online softmax (rows wrow+g, wrow+g+8), all in-warp ----
            float tm0 = -INFINITY, tm1 = -INFINITY;
            #pragma unroll
            for (int nt=0; nt<8; nt++) {
                tm0 = fmaxf(tm0, fmaxf(sf[nt][0], sf[nt][1]));
                tm1 = fmaxf(tm1, fmaxf(sf[nt][2], sf[nt][3]));
            }
            tm0 = fmaxf(tm0, __shfl_xor_sync(0xffffffffu, tm0, 1));
            tm0 = fmaxf(tm0, __shfl_xor_sync(0xffffffffu, tm0, 2));
            tm1 = fmaxf(tm1, __shfl_xor_sync(0xffffffffu, tm1, 1));
            tm1 = fmaxf(tm1, __shfl_xor_sync(0xffffffffu, tm1, 2));
            float mn0 = fmaxf(m0, tm0), mn1 = fmaxf(m1, tm1);
            float al0 = __expf(m0 - mn0), al1 = __expf(m1 - mn1);
            m0 = mn0; m1 = mn1;

            float s0 = 0.f, s1 = 0.f;
            #pragma unroll
            for (int nt=0; nt<8; nt++) {
                sf[nt][0] = __expf(sf[nt][0] - mn0);
                sf[nt][1] = __expf(sf[nt][1] - mn0);
                sf[nt][2] = __expf(sf[nt][2] - mn1);
                sf[nt][3] = __expf(sf[nt][3] - mn1);
                s0 += sf[nt][0] + sf[nt][1];
                s1 += sf[nt][2] + sf[nt][3];
            }
            s0 += __shfl_xor_sync(0xffffffffu, s0, 1);
            s0 += __shfl_xor_sync(0xffffffffu, s0, 2);
            s1 += __shfl_xor_sync(0xffffffffu, s1, 1);
            s1 += __shfl_xor_sync(0xffffffffu, s1, 2);
            l0 = l0*al0 + s0;
            l1 = l1*al1 + s1;

            // ---- pack P into per-warp smem ----
            #pragma unroll
            for (int nt=0; nt<8; nt++) {
                Pwu[(g  )*36 + nt*4+j] = pack_bf16(sf[nt][0], sf[nt][1]);
                Pwu[(g+8)*36 + nt*4+j] = pack_bf16(sf[nt][2], sf[nt][3]);
            }
            __syncwarp();
            // ---- rescale O, then O += P.V over this half's 64 tokens ----
            #pragma unroll
            for (int nt=0; nt<8; nt++) {
                ot[nt][0]*=al0; ot[nt][1]*=al0;
                ot[nt][2]*=al1; ot[nt][3]*=al1;
            }
            #pragma unroll
            for (int k02 = 0; k02 < 32; k02 += 8) {
                uint32_t a0 = Pwu[(g  )*36 + k02+j  ];
                uint32_t a1 = Pwu[(g+8)*36 + k02+j  ];
                uint32_t a2 = Pwu[(g  )*36 + k02+j+4];
                uint32_t a3 = Pwu[(g+8)*36 + k02+j+4];
                #pragma unroll
                for (int nt = 0; nt < 8; nt++) {
                    uint32_t b0 = Vsu[(nt*8+g)*68 + h2*32 + k02+j  ];
                    uint32_t b1 = Vsu[(nt*8+g)*68 + h2*32 + k02+j+4];
                    mma_bf16(ot[nt], a0,a1,a2,a3, b0,b1);
                }
            }
            __syncwarp();   // Pwu reads done before next half overwrites
        }
    }

    // ---- epilogue: O/l -> Vo [b][n][f] ----
    float inv0 = 1.0f/l0, inv1 = 1.0f/l1;
    const size_t vb = (size_t)b*NTOK*FF;
    const int fcol = h*DH + 2*j;
    #pragma unroll
    for (int nt=0; nt<8; nt++) {
        float2 o0 = { ot[nt][0]*inv0, ot[nt][1]*inv0 };
        float2 o1 = { ot[nt][2]*inv1, ot[nt][3]*inv1 };
        *(float2*)(Vo + vb + (size_t)(i0+wrow+g  )*FF + fcol + nt*8) = o0;
        *(float2*)(Vo + vb + (size_t)(i0+wrow+g+8)*FF + fcol + nt*8) = o1;
    }
}

// ---------------- BN finalize + apply ----------------
__global__ void bn_finalize_kernel() {
    int c = threadIdx.x;
    float s = 0.f, q = 0.f;
    #pragma unroll 8
    for (int p = 0; p < 64; p++) { s += g_ps[p*COUT + c]; q += g_pq[p*COUT + c]; }
    float mean = s / (float)(Bb*NTOK);
    float var  = q / (float)(Bb*NTOK) - mean*mean;
    g_mean[c] = mean;
    g_istd[c] = rsqrtf(var + BN_EPS);
}

__global__ __launch_bounds__(256) void bn_apply_kernel(
    const float* __restrict__ gamma, const float* __restrict__ beta,
    float* __restrict__ out)
{
    int idx4 = blockIdx.x*256 + threadIdx.x;       // 262144 total
    int c = (idx4 >> 9) & (COUT-1);
    float4 v = *((const float4*)g_y + idx4);
    float mu = g_mean[c], is = g_istd[c]*gamma[c], be = beta[c];
    float4 o;
    o.x = (v.x-mu)*is + be; o.y = (v.y-mu)*is + be;
    o.z = (v.z-mu)*is + be; o.w = (v.w-mu)*is + be;
    *((float4*)out + idx4) = o;
}

// ---------------- launch ----------------
extern "C" void kernel_launch(void* const* d_in, const int* in_sizes, int n_in,
                              void* d_out, int out_size)
{
    const float* x     = (const float*)d_in[0];
    const float* WK    = (const float*)d_in[1];
    const float* WQ    = (const float*)d_in[2];
    const float* WV    = (const float*)d_in[3];
    const float* Wo    = (const float*)d_in[4];
    const float* bo    = (const float*)d_in[5];
    const float* gamma = (const float*)d_in[6];
    const float* beta  = (const float*)d_in[7];
    float* out = (float*)d_out;

    float *pK, *pQ, *pV, *pVo, *pY;
    cudaGetSymbolAddress((void**)&pK,  g_K);
    cudaGetSymbolAddress((void**)&pQ,  g_Q);
    cudaGetSymbolAddress((void**)&pV,  g_V);
    cudaGetSymbolAddress((void**)&pVo, g_Vo);
    cudaGetSymbolAddress((void**)&pY,  g_y);

    dim3 gq(NTOK/64, 12, Bb);
    qkv_kernel<<<gq, 256>>>(WK, WQ, WV, x, pK, pQ, pV);

    size_t smem = (size_t)(128*36 + 32*136 + 64*68 + 8*16*36) * 4;
    cudaFuncSetAttribute(attn_kernel, cudaFuncAttributeMaxDynamicSharedMemorySize, (int)smem);
    dim3 ga(Tt, NH, Bb);
    attn_kernel<<<ga, 256, smem>>>(pK, pQ, pV, pVo);

    dim3 gp(NTOK/64, COUT/128, Bb);
    proj_kernel<<<gp, 256>>>(Wo, pVo, bo, x, pY);

    bn_finalize_kernel<<<1, COUT>>>();
    bn_apply_kernel<<<(Bb*COUT*NTOK/4 + 255)/256, 256>>>(gamma, beta, out);
}

// round 5
// speedup vs baseline: 6.6836x; 1.3198x over previous
#include <cuda_runtime.h>
#include <math.h>
#include <stdint.h>

#define Bb    2
#define CIN   256
#define FF    512
#define COUT  256
#define NH    8
#define DH    64
#define NTOK  2048
#define TB    128
#define Tt    16
#define INV_TEMP (1.0f/16.0f)
#define BN_EPS 1e-5f

// ---------------- scratch ----------------
__device__ float g_K [Bb*FF*NTOK];     // [b][f][n]  (K pre-scaled by 1/TEMP)
__device__ float g_Q [Bb*FF*NTOK];     // [b][f][n]
__device__ float g_V [Bb*FF*NTOK];     // [b][f][n]
__device__ float g_Vo[Bb*NTOK*FF];     // [b][n][f]
__device__ float g_y [Bb*COUT*NTOK];   // [b][c][n]
__device__ float g_Op[Bb*NH*12*4*TB*DH];  // attention partial O (it>=4)
__device__ float g_lp[Bb*NH*12*4*TB];     // attention partial l
__device__ float g_ps[COUT*64];
__device__ float g_pq[COUT*64];
__device__ float g_mean[COUT];
__device__ float g_istd[COUT];

// unit tables: 40 (it,chunk) units, LPT order (4-tile units first)
__constant__ int8_t U_IT[40] = {3,4,5,6,7,7,8,8,9,9,10,10,11,11,11,12,12,12,
                                13,13,13,14,14,14,15,15,15,15,
                                2,6,10,14, 1,5,9,13, 0,4,8,12};
__constant__ int8_t U_CH[40] = {0,0,0,0,0,1,0,1,0,1,0,1,0,1,2,0,1,2,
                                0,1,2,0,1,2,0,1,2,3,
                                0,1,2,3, 0,1,2,3, 0,1,2,3};

// ---------------- helpers ----------------
__device__ __forceinline__ uint32_t pack_bf16(float lo, float hi) {
    uint32_t r;
    asm("cvt.rn.bf16x2.f32 %0, %1, %2;" : "=r"(r) : "f"(hi), "f"(lo));
    return r;
}
__device__ __forceinline__ void mma_bf16(float d[4],
    uint32_t a0, uint32_t a1, uint32_t a2, uint32_t a3,
    uint32_t b0, uint32_t b1)
{
    asm volatile(
      "mma.sync.aligned.m16n8k16.row.col.f32.bf16.bf16.f32 "
      "{%0,%1,%2,%3}, {%4,%5,%6,%7}, {%8,%9}, {%0,%1,%2,%3};"
      : "+f"(d[0]), "+f"(d[1]), "+f"(d[2]), "+f"(d[3])
      : "r"(a0), "r"(a1), "r"(a2), "r"(a3), "r"(b0), "r"(b1));
}

__device__ __forceinline__ void chunk_mma(
    const uint32_t* Wsu, const uint32_t* Xsu,
    float sf[8][4], int wrow, int g, int j)
{
    #pragma unroll
    for (int k02 = 0; k02 < 16; k02 += 8) {
        uint32_t a0 = Wsu[(wrow+g  )*20 + k02+j  ];
        uint32_t a1 = Wsu[(wrow+g+8)*20 + k02+j  ];
        uint32_t a2 = Wsu[(wrow+g  )*20 + k02+j+4];
        uint32_t a3 = Wsu[(wrow+g+8)*20 + k02+j+4];
        #pragma unroll
        for (int nt = 0; nt < 8; nt++) {
            uint32_t b0 = Xsu[(k02+j  )*72 + nt*8+g];
            uint32_t b1 = Xsu[(k02+j+4)*72 + nt*8+g];
            mma_bf16(sf[nt], a0,a1,a2,a3, b0,b1);
        }
    }
}
__device__ __forceinline__ void stage_A(
    const float* __restrict__ Wp, int KD, int kc, uint32_t* Wsu, int tid)
{
    #pragma unroll
    for (int i = 0; i < 4; i++) {
        int id = tid + i*256;
        int m = id >> 3, kq = (id & 7) * 4;
        float4 w4 = *(const float4*)(Wp + (size_t)m*KD + kc + kq);
        Wsu[m*20 + (kq>>1)    ] = pack_bf16(w4.x, w4.y);
        Wsu[m*20 + (kq>>1) + 1] = pack_bf16(w4.z, w4.w);
    }
}

// ---------------- fused QKV GEMM: grid (32, 12, 2) ----------------
__global__ __launch_bounds__(256) void qkv_kernel(
    const float* __restrict__ WK, const float* __restrict__ WQ,
    const float* __restrict__ WV, const float* __restrict__ X,
    float* __restrict__ Ko, float* __restrict__ Qo, float* __restrict__ Vo)
{
    __shared__ uint32_t Wsu[128*20];
    __shared__ uint32_t Xsu[16*72];
    const int b = blockIdx.z, mb = blockIdx.y, n0 = blockIdx.x*64;
    const int sel = mb >> 2, m0 = (mb & 3)*128;
    const float* W = sel==0 ? WK : (sel==1 ? WQ : WV);
    float*       C = sel==0 ? Ko : (sel==1 ? Qo : Vo);
    const float scale = sel==0 ? INV_TEMP : 1.f;

    const int tid = threadIdx.x, w = tid>>5, lane = tid&31;
    const int g = lane>>2, j = lane&3, wrow = w*16;
    const float* Xp = X + (size_t)b*CIN*NTOK + n0;

    float sf[8][4];
    #pragma unroll
    for (int nt=0;nt<8;nt++){ sf[nt][0]=sf[nt][1]=sf[nt][2]=sf[nt][3]=0.f; }

    for (int kc = 0; kc < CIN; kc += 32) {
        __syncthreads();
        stage_A(W + (size_t)m0*CIN, CIN, kc, Wsu, tid);
        {
            int k2 = tid >> 4, n4 = (tid & 15) * 4;
            float4 xa = *(const float4*)(Xp + (size_t)(kc+2*k2  )*NTOK + n4);
            float4 xb = *(const float4*)(Xp + (size_t)(kc+2*k2+1)*NTOK + n4);
            uint4 o;
            o.x = pack_bf16(xa.x, xb.x); o.y = pack_bf16(xa.y, xb.y);
            o.z = pack_bf16(xa.z, xb.z); o.w = pack_bf16(xa.w, xb.w);
            *(uint4*)(Xsu + k2*72 + n4) = o;
        }
        __syncthreads();
        chunk_mma(Wsu, Xsu, sf, wrow, g, j);
    }

    const size_t cbase = (size_t)b*FF*NTOK;
    #pragma unroll
    for (int nt=0; nt<8; nt++) {
        int col = n0 + nt*8 + 2*j;
        float2 v0 = { sf[nt][0]*scale, sf[nt][1]*scale };
        float2 v1 = { sf[nt][2]*scale, sf[nt][3]*scale };
        *(float2*)(C + cbase + (size_t)(m0+wrow+g  )*NTOK + col) = v0;
        *(float2*)(C + cbase + (size_t)(m0+wrow+g+8)*NTOK + col) = v1;
    }
}

// ---------------- proj + bias + relu + skip + BN partials: grid (32,2,2) --
__global__ __launch_bounds__(256) void proj_kernel(
    const float* __restrict__ Wo, const float* __restrict__ Vi,
    const float* __restrict__ bias, const float* __restrict__ skip,
    float* __restrict__ Y)
{
    __shared__ uint32_t Wsu[128*20];
    __shared__ uint32_t Xsu[16*72];
    const int b = blockIdx.z, m0 = blockIdx.y*128, n0 = blockIdx.x*64;
    const int tid = threadIdx.x, w = tid>>5, lane = tid&31;
    const int g = lane>>2, j = lane&3, wrow = w*16;
    const float* Vp = Vi + (size_t)b*NTOK*FF + (size_t)n0*FF;

    float sf[8][4];
    #pragma unroll
    for (int nt=0;nt<8;nt++){ sf[nt][0]=sf[nt][1]=sf[nt][2]=sf[nt][3]=0.f; }

    for (int kc = 0; kc < FF; kc += 32) {
        __syncthreads();
        stage_A(Wo + (size_t)m0*FF, FF, kc, Wsu, tid);
        {
            int kq = (tid & 7) * 4;
            int n  = tid >> 3;
            #pragma unroll
            for (int i = 0; i < 2; i++, n += 32) {
                float4 xv = *(const float4*)(Vp + (size_t)n*FF + kc + kq);
                Xsu[(kq>>1)    *72 + n] = pack_bf16(xv.x, xv.y);
                Xsu[((kq>>1)+1)*72 + n] = pack_bf16(xv.z, xv.w);
            }
        }
        __syncthreads();
        chunk_mma(Wsu, Xsu, sf, wrow, g, j);
    }

    const int row0 = m0 + wrow + g, row1 = row0 + 8;
    const float b0v = bias[row0], b1v = bias[row1];
    const size_t ybase = (size_t)b*COUT*NTOK;
    float s0=0.f,q0=0.f,s1=0.f,q1=0.f;
    #pragma unroll
    for (int nt=0; nt<8; nt++) {
        int col = n0 + nt*8 + 2*j;
        float2 sk0 = *(const float2*)(skip + ybase + (size_t)row0*NTOK + col);
        float2 sk1 = *(const float2*)(skip + ybase + (size_t)row1*NTOK + col);
        float2 y0 = { fmaxf(sf[nt][0]+b0v,0.f)+sk0.x, fmaxf(sf[nt][1]+b0v,0.f)+sk0.y };
        float2 y1 = { fmaxf(sf[nt][2]+b1v,0.f)+sk1.x, fmaxf(sf[nt][3]+b1v,0.f)+sk1.y };
        *(float2*)(Y + ybase + (size_t)row0*NTOK + col) = y0;
        *(float2*)(Y + ybase + (size_t)row1*NTOK + col) = y1;
        s0 += y0.x + y0.y;  q0 += y0.x*y0.x + y0.y*y0.y;
        s1 += y1.x + y1.y;  q1 += y1.x*y1.x + y1.y*y1.y;
    }
    s0 += __shfl_xor_sync(0xffffffffu, s0, 1); s0 += __shfl_xor_sync(0xffffffffu, s0, 2);
    q0 += __shfl_xor_sync(0xffffffffu, q0, 1); q0 += __shfl_xor_sync(0xffffffffu, q0, 2);
    s1 += __shfl_xor_sync(0xffffffffu, s1, 1); s1 += __shfl_xor_sync(0xffffffffu, s1, 2);
    q1 += __shfl_xor_sync(0xffffffffu, q1, 1); q1 += __shfl_xor_sync(0xffffffffu, q1, 2);
    if (j == 0) {
        int part = b*32 + blockIdx.x;
        g_ps[row0*64 + part] = s0;  g_pq[row0*64 + part] = q0;
        g_ps[row1*64 + part] = s1;  g_pq[row1*64 + part] = q1;
    }
}

// ---------------- attention: bf16 mma, max-free softmax, j-chunked -------
// flat grid 640: unit = bx>>4 (LPT tables), bh = bx&15.
__global__ __launch_bounds__(256, 2) void attn_kernel(
    const float* __restrict__ K, const float* __restrict__ Q,
    const float* __restrict__ V, float* __restrict__ Vo)
{
    extern __shared__ uint32_t smu[];
    uint32_t* Ksu = smu;               // [128 r][36]
    uint32_t* Qsu = Ksu + 128*36;      // [32 d2][136]
    uint32_t* Vsu = Qsu + 32*136;      // [64 d][68]
    uint32_t* Psu = Vsu + 64*68;       // per warp [16 r][36]

    const int ux = blockIdx.x;
    const int unit = ux >> 4, bh = ux & 15;
    const int b = bh >> 3, h = bh & 7;
    const int it = U_IT[unit], ch = U_CH[unit];
    const int i0 = it*TB;
    const int jlo = ch*4;
    const int jhi = (jlo+3 < it) ? jlo+3 : it;
    const size_t base = ((size_t)b*FF + (size_t)h*DH)*NTOK;

    const int tid = threadIdx.x, w = tid>>5, lane = tid&31;
    const int g = lane>>2, j = lane&3, wrow = w*16;
    uint32_t* Pwu = Psu + w*16*36;

    // ---- stage K once (pre-scaled by 1/TEMP) ----
    {
        int r4 = (tid & 31) * 4;
        for (int d2 = tid>>5; d2 < 32; d2 += 8) {
            int d = 2*d2;
            float4 ka = *(const float4*)(K + base + (size_t)d    *NTOK + i0 + r4);
            float4 kb = *(const float4*)(K + base + (size_t)(d+1)*NTOK + i0 + r4);
            Ksu[(r4+0)*36 + d2] = pack_bf16(ka.x, kb.x);
            Ksu[(r4+1)*36 + d2] = pack_bf16(ka.y, kb.y);
            Ksu[(r4+2)*36 + d2] = pack_bf16(ka.z, kb.z);
            Ksu[(r4+3)*36 + d2] = pack_bf16(ka.w, kb.w);
        }
    }

    float l0 = 0.f, l1 = 0.f;
    float ot[8][4];
    #pragma unroll
    for (int nt=0;nt<8;nt++){ ot[nt][0]=ot[nt][1]=ot[nt][2]=ot[nt][3]=0.f; }

    for (int jt = jlo; jt <= jhi; jt++) {
        const int j0 = jt*TB;
        __syncthreads();
        {   // stage Q (d-interleaved) + V (c-paired)
            int c4 = (tid & 31) * 4;
            for (int d2 = tid>>5; d2 < 32; d2 += 8) {
                int d = 2*d2;
                float4 qa = *(const float4*)(Q + base + (size_t)d    *NTOK + j0 + c4);
                float4 qb = *(const float4*)(Q + base + (size_t)(d+1)*NTOK + j0 + c4);
                uint4 o;
                o.x = pack_bf16(qa.x, qb.x); o.y = pack_bf16(qa.y, qb.y);
                o.z = pack_bf16(qa.z, qb.z); o.w = pack_bf16(qa.w, qb.w);
                *(uint4*)(Qsu + d2*136 + c4) = o;
            }
            for (int d = tid>>5; d < 64; d += 8) {
                float4 v4 = *(const float4*)(V + base + (size_t)d*NTOK + j0 + c4);
                uint2 o;
                o.x = pack_bf16(v4.x, v4.y); o.y = pack_bf16(v4.z, v4.w);
                *(uint2*)(Vsu + d*68 + (c4>>1)) = o;
            }
        }
        __syncthreads();

        #pragma unroll
        for (int h2 = 0; h2 < 2; h2++) {
            const int chh = h2*64;
            // ---- S = K.Q over 64 cols ----
            float sf[8][4];
            #pragma unroll
            for (int nt=0;nt<8;nt++){ sf[nt][0]=sf[nt][1]=sf[nt][2]=sf[nt][3]=0.f; }
            #pragma unroll
            for (int k02 = 0; k02 < 32; k02 += 8) {
                uint32_t a0 = Ksu[(wrow+g  )*36 + k02+j  ];
                uint32_t a1 = Ksu[(wrow+g+8)*36 + k02+j  ];
                uint32_t a2 = Ksu[(wrow+g  )*36 + k02+j+4];
                uint32_t a3 = Ksu[(wrow+g+8)*36 + k02+j+4];
                #pragma unroll
                for (int nt = 0; nt < 8; nt++) {
                    uint32_t b0 = Qsu[(k02+j  )*136 + chh + nt*8+g];
                    uint32_t b1 = Qsu[(k02+j+4)*136 + chh + nt*8+g];
                    mma_bf16(sf[nt], a0,a1,a2,a3, b0,b1);
                }
            }
            // ---- max-free softmax: P = exp(S), accumulate l per-thread ----
            #pragma unroll
            for (int nt=0; nt<8; nt++) {
                sf[nt][0] = __expf(sf[nt][0]);
                sf[nt][1] = __expf(sf[nt][1]);
                sf[nt][2] = __expf(sf[nt][2]);
                sf[nt][3] = __expf(sf[nt][3]);
                l0 += sf[nt][0] + sf[nt][1];
                l1 += sf[nt][2] + sf[nt][3];
                Pwu[(g  )*36 + nt*4+j] = pack_bf16(sf[nt][0], sf[nt][1]);
                Pwu[(g+8)*36 + nt*4+j] = pack_bf16(sf[nt][2], sf[nt][3]);
            }
            __syncwarp();
            // ---- O += P.V over this half's 64 tokens ----
            #pragma unroll
            for (int k02 = 0; k02 < 32; k02 += 8) {
                uint32_t a0 = Pwu[(g  )*36 + k02+j  ];
                uint32_t a1 = Pwu[(g+8)*36 + k02+j  ];
                uint32_t a2 = Pwu[(g  )*36 + k02+j+4];
                uint32_t a3 = Pwu[(g+8)*36 + k02+j+4];
                #pragma unroll
                for (int nt = 0; nt < 8; nt++) {
                    uint32_t b0 = Vsu[(nt*8+g)*68 + h2*32 + k02+j  ];
                    uint32_t b1 = Vsu[(nt*8+g)*68 + h2*32 + k02+j+4];
                    mma_bf16(ot[nt], a0,a1,a2,a3, b0,b1);
                }
            }
            __syncwarp();
        }
    }

    // reduce l across quad
    l0 += __shfl_xor_sync(0xffffffffu, l0, 1);
    l0 += __shfl_xor_sync(0xffffffffu, l0, 2);
    l1 += __shfl_xor_sync(0xffffffffu, l1, 1);
    l1 += __shfl_xor_sync(0xffffffffu, l1, 2);

    if (it < 4) {
        // single chunk: finalize directly into Vo [b][n][f]
        float inv0 = 1.0f/l0, inv1 = 1.0f/l1;
        const size_t vb = (size_t)b*NTOK*FF;
        const int fcol = h*DH + 2*j;
        #pragma unroll
        for (int nt=0; nt<8; nt++) {
            float2 o0 = { ot[nt][0]*inv0, ot[nt][1]*inv0 };
            float2 o1 = { ot[nt][2]*inv1, ot[nt][3]*inv1 };
            *(float2*)(Vo + vb + (size_t)(i0+wrow+g  )*FF + fcol + nt*8) = o0;
            *(float2*)(Vo + vb + (size_t)(i0+wrow+g+8)*FF + fcol + nt*8) = o1;
        }
    } else {
        const int p = ((b*NH + h)*12 + (it-4))*4 + ch;
        float* op = g_Op + (size_t)p*TB*DH;
        #pragma unroll
        for (int nt=0; nt<8; nt++) {
            float2 o0 = { ot[nt][0], ot[nt][1] };
            float2 o1 = { ot[nt][2], ot[nt][3] };
            *(float2*)(op + (wrow+g  )*DH + nt*8 + 2*j) = o0;
            *(float2*)(op + (wrow+g+8)*DH + nt*8 + 2*j) = o1;
        }
        if (j == 0) {
            g_lp[p*TB + wrow+g  ] = l0;
            g_lp[p*TB + wrow+g+8] = l1;
        }
    }
}

// ---------------- attention merge: flat grid 192 (12 it x 16 bh) ---------
__global__ __launch_bounds__(256) void attn_merge_kernel(float* __restrict__ Vo)
{
    const int m = blockIdx.x;
    const int itx = m >> 4, bh = m & 15;
    const int b = bh >> 3, h = bh & 7;
    const int it = 4 + itx;
    const int nch = it/4 + 1;
    const int pbase = ((b*NH + h)*12 + itx)*4;
    const int t = threadIdx.x;
    const int d4 = (t & 15)*4;
    const size_t vb = (size_t)b*NTOK*FF;

    for (int r = t>>4; r < TB; r += 16) {
        float4 acc = {0.f,0.f,0.f,0.f};
        float l = 0.f;
        for (int c = 0; c < nch; c++) {
            const float* op = g_Op + (size_t)(pbase+c)*TB*DH + r*DH + d4;
            float4 v = *(const float4*)op;
            acc.x += v.x; acc.y += v.y; acc.z += v.z; acc.w += v.w;
            l += g_lp[(pbase+c)*TB + r];
        }
        float inv = 1.0f/l;
        float4 o = { acc.x*inv, acc.y*inv, acc.z*inv, acc.w*inv };
        *(float4*)(Vo + vb + (size_t)(it*TB + r)*FF + h*DH + d4) = o;
    }
}

// ---------------- BN finalize (parallel) + apply ----------------
__global__ void bn_finalize_kernel() {
    const int c = blockIdx.x, t = threadIdx.x;
    float s = g_ps[c*64 + t] + g_ps[c*64 + 32 + t];
    float q = g_pq[c*64 + t] + g_pq[c*64 + 32 + t];
    #pragma unroll
    for (int o = 16; o; o >>= 1) {
        s += __shfl_xor_sync(0xffffffffu, s, o);
        q += __shfl_xor_sync(0xffffffffu, q, o);
    }
    if (t == 0) {
        float mean = s / (float)(Bb*NTOK);
        float var  = q / (float)(Bb*NTOK) - mean*mean;
        g_mean[c] = mean;
        g_istd[c] = rsqrtf(var + BN_EPS);
    }
}

__global__ __launch_bounds__(256) void bn_apply_kernel(
    const float* __restrict__ gamma, const float* __restrict__ beta,
    float* __restrict__ out)
{
    int idx4 = blockIdx.x*256 + threadIdx.x;
    int c = (idx4 >> 9) & (COUT-1);
    float4 v = *((const float4*)g_y + idx4);
    float mu = g_mean[c], is = g_istd[c]*gamma[c], be = beta[c];
    float4 o;
    o.x = (v.x-mu)*is + be; o.y = (v.y-mu)*is + be;
    o.z = (v.z-mu)*is + be; o.w = (v.w-mu)*is + be;
    *((float4*)out + idx4) = o;
}

// ---------------- launch ----------------
extern "C" void kernel_launch(void* const* d_in, const int* in_sizes, int n_in,
                              void* d_out, int out_size)
{
    const float* x     = (const float*)d_in[0];
    const float* WK    = (const float*)d_in[1];
    const float* WQ    = (const float*)d_in[2];
    const float* WV    = (const float*)d_in[3];
    const float* Wo    = (const float*)d_in[4];
    const float* bo    = (const float*)d_in[5];
    const float* gamma = (const float*)d_in[6];
    const float* beta  = (const float*)d_in[7];
    float* out = (float*)d_out;

    float *pK, *pQ, *pV, *pVo, *pY;
    cudaGetSymbolAddress((void**)&pK,  g_K);
    cudaGetSymbolAddress((void**)&pQ,  g_Q);
    cudaGetSymbolAddress((void**)&pV,  g_V);
    cudaGetSymbolAddress((void**)&pVo, g_Vo);
    cudaGetSymbolAddress((void**)&pY,  g_y);

    dim3 gq(NTOK/64, 12, Bb);
    qkv_kernel<<<gq, 256>>>(WK, WQ, WV, x, pK, pQ, pV);

    size_t smem = (size_t)(128*36 + 32*136 + 64*68 + 8*16*36) * 4;
    cudaFuncSetAttribute(attn_kernel, cudaFuncAttributeMaxDynamicSharedMemorySize, (int)smem);
    attn_kernel<<<640, 256, smem>>>(pK, pQ, pV, pVo);

    attn_merge_kernel<<<192, 256>>>(pVo);

    dim3 gp(NTOK/64, COUT/128, Bb);
    proj_kernel<<<gp, 256>>>(Wo, pVo, bo, x, pY);

    bn_finalize_kernel<<<COUT, 32>>>();
    bn_apply_kernel<<<(Bb*COUT*NTOK/4 + 255)/256, 256>>>(gamma, beta, out);
}

// round 6
// speedup vs baseline: 8.5487x; 1.2791x over previous
#include <cuda_runtime.h>
#include <cuda_bf16.h>
#include <math.h>
#include <stdint.h>

#define Bb    2
#define CIN   256
#define FF    512
#define COUT  256
#define NH    8
#define DH    64
#define NTOK  2048
#define TB    128
#define Tt    16
#define INV_TEMP (1.0f/16.0f)
#define BN_EPS 1e-5f

// ---------------- scratch (all bf16 stored as packed uint32 words) -------
__device__ uint32_t g_Wb[4*65536];        // WK,WQ,WV rows 128w; Wo rows 256w
__device__ uint32_t g_Kb[Bb*NTOK*FF/2];   // [b][n][f/2]  (K pre-scaled 1/TEMP)
__device__ uint32_t g_Qb[Bb*NTOK*FF/2];   // [b][n][f/2]
__device__ uint32_t g_Vb[Bb*FF*NTOK/2];   // [b][f][n/2]
__device__ uint32_t g_Vo[Bb*NTOK*FF/2];   // [b][n][f/2]
__device__ float g_y [Bb*COUT*NTOK];      // [b][c][n] fp32
__device__ float g_Op[Bb*NH*12*4*TB*DH];  // attention partial O (it>=4)
__device__ float g_lp[Bb*NH*12*4*TB];     // attention partial l
__device__ float g_ps[COUT*64];
__device__ float g_pq[COUT*64];
__device__ float g_mean[COUT];
__device__ float g_istd[COUT];

// unit tables: 40 (it,chunk) units, LPT order
__constant__ int8_t U_IT[40] = {3,4,5,6,7,7,8,8,9,9,10,10,11,11,11,12,12,12,
                                13,13,13,14,14,14,15,15,15,15,
                                2,6,10,14, 1,5,9,13, 0,4,8,12};
__constant__ int8_t U_CH[40] = {0,0,0,0,0,1,0,1,0,1,0,1,0,1,2,0,1,2,
                                0,1,2,0,1,2,0,1,2,3,
                                0,1,2,3, 0,1,2,3, 0,1,2,3};

// ---------------- helpers ----------------
__device__ __forceinline__ uint32_t pack_bf16(float lo, float hi) {
    uint32_t r;
    asm("cvt.rn.bf16x2.f32 %0, %1, %2;" : "=r"(r) : "f"(hi), "f"(lo));
    return r;
}
__device__ __forceinline__ void mma_bf16(float d[4],
    uint32_t a0, uint32_t a1, uint32_t a2, uint32_t a3,
    uint32_t b0, uint32_t b1)
{
    asm volatile(
      "mma.sync.aligned.m16n8k16.row.col.f32.bf16.bf16.f32 "
      "{%0,%1,%2,%3}, {%4,%5,%6,%7}, {%8,%9}, {%0,%1,%2,%3};"
      : "+f"(d[0]), "+f"(d[1]), "+f"(d[2]), "+f"(d[3])
      : "r"(a0), "r"(a1), "r"(a2), "r"(a3), "r"(b0), "r"(b1));
}
__device__ __forceinline__ uint32_t smem_u32(const void* p) {
    return (uint32_t)__cvta_generic_to_shared(p);
}
__device__ __forceinline__ void cp16(uint32_t s, const void* g) {
    asm volatile("cp.async.cg.shared.global [%0], [%1], 16;" :: "r"(s), "l"(g));
}
#define CP_COMMIT asm volatile("cp.async.commit_group;")
#define CP_WAIT0  asm volatile("cp.async.wait_group 0;")

// ---------------- weight conversion: fp32 -> bf16 packed ----------------
__global__ __launch_bounds__(256) void conv_w_kernel(
    const float* __restrict__ WK, const float* __restrict__ WQ,
    const float* __restrict__ WV, const float* __restrict__ Wo)
{
    int e8 = blockIdx.x*256 + threadIdx.x;   // handles 8 elements
    int e  = e8*8;
    const float* src; int off;
    if      (e < 131072) { src = WK; off = e; }
    else if (e < 262144) { src = WQ; off = e - 131072; }
    else if (e < 393216) { src = WV; off = e - 262144; }
    else                 { src = Wo; off = e - 393216; }
    float4 a = *(const float4*)(src + off);
    float4 c = *(const float4*)(src + off + 4);
    uint4 o;
    o.x = pack_bf16(a.x, a.y); o.y = pack_bf16(a.z, a.w);
    o.z = pack_bf16(c.x, c.y); o.w = pack_bf16(c.z, c.w);
    *(uint4*)(g_Wb + e8*4) = o;
}

// ---------------- fused QKV GEMM (pipelined): grid (32, 12, 2) ----------
__global__ __launch_bounds__(256) void qkv_kernel(
    const float* __restrict__ X,
    uint32_t* __restrict__ Kb, uint32_t* __restrict__ Qb,
    uint32_t* __restrict__ Vb)
{
    __shared__ __align__(16) uint32_t Wsu[2][128*20];
    __shared__ __align__(16) uint32_t Xsu[2][16*72];
    const int b = blockIdx.z, mb = blockIdx.y, n0 = blockIdx.x*64;
    const int sel = mb >> 2, m0 = (mb & 3)*128;
    const uint32_t* W = g_Wb + sel*65536;    // rows of 128 words
    const int tid = threadIdx.x, w = tid>>5, lane = tid&31;
    const int g = lane>>2, j = lane&3, wrow = w*16;
    const float* Xp = X + (size_t)b*CIN*NTOK + n0;
    const int k2 = tid>>4, n4 = (tid&15)*4;

    float sf[8][4];
    #pragma unroll
    for (int nt=0;nt<8;nt++){ sf[nt][0]=sf[nt][1]=sf[nt][2]=sf[nt][3]=0.f; }

    // prologue: W chunk0 async, X chunk0 -> regs
    #pragma unroll
    for (int i=0;i<2;i++){
        int idx = tid + i*256, m = idx>>2, seg = idx&3;
        cp16(smem_u32(&Wsu[0][m*20 + seg*4]), W + (size_t)(m0+m)*128 + seg*4);
    }
    CP_COMMIT;
    float4 xr0 = *(const float4*)(Xp + (size_t)(2*k2  )*NTOK + n4);
    float4 xr1 = *(const float4*)(Xp + (size_t)(2*k2+1)*NTOK + n4);

    for (int c = 0; c < 8; c++) {
        int cur = c & 1;
        CP_WAIT0;
        {   uint4 o;
            o.x = pack_bf16(xr0.x, xr1.x); o.y = pack_bf16(xr0.y, xr1.y);
            o.z = pack_bf16(xr0.z, xr1.z); o.w = pack_bf16(xr0.w, xr1.w);
            *(uint4*)&Xsu[cur][k2*72 + n4] = o;
        }
        __syncthreads();
        if (c < 7) {
            #pragma unroll
            for (int i=0;i<2;i++){
                int idx = tid + i*256, m = idx>>2, seg = idx&3;
                cp16(smem_u32(&Wsu[cur^1][m*20 + seg*4]),
                     W + (size_t)(m0+m)*128 + (c+1)*16 + seg*4);
            }
            CP_COMMIT;
            xr0 = *(const float4*)(Xp + (size_t)((c+1)*32 + 2*k2  )*NTOK + n4);
            xr1 = *(const float4*)(Xp + (size_t)((c+1)*32 + 2*k2+1)*NTOK + n4);
        }
        const uint32_t* Ws = Wsu[cur];
        const uint32_t* Xs = Xsu[cur];
        #pragma unroll
        for (int k02 = 0; k02 < 16; k02 += 8) {
            uint32_t a0 = Ws[(wrow+g  )*20 + k02+j  ];
            uint32_t a1 = Ws[(wrow+g+8)*20 + k02+j  ];
            uint32_t a2 = Ws[(wrow+g  )*20 + k02+j+4];
            uint32_t a3 = Ws[(wrow+g+8)*20 + k02+j+4];
            #pragma unroll
            for (int nt = 0; nt < 8; nt++) {
                uint32_t b0 = Xs[(k02+j  )*72 + nt*8+g];
                uint32_t b1 = Xs[(k02+j+4)*72 + nt*8+g];
                mma_bf16(sf[nt], a0,a1,a2,a3, b0,b1);
            }
        }
    }
    __syncthreads();   // smem reuse below

    if (sel == 2) {
        // V: [b][f][n/2] natural
        size_t basew = ((size_t)b*FF + m0)*1024 + (n0>>1);
        #pragma unroll
        for (int nt=0; nt<8; nt++) {
            Vb[basew + (size_t)(wrow+g  )*1024 + nt*4 + j] = pack_bf16(sf[nt][0], sf[nt][1]);
            Vb[basew + (size_t)(wrow+g+8)*1024 + nt*4 + j] = pack_bf16(sf[nt][2], sf[nt][3]);
        }
    } else {
        // K/Q: transpose to [b][n][f/2] via smem tile [64 n][136 bf16]
        const float scale = (sel==0) ? INV_TEMP : 1.f;
        __nv_bfloat16* tileh = (__nv_bfloat16*)&Wsu[0][0];
        #pragma unroll
        for (int nt=0; nt<8; nt++) {
            int c = nt*8 + 2*j;
            tileh[(c  )*136 + wrow+g  ] = __float2bfloat16(sf[nt][0]*scale);
            tileh[(c+1)*136 + wrow+g  ] = __float2bfloat16(sf[nt][1]*scale);
            tileh[(c  )*136 + wrow+g+8] = __float2bfloat16(sf[nt][2]*scale);
            tileh[(c+1)*136 + wrow+g+8] = __float2bfloat16(sf[nt][3]*scale);
        }
        __syncthreads();
        uint32_t* C = (sel==0) ? Kb : Qb;
        const uint32_t* tw = (const uint32_t*)tileh;   // stride 68 words
        int cc = tid>>2, seg = tid&3;
        size_t dstw = ((size_t)b*NTOK + n0 + cc)*256 + (m0>>1) + seg*16;
        #pragma unroll
        for (int q=0; q<4; q++) {
            uint4 v = *(const uint4*)(tw + cc*68 + seg*16 + q*4);
            *(uint4*)(C + dstw + q*4) = v;
        }
    }
}

// ---------------- proj (fully async pipelined): grid (32,2,2) ------------
__global__ __launch_bounds__(256) void proj_kernel(
    const uint32_t* __restrict__ Vo,
    const float* __restrict__ bias, const float* __restrict__ skip,
    float* __restrict__ Y)
{
    __shared__ __align__(16) uint32_t Wsu[2][128*20];
    __shared__ __align__(16) uint32_t Xsu[2][64*20];
    const int b = blockIdx.z, m0 = blockIdx.y*128, n0 = blockIdx.x*64;
    const int tid = threadIdx.x, w = tid>>5, lane = tid&31;
    const int g = lane>>2, j = lane&3, wrow = w*16;
    const uint32_t* W  = g_Wb + 3*65536;                      // Wo rows of 256 words
    const uint32_t* Vp = Vo + ((size_t)b*NTOK + n0)*256;      // rows of 256 words

    float sf[8][4];
    #pragma unroll
    for (int nt=0;nt<8;nt++){ sf[nt][0]=sf[nt][1]=sf[nt][2]=sf[nt][3]=0.f; }

    // prologue chunk0
    #pragma unroll
    for (int i=0;i<2;i++){
        int idx = tid + i*256, m = idx>>2, seg = idx&3;
        cp16(smem_u32(&Wsu[0][m*20 + seg*4]), W + (size_t)(m0+m)*256 + seg*4);
    }
    {   int r = tid>>2, seg = tid&3;
        cp16(smem_u32(&Xsu[0][r*20 + seg*4]), Vp + (size_t)r*256 + seg*4);
    }
    CP_COMMIT;

    for (int c = 0; c < 16; c++) {
        int cur = c & 1;
        CP_WAIT0;
        __syncthreads();
        if (c < 15) {
            #pragma unroll
            for (int i=0;i<2;i++){
                int idx = tid + i*256, m = idx>>2, seg = idx&3;
                cp16(smem_u32(&Wsu[cur^1][m*20 + seg*4]),
                     W + (size_t)(m0+m)*256 + (c+1)*16 + seg*4);
            }
            {   int r = tid>>2, seg = tid&3;
                cp16(smem_u32(&Xsu[cur^1][r*20 + seg*4]),
                     Vp + (size_t)r*256 + (c+1)*16 + seg*4);
            }
            CP_COMMIT;
        }
        const uint32_t* Ws = Wsu[cur];
        const uint32_t* Xs = Xsu[cur];
        #pragma unroll
        for (int k02 = 0; k02 < 16; k02 += 8) {
            uint32_t a0 = Ws[(wrow+g  )*20 + k02+j  ];
            uint32_t a1 = Ws[(wrow+g+8)*20 + k02+j  ];
            uint32_t a2 = Ws[(wrow+g  )*20 + k02+j+4];
            uint32_t a3 = Ws[(wrow+g+8)*20 + k02+j+4];
            #pragma unroll
            for (int nt = 0; nt < 8; nt++) {
                uint32_t b0 = Xs[(nt*8+g)*20 + k02+j  ];
                uint32_t b1 = Xs[(nt*8+g)*20 + k02+j+4];
                mma_bf16(sf[nt], a0,a1,a2,a3, b0,b1);
            }
        }
    }

    const int row0 = m0 + wrow + g, row1 = row0 + 8;
    const float b0v = bias[row0], b1v = bias[row1];
    const size_t ybase = (size_t)b*COUT*NTOK;
    float s0=0.f,q0=0.f,s1=0.f,q1=0.f;
    #pragma unroll
    for (int nt=0; nt<8; nt++) {
        int col = n0 + nt*8 + 2*j;
        float2 sk0 = *(const float2*)(skip + ybase + (size_t)row0*NTOK + col);
        float2 sk1 = *(const float2*)(skip + ybase + (size_t)row1*NTOK + col);
        float2 y0 = { fmaxf(sf[nt][0]+b0v,0.f)+sk0.x, fmaxf(sf[nt][1]+b0v,0.f)+sk0.y };
        float2 y1 = { fmaxf(sf[nt][2]+b1v,0.f)+sk1.x, fmaxf(sf[nt][3]+b1v,0.f)+sk1.y };
        *(float2*)(Y + ybase + (size_t)row0*NTOK + col) = y0;
        *(float2*)(Y + ybase + (size_t)row1*NTOK + col) = y1;
        s0 += y0.x + y0.y;  q0 += y0.x*y0.x + y0.y*y0.y;
        s1 += y1.x + y1.y;  q1 += y1.x*y1.x + y1.y*y1.y;
    }
    s0 += __shfl_xor_sync(0xffffffffu, s0, 1); s0 += __shfl_xor_sync(0xffffffffu, s0, 2);
    q0 += __shfl_xor_sync(0xffffffffu, q0, 1); q0 += __shfl_xor_sync(0xffffffffu, q0, 2);
    s1 += __shfl_xor_sync(0xffffffffu, s1, 1); s1 += __shfl_xor_sync(0xffffffffu, s1, 2);
    q1 += __shfl_xor_sync(0xffffffffu, q1, 1); q1 += __shfl_xor_sync(0xffffffffu, q1, 2);
    if (j == 0) {
        int part = b*32 + blockIdx.x;
        g_ps[row0*64 + part] = s0;  g_pq[row0*64 + part] = q0;
        g_ps[row1*64 + part] = s1;  g_pq[row1*64 + part] = q1;
    }
}

// ---------------- attention (cp.async double-buffered): flat grid 640 ----
__global__ __launch_bounds__(256, 2) void attn_kernel(
    const uint32_t* __restrict__ Kb, const uint32_t* __restrict__ Qb,
    const uint32_t* __restrict__ Vb, uint32_t* __restrict__ Vo)
{
    extern __shared__ __align__(16) uint32_t smu[];
    uint32_t* Ksu = smu;                     // [128 r][36]
    uint32_t* Qsu = Ksu + 128*36;            // [2][128 c][36]
    uint32_t* Vsu = Qsu + 2*128*36;          // [2][64 d][68]
    uint32_t* Psu = Vsu + 2*64*68;           // [8 warps][16 r][36]

    const int ux = blockIdx.x;
    const int unit = ux >> 4, bh = ux & 15;
    const int b = bh >> 3, h = bh & 7;
    const int it = U_IT[unit], ch = U_CH[unit];
    const int i0 = it*TB;
    const int jlo = ch*4;
    const int jhi = (jlo+3 < it) ? jlo+3 : it;

    const int tid = threadIdx.x, w = tid>>5, lane = tid&31;
    const int g = lane>>2, j = lane&3, wrow = w*16;
    uint32_t* Pwu = Psu + w*16*36;

    const size_t rowKQ = (size_t)b*NTOK*256 + h*32;        // + n*256
    const size_t rowV  = ((size_t)b*FF + h*64)*1024;       // + d*1024 + (j0>>1)

    // issue K (once) + QV tile jlo into buf0 — one group
    #pragma unroll
    for (int i=0;i<4;i++){
        int idx = tid + i*256, r = idx>>3, seg = idx&7;
        cp16(smem_u32(Ksu + r*36 + seg*4), Kb + rowKQ + (size_t)(i0+r)*256 + seg*4);
    }
    {
        int j0 = jlo*TB;
        #pragma unroll
        for (int i=0;i<4;i++){
            int idx = tid + i*256, r = idx>>3, seg = idx&7;
            cp16(smem_u32(Qsu + r*36 + seg*4), Qb + rowKQ + (size_t)(j0+r)*256 + seg*4);
        }
        #pragma unroll
        for (int i=0;i<4;i++){
            int idx = tid + i*256, d = idx>>4, seg = idx&15;
            cp16(smem_u32(Vsu + d*68 + seg*4), Vb + rowV + (size_t)d*1024 + (j0>>1) + seg*4);
        }
    }
    CP_COMMIT;

    float l0 = 0.f, l1 = 0.f;
    float ot[8][4];
    #pragma unroll
    for (int nt=0;nt<8;nt++){ ot[nt][0]=ot[nt][1]=ot[nt][2]=ot[nt][3]=0.f; }

    for (int jt = jlo; jt <= jhi; jt++) {
        const int cur = (jt - jlo) & 1;
        const uint32_t* Qc = Qsu + cur*128*36;
        const uint32_t* Vc = Vsu + cur*64*68;
        CP_WAIT0;
        __syncthreads();
        if (jt < jhi) {
            uint32_t* Qn = Qsu + (cur^1)*128*36;
            uint32_t* Vn = Vsu + (cur^1)*64*68;
            int j0n = (jt+1)*TB;
            #pragma unroll
            for (int i=0;i<4;i++){
                int idx = tid + i*256, r = idx>>3, seg = idx&7;
                cp16(smem_u32(Qn + r*36 + seg*4), Qb + rowKQ + (size_t)(j0n+r)*256 + seg*4);
            }
            #pragma unroll
            for (int i=0;i<4;i++){
                int idx = tid + i*256, d = idx>>4, seg = idx&15;
                cp16(smem_u32(Vn + d*68 + seg*4), Vb + rowV + (size_t)d*1024 + (j0n>>1) + seg*4);
            }
            CP_COMMIT;
        }

        #pragma unroll
        for (int h2 = 0; h2 < 2; h2++) {
            const int chh = h2*64;
            float sf[8][4];
            #pragma unroll
            for (int nt=0;nt<8;nt++){ sf[nt][0]=sf[nt][1]=sf[nt][2]=sf[nt][3]=0.f; }
            #pragma unroll
            for (int k02 = 0; k02 < 32; k02 += 8) {
                uint32_t a0 = Ksu[(wrow+g  )*36 + k02+j  ];
                uint32_t a1 = Ksu[(wrow+g+8)*36 + k02+j  ];
                uint32_t a2 = Ksu[(wrow+g  )*36 + k02+j+4];
                uint32_t a3 = Ksu[(wrow+g+8)*36 + k02+j+4];
                #pragma unroll
                for (int nt = 0; nt < 8; nt++) {
                    uint32_t b0 = Qc[(chh + nt*8+g)*36 + k02+j  ];
                    uint32_t b1 = Qc[(chh + nt*8+g)*36 + k02+j+4];
                    mma_bf16(sf[nt], a0,a1,a2,a3, b0,b1);
                }
            }
            // max-free softmax: P = exp(S)
            #pragma unroll
            for (int nt=0; nt<8; nt++) {
                sf[nt][0] = __expf(sf[nt][0]);
                sf[nt][1] = __expf(sf[nt][1]);
                sf[nt][2] = __expf(sf[nt][2]);
                sf[nt][3] = __expf(sf[nt][3]);
                l0 += sf[nt][0] + sf[nt][1];
                l1 += sf[nt][2] + sf[nt][3];
                Pwu[(g  )*36 + nt*4+j] = pack_bf16(sf[nt][0], sf[nt][1]);
                Pwu[(g+8)*36 + nt*4+j] = pack_bf16(sf[nt][2], sf[nt][3]);
            }
            __syncwarp();
            #pragma unroll
            for (int k02 = 0; k02 < 32; k02 += 8) {
                uint32_t a0 = Pwu[(g  )*36 + k02+j  ];
                uint32_t a1 = Pwu[(g+8)*36 + k02+j  ];
                uint32_t a2 = Pwu[(g  )*36 + k02+j+4];
                uint32_t a3 = Pwu[(g+8)*36 + k02+j+4];
                #pragma unroll
                for (int nt = 0; nt < 8; nt++) {
                    uint32_t b0 = Vc[(nt*8+g)*68 + h2*32 + k02+j  ];
                    uint32_t b1 = Vc[(nt*8+g)*68 + h2*32 + k02+j+4];
                    mma_bf16(ot[nt], a0,a1,a2,a3, b0,b1);
                }
            }
            __syncwarp();
        }
    }

    l0 += __shfl_xor_sync(0xffffffffu, l0, 1);
    l0 += __shfl_xor_sync(0xffffffffu, l0, 2);
    l1 += __shfl_xor_sync(0xffffffffu, l1, 1);
    l1 += __shfl_xor_sync(0xffffffffu, l1, 2);

    if (it < 4) {
        float inv0 = 1.0f/l0, inv1 = 1.0f/l1;
        size_t d0 = ((size_t)b*NTOK + i0 + wrow + g)*256 + h*32;
        size_t d1 = ((size_t)b*NTOK + i0 + wrow + g + 8)*256 + h*32;
        #pragma unroll
        for (int nt=0; nt<8; nt++) {
            Vo[d0 + nt*4 + j] = pack_bf16(ot[nt][0]*inv0, ot[nt][1]*inv0);
            Vo[d1 + nt*4 + j] = pack_bf16(ot[nt][2]*inv1, ot[nt][3]*inv1);
        }
    } else {
        const int p = ((b*NH + h)*12 + (it-4))*4 + ch;
        float* op = g_Op + (size_t)p*TB*DH;
        #pragma unroll
        for (int nt=0; nt<8; nt++) {
            float2 o0 = { ot[nt][0], ot[nt][1] };
            float2 o1 = { ot[nt][2], ot[nt][3] };
            *(float2*)(op + (wrow+g  )*DH + nt*8 + 2*j) = o0;
            *(float2*)(op + (wrow+g+8)*DH + nt*8 + 2*j) = o1;
        }
        if (j == 0) {
            g_lp[p*TB + wrow+g  ] = l0;
            g_lp[p*TB + wrow+g+8] = l1;
        }
    }
}

// ---------------- attention merge: flat grid 192 -------------------------
__global__ __launch_bounds__(256) void attn_merge_kernel(uint32_t* __restrict__ Vo)
{
    const int m = blockIdx.x;
    const int itx = m >> 4, bh = m & 15;
    const int b = bh >> 3, h = bh & 7;
    const int it = 4 + itx;
    const int nch = it/4 + 1;
    const int pbase = ((b*NH + h)*12 + itx)*4;
    const int t = threadIdx.x;
    const int d4 = (t & 15)*4;

    for (int r = t>>4; r < TB; r += 16) {
        float4 acc = {0.f,0.f,0.f,0.f};
        float l = 0.f;
        for (int c = 0; c < nch; c++) {
            const float* op = g_Op + (size_t)(pbase+c)*TB*DH + r*DH + d4;
            float4 v = *(const float4*)op;
            acc.x += v.x; acc.y += v.y; acc.z += v.z; acc.w += v.w;
            l += g_lp[(pbase+c)*TB + r];
        }
        float inv = 1.0f/l;
        uint2 o;
        o.x = pack_bf16(acc.x*inv, acc.y*inv);
        o.y = pack_bf16(acc.z*inv, acc.w*inv);
        *(uint2*)(Vo + ((size_t)b*NTOK + it*TB + r)*256 + h*32 + (d4>>1)) = o;
    }
}

// ---------------- BN finalize + apply ----------------
__global__ void bn_finalize_kernel() {
    const int c = blockIdx.x, t = threadIdx.x;
    float s = g_ps[c*64 + t] + g_ps[c*64 + 32 + t];
    float q = g_pq[c*64 + t] + g_pq[c*64 + 32 + t];
    #pragma unroll
    for (int o = 16; o; o >>= 1) {
        s += __shfl_xor_sync(0xffffffffu, s, o);
        q += __shfl_xor_sync(0xffffffffu, q, o);
    }
    if (t == 0) {
        float mean = s / (float)(Bb*NTOK);
        float var  = q / (float)(Bb*NTOK) - mean*mean;
        g_mean[c] = mean;
        g_istd[c] = rsqrtf(var + BN_EPS);
    }
}

__global__ __launch_bounds__(256) void bn_apply_kernel(
    const float* __restrict__ gamma, const float* __restrict__ beta,
    float* __restrict__ out)
{
    int idx4 = blockIdx.x*256 + threadIdx.x;
    int c = (idx4 >> 9) & (COUT-1);
    float4 v = *((const float4*)g_y + idx4);
    float mu = g_mean[c], is = g_istd[c]*gamma[c], be = beta[c];
    float4 o;
    o.x = (v.x-mu)*is + be; o.y = (v.y-mu)*is + be;
    o.z = (v.z-mu)*is + be; o.w = (v.w-mu)*is + be;
    *((float4*)out + idx4) = o;
}

// ---------------- launch ----------------
extern "C" void kernel_launch(void* const* d_in, const int* in_sizes, int n_in,
                              void* d_out, int out_size)
{
    const float* x     = (const float*)d_in[0];
    const float* WK    = (const float*)d_in[1];
    const float* WQ    = (const float*)d_in[2];
    const float* WV    = (const float*)d_in[3];
    const float* Wo    = (const float*)d_in[4];
    const float* bo    = (const float*)d_in[5];
    const float* gamma = (const float*)d_in[6];
    const float* beta  = (const float*)d_in[7];
    float* out = (float*)d_out;

    uint32_t *pK, *pQ, *pV, *pVo;
    float *pY;
    cudaGetSymbolAddress((void**)&pK,  g_Kb);
    cudaGetSymbolAddress((void**)&pQ,  g_Qb);
    cudaGetSymbolAddress((void**)&pV,  g_Vb);
    cudaGetSymbolAddress((void**)&pVo, g_Vo);
    cudaGetSymbolAddress((void**)&pY,  g_y);

    conv_w_kernel<<<256, 256>>>(WK, WQ, WV, Wo);

    dim3 gq(NTOK/64, 12, Bb);
    qkv_kernel<<<gq, 256>>>(x, pK, pQ, pV);

    size_t smem = (size_t)(128*36 + 2*128*36 + 2*64*68 + 8*16*36) * 4;
    cudaFuncSetAttribute(attn_kernel, cudaFuncAttributeMaxDynamicSharedMemorySize, (int)smem);
    attn_kernel<<<640, 256, smem>>>(pK, pQ, pV, pVo);

    attn_merge_kernel<<<192, 256>>>(pVo);

    dim3 gp(NTOK/64, COUT/128, Bb);
    proj_kernel<<<gp, 256>>>(pVo, bo, x, pY);

    bn_finalize_kernel<<<COUT, 32>>>();
    bn_apply_kernel<<<(Bb*COUT*NTOK/4 + 255)/256, 256>>>(gamma, beta, out);
}

// round 7
// speedup vs baseline: 8.9460x; 1.0465x over previous
#include <cuda_runtime.h>
#include <cuda_bf16.h>
#include <math.h>
#include <stdint.h>

#define Bb    2
#define CIN   256
#define FF    512
#define COUT  256
#define NH    8
#define DH    64
#define NTOK  2048
#define TB    128
#define Tt    16
#define INV_TEMP (1.0f/16.0f)
#define BN_EPS 1e-5f

// ---------------- scratch (all bf16 stored as packed uint32 words) -------
__device__ uint32_t g_Wb[4*65536];        // WK,WQ,WV rows 128w; Wo rows 256w
__device__ uint32_t g_Kb[Bb*NTOK*FF/2];   // [b][n][f/2]  (K pre-scaled 1/TEMP)
__device__ uint32_t g_Qb[Bb*NTOK*FF/2];   // [b][n][f/2]
__device__ uint32_t g_Vb[Bb*FF*NTOK/2];   // [b][f][n/2]
__device__ uint32_t g_Vo[Bb*NTOK*FF/2];   // [b][n][f/2]
__device__ float g_y [Bb*COUT*NTOK];      // [b][c][n] fp32
__device__ uint32_t g_Opb[Bb*NH*12*4*TB*(DH/2)];  // partial O, bf16 packed
__device__ float g_lp[Bb*NH*12*4*TB];     // partial l
__device__ float g_ps[COUT*64];
__device__ float g_pq[COUT*64];
__device__ float g_mean[COUT];
__device__ float g_istd[COUT];

// unit tables: 40 (it,chunk) units, LPT order
__constant__ int8_t U_IT[40] = {3,4,5,6,7,7,8,8,9,9,10,10,11,11,11,12,12,12,
                                13,13,13,14,14,14,15,15,15,15,
                                2,6,10,14, 1,5,9,13, 0,4,8,12};
__constant__ int8_t U_CH[40] = {0,0,0,0,0,1,0,1,0,1,0,1,0,1,2,0,1,2,
                                0,1,2,0,1,2,0,1,2,3,
                                0,1,2,3, 0,1,2,3, 0,1,2,3};

// ---------------- helpers ----------------
__device__ __forceinline__ uint32_t pack_bf16(float lo, float hi) {
    uint32_t r;
    asm("cvt.rn.bf16x2.f32 %0, %1, %2;" : "=r"(r) : "f"(hi), "f"(lo));
    return r;
}
__device__ __forceinline__ void mma_bf16(float d[4],
    uint32_t a0, uint32_t a1, uint32_t a2, uint32_t a3,
    uint32_t b0, uint32_t b1)
{
    asm volatile(
      "mma.sync.aligned.m16n8k16.row.col.f32.bf16.bf16.f32 "
      "{%0,%1,%2,%3}, {%4,%5,%6,%7}, {%8,%9}, {%0,%1,%2,%3};"
      : "+f"(d[0]), "+f"(d[1]), "+f"(d[2]), "+f"(d[3])
      : "r"(a0), "r"(a1), "r"(a2), "r"(a3), "r"(b0), "r"(b1));
}
__device__ __forceinline__ uint32_t smem_u32(const void* p) {
    return (uint32_t)__cvta_generic_to_shared(p);
}
__device__ __forceinline__ void cp16(uint32_t s, const void* g) {
    asm volatile("cp.async.cg.shared.global [%0], [%1], 16;" :: "r"(s), "l"(g));
}
#define CP_COMMIT asm volatile("cp.async.commit_group;")
#define CP_WAIT0  asm volatile("cp.async.wait_group 0;")

// ---------------- weight conversion: fp32 -> bf16 packed ----------------
__global__ __launch_bounds__(256) void conv_w_kernel(
    const float* __restrict__ WK, const float* __restrict__ WQ,
    const float* __restrict__ WV, const float* __restrict__ Wo)
{
    int e8 = blockIdx.x*256 + threadIdx.x;
    int e  = e8*8;
    const float* src; int off;
    if      (e < 131072) { src = WK; off = e; }
    else if (e < 262144) { src = WQ; off = e - 131072; }
    else if (e < 393216) { src = WV; off = e - 262144; }
    else                 { src = Wo; off = e - 393216; }
    float4 a = *(const float4*)(src + off);
    float4 c = *(const float4*)(src + off + 4);
    uint4 o;
    o.x = pack_bf16(a.x, a.y); o.y = pack_bf16(a.z, a.w);
    o.z = pack_bf16(c.x, c.y); o.w = pack_bf16(c.z, c.w);
    *(uint4*)(g_Wb + e8*4) = o;
}

// ---------------- fused QKV GEMM (pipelined): grid (32, 12, 2) ----------
__global__ __launch_bounds__(256) void qkv_kernel(
    const float* __restrict__ X,
    uint32_t* __restrict__ Kb, uint32_t* __restrict__ Qb,
    uint32_t* __restrict__ Vb)
{
    __shared__ __align__(16) uint32_t Wsu[2][128*20];
    __shared__ __align__(16) uint32_t Xsu[2][16*72];
    const int b = blockIdx.z, mb = blockIdx.y, n0 = blockIdx.x*64;
    const int sel = mb >> 2, m0 = (mb & 3)*128;
    const uint32_t* W = g_Wb + sel*65536;
    const int tid = threadIdx.x, w = tid>>5, lane = tid&31;
    const int g = lane>>2, j = lane&3, wrow = w*16;
    const float* Xp = X + (size_t)b*CIN*NTOK + n0;
    const int k2 = tid>>4, n4 = (tid&15)*4;

    float sf[8][4];
    #pragma unroll
    for (int nt=0;nt<8;nt++){ sf[nt][0]=sf[nt][1]=sf[nt][2]=sf[nt][3]=0.f; }

    #pragma unroll
    for (int i=0;i<2;i++){
        int idx = tid + i*256, m = idx>>2, seg = idx&3;
        cp16(smem_u32(&Wsu[0][m*20 + seg*4]), W + (size_t)(m0+m)*128 + seg*4);
    }
    CP_COMMIT;
    float4 xr0 = *(const float4*)(Xp + (size_t)(2*k2  )*NTOK + n4);
    float4 xr1 = *(const float4*)(Xp + (size_t)(2*k2+1)*NTOK + n4);

    for (int c = 0; c < 8; c++) {
        int cur = c & 1;
        CP_WAIT0;
        {   uint4 o;
            o.x = pack_bf16(xr0.x, xr1.x); o.y = pack_bf16(xr0.y, xr1.y);
            o.z = pack_bf16(xr0.z, xr1.z); o.w = pack_bf16(xr0.w, xr1.w);
            *(uint4*)&Xsu[cur][k2*72 + n4] = o;
        }
        __syncthreads();
        if (c < 7) {
            #pragma unroll
            for (int i=0;i<2;i++){
                int idx = tid + i*256, m = idx>>2, seg = idx&3;
                cp16(smem_u32(&Wsu[cur^1][m*20 + seg*4]),
                     W + (size_t)(m0+m)*128 + (c+1)*16 + seg*4);
            }
            CP_COMMIT;
            xr0 = *(const float4*)(Xp + (size_t)((c+1)*32 + 2*k2  )*NTOK + n4);
            xr1 = *(const float4*)(Xp + (size_t)((c+1)*32 + 2*k2+1)*NTOK + n4);
        }
        const uint32_t* Ws = Wsu[cur];
        const uint32_t* Xs = Xsu[cur];
        #pragma unroll
        for (int k02 = 0; k02 < 16; k02 += 8) {
            uint32_t a0 = Ws[(wrow+g  )*20 + k02+j  ];
            uint32_t a1 = Ws[(wrow+g+8)*20 + k02+j  ];
            uint32_t a2 = Ws[(wrow+g  )*20 + k02+j+4];
            uint32_t a3 = Ws[(wrow+g+8)*20 + k02+j+4];
            #pragma unroll
            for (int nt = 0; nt < 8; nt++) {
                uint32_t b0 = Xs[(k02+j  )*72 + nt*8+g];
                uint32_t b1 = Xs[(k02+j+4)*72 + nt*8+g];
                mma_bf16(sf[nt], a0,a1,a2,a3, b0,b1);
            }
        }
    }
    __syncthreads();

    if (sel == 2) {
        size_t basew = ((size_t)b*FF + m0)*1024 + (n0>>1);
        #pragma unroll
        for (int nt=0; nt<8; nt++) {
            Vb[basew + (size_t)(wrow+g  )*1024 + nt*4 + j] = pack_bf16(sf[nt][0], sf[nt][1]);
            Vb[basew + (size_t)(wrow+g+8)*1024 + nt*4 + j] = pack_bf16(sf[nt][2], sf[nt][3]);
        }
    } else {
        const float scale = (sel==0) ? INV_TEMP : 1.f;
        __nv_bfloat16* tileh = (__nv_bfloat16*)&Wsu[0][0];
        #pragma unroll
        for (int nt=0; nt<8; nt++) {
            int c = nt*8 + 2*j;
            tileh[(c  )*136 + wrow+g  ] = __float2bfloat16(sf[nt][0]*scale);
            tileh[(c+1)*136 + wrow+g  ] = __float2bfloat16(sf[nt][1]*scale);
            tileh[(c  )*136 + wrow+g+8] = __float2bfloat16(sf[nt][2]*scale);
            tileh[(c+1)*136 + wrow+g+8] = __float2bfloat16(sf[nt][3]*scale);
        }
        __syncthreads();
        uint32_t* C = (sel==0) ? Kb : Qb;
        const uint32_t* tw = (const uint32_t*)tileh;
        int cc = tid>>2, seg = tid&3;
        size_t dstw = ((size_t)b*NTOK + n0 + cc)*256 + (m0>>1) + seg*16;
        #pragma unroll
        for (int q=0; q<4; q++) {
            uint4 v = *(const uint4*)(tw + cc*68 + seg*16 + q*4);
            *(uint4*)(C + dstw + q*4) = v;
        }
    }
}

// ---------------- proj (fully async pipelined): grid (32,2,2) ------------
__global__ __launch_bounds__(256) void proj_kernel(
    const uint32_t* __restrict__ Vo,
    const float* __restrict__ bias, const float* __restrict__ skip,
    float* __restrict__ Y)
{
    __shared__ __align__(16) uint32_t Wsu[2][128*20];
    __shared__ __align__(16) uint32_t Xsu[2][64*20];
    const int b = blockIdx.z, m0 = blockIdx.y*128, n0 = blockIdx.x*64;
    const int tid = threadIdx.x, w = tid>>5, lane = tid&31;
    const int g = lane>>2, j = lane&3, wrow = w*16;
    const uint32_t* W  = g_Wb + 3*65536;
    const uint32_t* Vp = Vo + ((size_t)b*NTOK + n0)*256;

    float sf[8][4];
    #pragma unroll
    for (int nt=0;nt<8;nt++){ sf[nt][0]=sf[nt][1]=sf[nt][2]=sf[nt][3]=0.f; }

    #pragma unroll
    for (int i=0;i<2;i++){
        int idx = tid + i*256, m = idx>>2, seg = idx&3;
        cp16(smem_u32(&Wsu[0][m*20 + seg*4]), W + (size_t)(m0+m)*256 + seg*4);
    }
    {   int r = tid>>2, seg = tid&3;
        cp16(smem_u32(&Xsu[0][r*20 + seg*4]), Vp + (size_t)r*256 + seg*4);
    }
    CP_COMMIT;

    for (int c = 0; c < 16; c++) {
        int cur = c & 1;
        CP_WAIT0;
        __syncthreads();
        if (c < 15) {
            #pragma unroll
            for (int i=0;i<2;i++){
                int idx = tid + i*256, m = idx>>2, seg = idx&3;
                cp16(smem_u32(&Wsu[cur^1][m*20 + seg*4]),
                     W + (size_t)(m0+m)*256 + (c+1)*16 + seg*4);
            }
            {   int r = tid>>2, seg = tid&3;
                cp16(smem_u32(&Xsu[cur^1][r*20 + seg*4]),
                     Vp + (size_t)r*256 + (c+1)*16 + seg*4);
            }
            CP_COMMIT;
        }
        const uint32_t* Ws = Wsu[cur];
        const uint32_t* Xs = Xsu[cur];
        #pragma unroll
        for (int k02 = 0; k02 < 16; k02 += 8) {
            uint32_t a0 = Ws[(wrow+g  )*20 + k02+j  ];
            uint32_t a1 = Ws[(wrow+g+8)*20 + k02+j  ];
            uint32_t a2 = Ws[(wrow+g  )*20 + k02+j+4];
            uint32_t a3 = Ws[(wrow+g+8)*20 + k02+j+4];
            #pragma unroll
            for (int nt = 0; nt < 8; nt++) {
                uint32_t b0 = Xs[(nt*8+g)*20 + k02+j  ];
                uint32_t b1 = Xs[(nt*8+g)*20 + k02+j+4];
                mma_bf16(sf[nt], a0,a1,a2,a3, b0,b1);
            }
        }
    }

    const int row0 = m0 + wrow + g, row1 = row0 + 8;
    const float b0v = bias[row0], b1v = bias[row1];
    const size_t ybase = (size_t)b*COUT*NTOK;
    float s0=0.f,q0=0.f,s1=0.f,q1=0.f;
    #pragma unroll
    for (int nt=0; nt<8; nt++) {
        int col = n0 + nt*8 + 2*j;
        float2 sk0 = *(const float2*)(skip + ybase + (size_t)row0*NTOK + col);
        float2 sk1 = *(const float2*)(skip + ybase + (size_t)row1*NTOK + col);
        float2 y0 = { fmaxf(sf[nt][0]+b0v,0.f)+sk0.x, fmaxf(sf[nt][1]+b0v,0.f)+sk0.y };
        float2 y1 = { fmaxf(sf[nt][2]+b1v,0.f)+sk1.x, fmaxf(sf[nt][3]+b1v,0.f)+sk1.y };
        *(float2*)(Y + ybase + (size_t)row0*NTOK + col) = y0;
        *(float2*)(Y + ybase + (size_t)row1*NTOK + col) = y1;
        s0 += y0.x + y0.y;  q0 += y0.x*y0.x + y0.y*y0.y;
        s1 += y1.x + y1.y;  q1 += y1.x*y1.x + y1.y*y1.y;
    }
    s0 += __shfl_xor_sync(0xffffffffu, s0, 1); s0 += __shfl_xor_sync(0xffffffffu, s0, 2);
    q0 += __shfl_xor_sync(0xffffffffu, q0, 1); q0 += __shfl_xor_sync(0xffffffffu, q0, 2);
    s1 += __shfl_xor_sync(0xffffffffu, s1, 1); s1 += __shfl_xor_sync(0xffffffffu, s1, 2);
    q1 += __shfl_xor_sync(0xffffffffu, q1, 1); q1 += __shfl_xor_sync(0xffffffffu, q1, 2);
    if (j == 0) {
        int part = b*32 + blockIdx.x;
        g_ps[row0*64 + part] = s0;  g_pq[row0*64 + part] = q0;
        g_ps[row1*64 + part] = s1;  g_pq[row1*64 + part] = q1;
    }
}

// ---------------- attention (cp.async double-buffered): flat grid 640 ----
__global__ __launch_bounds__(256, 2) void attn_kernel(
    const uint32_t* __restrict__ Kb, const uint32_t* __restrict__ Qb,
    const uint32_t* __restrict__ Vb, uint32_t* __restrict__ Vo)
{
    extern __shared__ __align__(16) uint32_t smu[];
    uint32_t* Ksu = smu;                     // [128 r][36]
    uint32_t* Qsu = Ksu + 128*36;            // [2][128 c][36]
    uint32_t* Vsu = Qsu + 2*128*36;          // [2][64 d][68]
    uint32_t* Psu = Vsu + 2*64*68;           // [8 warps][16 r][36]

    const int ux = blockIdx.x;
    const int unit = ux >> 4, bh = ux & 15;
    const int b = bh >> 3, h = bh & 7;
    const int it = U_IT[unit], ch = U_CH[unit];
    const int i0 = it*TB;
    const int jlo = ch*4;
    const int jhi = (jlo+3 < it) ? jlo+3 : it;

    const int tid = threadIdx.x, w = tid>>5, lane = tid&31;
    const int g = lane>>2, j = lane&3, wrow = w*16;
    uint32_t* Pwu = Psu + w*16*36;

    const size_t rowKQ = (size_t)b*NTOK*256 + h*32;
    const size_t rowV  = ((size_t)b*FF + h*64)*1024;

    #pragma unroll
    for (int i=0;i<4;i++){
        int idx = tid + i*256, r = idx>>3, seg = idx&7;
        cp16(smem_u32(Ksu + r*36 + seg*4), Kb + rowKQ + (size_t)(i0+r)*256 + seg*4);
    }
    {
        int j0 = jlo*TB;
        #pragma unroll
        for (int i=0;i<4;i++){
            int idx = tid + i*256, r = idx>>3, seg = idx&7;
            cp16(smem_u32(Qsu + r*36 + seg*4), Qb + rowKQ + (size_t)(j0+r)*256 + seg*4);
        }
        #pragma unroll
        for (int i=0;i<4;i++){
            int idx = tid + i*256, d = idx>>4, seg = idx&15;
            cp16(smem_u32(Vsu + d*68 + seg*4), Vb + rowV + (size_t)d*1024 + (j0>>1) + seg*4);
        }
    }
    CP_COMMIT;

    float l0 = 0.f, l1 = 0.f;
    float ot[8][4];
    #pragma unroll
    for (int nt=0;nt<8;nt++){ ot[nt][0]=ot[nt][1]=ot[nt][2]=ot[nt][3]=0.f; }

    for (int jt = jlo; jt <= jhi; jt++) {
        const int cur = (jt - jlo) & 1;
        const uint32_t* Qc = Qsu + cur*128*36;
        const uint32_t* Vc = Vsu + cur*64*68;
        CP_WAIT0;
        __syncthreads();
        if (jt < jhi) {
            uint32_t* Qn = Qsu + (cur^1)*128*36;
            uint32_t* Vn = Vsu + (cur^1)*64*68;
            int j0n = (jt+1)*TB;
            #pragma unroll
            for (int i=0;i<4;i++){
                int idx = tid + i*256, r = idx>>3, seg = idx&7;
                cp16(smem_u32(Qn + r*36 + seg*4), Qb + rowKQ + (size_t)(j0n+r)*256 + seg*4);
            }
            #pragma unroll
            for (int i=0;i<4;i++){
                int idx = tid + i*256, d = idx>>4, seg = idx&15;
                cp16(smem_u32(Vn + d*68 + seg*4), Vb + rowV + (size_t)d*1024 + (j0n>>1) + seg*4);
            }
            CP_COMMIT;
        }

        #pragma unroll
        for (int h2 = 0; h2 < 2; h2++) {
            const int chh = h2*64;
            float sf[8][4];
            #pragma unroll
            for (int nt=0;nt<8;nt++){ sf[nt][0]=sf[nt][1]=sf[nt][2]=sf[nt][3]=0.f; }
            #pragma unroll
            for (int k02 = 0; k02 < 32; k02 += 8) {
                uint32_t a0 = Ksu[(wrow+g  )*36 + k02+j  ];
                uint32_t a1 = Ksu[(wrow+g+8)*36 + k02+j  ];
                uint32_t a2 = Ksu[(wrow+g  )*36 + k02+j+4];
                uint32_t a3 = Ksu[(wrow+g+8)*36 + k02+j+4];
                #pragma unroll
                for (int nt = 0; nt < 8; nt++) {
                    uint32_t b0 = Qc[(chh + nt*8+g)*36 + k02+j  ];
                    uint32_t b1 = Qc[(chh + nt*8+g)*36 + k02+j+4];
                    mma_bf16(sf[nt], a0,a1,a2,a3, b0,b1);
                }
            }
            #pragma unroll
            for (int nt=0; nt<8; nt++) {
                sf[nt][0] = __expf(sf[nt][0]);
                sf[nt][1] = __expf(sf[nt][1]);
                sf[nt][2] = __expf(sf[nt][2]);
                sf[nt][3] = __expf(sf[nt][3]);
                l0 += sf[nt][0] + sf[nt][1];
                l1 += sf[nt][2] + sf[nt][3];
                Pwu[(g  )*36 + nt*4+j] = pack_bf16(sf[nt][0], sf[nt][1]);
                Pwu[(g+8)*36 + nt*4+j] = pack_bf16(sf[nt][2], sf[nt][3]);
            }
            __syncwarp();
            #pragma unroll
            for (int k02 = 0; k02 < 32; k02 += 8) {
                uint32_t a0 = Pwu[(g  )*36 + k02+j  ];
                uint32_t a1 = Pwu[(g+8)*36 + k02+j  ];
                uint32_t a2 = Pwu[(g  )*36 + k02+j+4];
                uint32_t a3 = Pwu[(g+8)*36 + k02+j+4];
                #pragma unroll
                for (int nt = 0; nt < 8; nt++) {
                    uint32_t b0 = Vc[(nt*8+g)*68 + h2*32 + k02+j  ];
                    uint32_t b1 = Vc[(nt*8+g)*68 + h2*32 + k02+j+4];
                    mma_bf16(ot[nt], a0,a1,a2,a3, b0,b1);
                }
            }
            __syncwarp();
        }
    }

    l0 += __shfl_xor_sync(0xffffffffu, l0, 1);
    l0 += __shfl_xor_sync(0xffffffffu, l0, 2);
    l1 += __shfl_xor_sync(0xffffffffu, l1, 1);
    l1 += __shfl_xor_sync(0xffffffffu, l1, 2);

    if (it < 4) {
        float inv0 = 1.0f/l0, inv1 = 1.0f/l1;
        size_t d0 = ((size_t)b*NTOK + i0 + wrow + g)*256 + h*32;
        size_t d1 = ((size_t)b*NTOK + i0 + wrow + g + 8)*256 + h*32;
        #pragma unroll
        for (int nt=0; nt<8; nt++) {
            Vo[d0 + nt*4 + j] = pack_bf16(ot[nt][0]*inv0, ot[nt][1]*inv0);
            Vo[d1 + nt*4 + j] = pack_bf16(ot[nt][2]*inv1, ot[nt][3]*inv1);
        }
    } else {
        const int p = ((b*NH + h)*12 + (it-4))*4 + ch;
        uint32_t* op = g_Opb + (size_t)p*TB*32;
        #pragma unroll
        for (int nt=0; nt<8; nt++) {
            op[(wrow+g  )*32 + nt*4 + j] = pack_bf16(ot[nt][0], ot[nt][1]);
            op[(wrow+g+8)*32 + nt*4 + j] = pack_bf16(ot[nt][2], ot[nt][3]);
        }
        if (j == 0) {
            g_lp[p*TB + wrow+g  ] = l0;
            g_lp[p*TB + wrow+g+8] = l1;
        }
    }
}

// ---------------- attention merge: grid 768 (192 x 4 row groups) ---------
__global__ __launch_bounds__(256) void attn_merge_kernel(uint32_t* __restrict__ Vo)
{
    const int m = blockIdx.x;
    const int grp = m & 3, mm = m >> 2;
    const int itx = mm >> 4, bh = mm & 15;
    const int b = bh >> 3, h = bh & 7;
    const int it = 4 + itx;
    const int nch = it/4 + 1;
    const int pbase = ((b*NH + h)*12 + itx)*4;
    const int t = threadIdx.x;
    const int r  = grp*32 + (t >> 3);        // row within i-tile
    const int wq = (t & 7) * 4;              // word offset within 32-word row

    float acc[8] = {0,0,0,0,0,0,0,0};
    float l = 0.f;
    #pragma unroll 4
    for (int c = 0; c < nch; c++) {
        uint4 v = *(const uint4*)(g_Opb + (size_t)(pbase+c)*TB*32 + r*32 + wq);
        l += g_lp[(pbase+c)*TB + r];
        acc[0] += __uint_as_float(v.x << 16);
        acc[1] += __uint_as_float(v.x & 0xffff0000u);
        acc[2] += __uint_as_float(v.y << 16);
        acc[3] += __uint_as_float(v.y & 0xffff0000u);
        acc[4] += __uint_as_float(v.z << 16);
        acc[5] += __uint_as_float(v.z & 0xffff0000u);
        acc[6] += __uint_as_float(v.w << 16);
        acc[7] += __uint_as_float(v.w & 0xffff0000u);
    }
    float inv = 1.0f/l;
    uint4 o;
    o.x = pack_bf16(acc[0]*inv, acc[1]*inv);
    o.y = pack_bf16(acc[2]*inv, acc[3]*inv);
    o.z = pack_bf16(acc[4]*inv, acc[5]*inv);
    o.w = pack_bf16(acc[6]*inv, acc[7]*inv);
    *(uint4*)(Vo + ((size_t)b*NTOK + it*TB + r)*256 + h*32 + wq) = o;
}

// ---------------- BN finalize + apply ----------------
__global__ void bn_finalize_kernel() {
    const int c = blockIdx.x, t = threadIdx.x;
    float s = g_ps[c*64 + t] + g_ps[c*64 + 32 + t];
    float q = g_pq[c*64 + t] + g_pq[c*64 + 32 + t];
    #pragma unroll
    for (int o = 16; o; o >>= 1) {
        s += __shfl_xor_sync(0xffffffffu, s, o);
        q += __shfl_xor_sync(0xffffffffu, q, o);
    }
    if (t == 0) {
        float mean = s / (float)(Bb*NTOK);
        float var  = q / (float)(Bb*NTOK) - mean*mean;
        g_mean[c] = mean;
        g_istd[c] = rsqrtf(var + BN_EPS);
    }
}

__global__ __launch_bounds__(256) void bn_apply_kernel(
    const float* __restrict__ gamma, const float* __restrict__ beta,
    float* __restrict__ out)
{
    int idx = blockIdx.x*256 + threadIdx.x;   // 0..131071, 2 float4 each
    int i0 = idx, i1 = idx + 131072;
    int c0 = (i0 >> 9) & (COUT-1);
    int c1 = (i1 >> 9) & (COUT-1);
    float4 v0 = *((const float4*)g_y + i0);
    float4 v1 = *((const float4*)g_y + i1);
    float mu0 = g_mean[c0], is0 = g_istd[c0]*gamma[c0], be0 = beta[c0];
    float mu1 = g_mean[c1], is1 = g_istd[c1]*gamma[c1], be1 = beta[c1];
    float4 o0, o1;
    o0.x = (v0.x-mu0)*is0 + be0; o0.y = (v0.y-mu0)*is0 + be0;
    o0.z = (v0.z-mu0)*is0 + be0; o0.w = (v0.w-mu0)*is0 + be0;
    o1.x = (v1.x-mu1)*is1 + be1; o1.y = (v1.y-mu1)*is1 + be1;
    o1.z = (v1.z-mu1)*is1 + be1; o1.w = (v1.w-mu1)*is1 + be1;
    *((float4*)out + i0) = o0;
    *((float4*)out + i1) = o1;
}

// ---------------- launch ----------------
extern "C" void kernel_launch(void* const* d_in, const int* in_sizes, int n_in,
                              void* d_out, int out_size)
{
    const float* x     = (const float*)d_in[0];
    const float* WK    = (const float*)d_in[1];
    const float* WQ    = (const float*)d_in[2];
    const float* WV    = (const float*)d_in[3];
    const float* Wo    = (const float*)d_in[4];
    const float* bo    = (const float*)d_in[5];
    const float* gamma = (const float*)d_in[6];
    const float* beta  = (const float*)d_in[7];
    float* out = (float*)d_out;

    uint32_t *pK, *pQ, *pV, *pVo;
    float *pY;
    cudaGetSymbolAddress((void**)&pK,  g_Kb);
    cudaGetSymbolAddress((void**)&pQ,  g_Qb);
    cudaGetSymbolAddress((void**)&pV,  g_Vb);
    cudaGetSymbolAddress((void**)&pVo, g_Vo);
    cudaGetSymbolAddress((void**)&pY,  g_y);

    conv_w_kernel<<<256, 256>>>(WK, WQ, WV, Wo);

    dim3 gq(NTOK/64, 12, Bb);
    qkv_kernel<<<gq, 256>>>(x, pK, pQ, pV);

    size_t smem = (size_t)(128*36 + 2*128*36 + 2*64*68 + 8*16*36) * 4;
    cudaFuncSetAttribute(attn_kernel, cudaFuncAttributeMaxDynamicSharedMemorySize, (int)smem);
    attn_kernel<<<640, 256, smem>>>(pK, pQ, pV, pVo);

    attn_merge_kernel<<<768, 256>>>(pVo);

    dim3 gp(NTOK/64, COUT/128, Bb);
    proj_kernel<<<gp, 256>>>(pVo, bo, x, pY);

    bn_finalize_kernel<<<COUT, 32>>>();
    bn_apply_kernel<<<512, 256>>>(gamma, beta, out);
}

// round 8
// speedup vs baseline: 9.6732x; 1.0813x over previous
#include <cuda_runtime.h>
#include <cuda_bf16.h>
#include <math.h>
#include <stdint.h>

#define Bb    2
#define CIN   256
#define FF    512
#define COUT  256
#define NH    8
#define DH    64
#define NTOK  2048
#define TB    128
#define Tt    16
#define INV_TEMP (1.0f/16.0f)
#define BN_EPS 1e-5f

// ---------------- scratch (bf16 packed in uint32 words) ----------------
__device__ uint32_t g_Wb[4*65536];        // WK,WQ,WV rows 128w; Wo rows 256w
__device__ uint32_t g_Xt[Bb*NTOK*(CIN/2)];// [b][n][c/2]
__device__ uint32_t g_Kb[Bb*NTOK*FF/2];   // [b][n][f/2]  (pre-scaled 1/TEMP)
__device__ uint32_t g_Qb[Bb*NTOK*FF/2];   // [b][n][f/2]
__device__ uint32_t g_Vb[Bb*FF*NTOK/2];   // [b][f][n/2]
__device__ uint32_t g_Vo[Bb*NTOK*FF/2];   // [b][n][f/2]
__device__ float g_y [Bb*COUT*NTOK];      // [b][c][n]
__device__ uint32_t g_Opb[Bb*NH*12*4*TB*(DH/2)];
__device__ float g_lp[Bb*NH*12*4*TB];
__device__ float g_ps[COUT*64];
__device__ float g_pq[COUT*64];
__device__ float g_mean[COUT];
__device__ float g_istd[COUT];

__constant__ int8_t U_IT[40] = {3,4,5,6,7,7,8,8,9,9,10,10,11,11,11,12,12,12,
                                13,13,13,14,14,14,15,15,15,15,
                                2,6,10,14, 1,5,9,13, 0,4,8,12};
__constant__ int8_t U_CH[40] = {0,0,0,0,0,1,0,1,0,1,0,1,0,1,2,0,1,2,
                                0,1,2,0,1,2,0,1,2,3,
                                0,1,2,3, 0,1,2,3, 0,1,2,3};

// ---------------- helpers ----------------
__device__ __forceinline__ uint32_t pack_bf16(float lo, float hi) {
    uint32_t r;
    asm("cvt.rn.bf16x2.f32 %0, %1, %2;" : "=r"(r) : "f"(hi), "f"(lo));
    return r;
}
__device__ __forceinline__ void mma4(float d[4], const uint32_t a[4],
                                     uint32_t b0, uint32_t b1)
{
    asm volatile(
      "mma.sync.aligned.m16n8k16.row.col.f32.bf16.bf16.f32 "
      "{%0,%1,%2,%3}, {%4,%5,%6,%7}, {%8,%9}, {%0,%1,%2,%3};"
      : "+f"(d[0]), "+f"(d[1]), "+f"(d[2]), "+f"(d[3])
      : "r"(a[0]), "r"(a[1]), "r"(a[2]), "r"(a[3]), "r"(b0), "r"(b1));
}
__device__ __forceinline__ void ldsm4(uint32_t r[4], uint32_t addr) {
    asm volatile("ldmatrix.sync.aligned.m8n8.x4.shared.b16 {%0,%1,%2,%3}, [%4];"
        : "=r"(r[0]), "=r"(r[1]), "=r"(r[2]), "=r"(r[3]) : "r"(addr));
}
__device__ __forceinline__ uint32_t smem_u32(const void* p) {
    return (uint32_t)__cvta_generic_to_shared(p);
}
__device__ __forceinline__ void cp16(uint32_t s, const void* g) {
    asm volatile("cp.async.cg.shared.global [%0], [%1], 16;" :: "r"(s), "l"(g));
}
#define CP_COMMIT asm volatile("cp.async.commit_group;")
#define CP_WAIT0  asm volatile("cp.async.wait_group 0;")

__device__ __forceinline__ uint32_t laneA(int l, int S) {
    return (uint32_t)((((l&7) + ((l>>3)&1)*8)*S + (l>>4)*4) * 4);
}
__device__ __forceinline__ uint32_t laneB(int l, int S) {
    return (uint32_t)((((l&7) + ((l>>4)&1)*8)*S + ((l>>3)&1)*4) * 4);
}

// ---------------- prep: weights -> bf16; X -> bf16 transposed ------------
__global__ __launch_bounds__(256) void prep_kernel(
    const float* __restrict__ WK, const float* __restrict__ WQ,
    const float* __restrict__ WV, const float* __restrict__ Wo,
    const float* __restrict__ X)
{
    const int tid = threadIdx.x;
    if (blockIdx.x < 256) {
        int e8 = blockIdx.x*256 + tid;
        int e  = e8*8;
        const float* src; int off;
        if      (e < 131072) { src = WK; off = e; }
        else if (e < 262144) { src = WQ; off = e - 131072; }
        else if (e < 393216) { src = WV; off = e - 262144; }
        else                 { src = Wo; off = e - 393216; }
        float4 a = *(const float4*)(src + off);
        float4 c = *(const float4*)(src + off + 4);
        uint4 o;
        o.x = pack_bf16(a.x, a.y); o.y = pack_bf16(a.z, a.w);
        o.z = pack_bf16(c.x, c.y); o.w = pack_bf16(c.z, c.w);
        *(uint4*)(g_Wb + e8*4) = o;
    } else {
        __shared__ float ts[32][68];
        int bx = blockIdx.x - 256;
        int b  = bx >> 8;
        int t8 = bx & 255;
        int n0 = (t8 >> 3) * 64;
        int c0 = (t8 & 7) * 32;
        const float* Xb = X + (size_t)b*CIN*NTOK;
        #pragma unroll
        for (int i = 0; i < 2; i++) {
            int c = (tid>>4) + i*16, n4 = (tid&15)*4;
            float4 v = *(const float4*)(Xb + (size_t)(c0+c)*NTOK + n0 + n4);
            *(float4*)&ts[c][n4] = v;
        }
        __syncthreads();
        int n = tid>>2, w0 = tid&3;
        size_t dst = ((size_t)b*NTOK + n0 + n)*128 + (c0>>1);
        #pragma unroll
        for (int ii = 0; ii < 4; ii++) {
            int w = w0 + 4*ii;
            g_Xt[dst + w] = pack_bf16(ts[2*w][n], ts[2*w+1][n]);
        }
    }
}

// ---------------- fused QKV GEMM: grid (32,12,2) -------------------------
__global__ __launch_bounds__(256) void qkv_kernel(
    uint32_t* __restrict__ Kb, uint32_t* __restrict__ Qb,
    uint32_t* __restrict__ Vb)
{
    __shared__ __align__(16) uint32_t Wsu[2][128*20];
    __shared__ __align__(16) uint32_t Xsu[2][64*20];
    const int b = blockIdx.z, mb = blockIdx.y, n0 = blockIdx.x*64;
    const int sel = mb >> 2, m0 = (mb & 3)*128;
    const uint32_t* W  = g_Wb + sel*65536;
    const uint32_t* Xp = g_Xt + ((size_t)b*NTOK + n0)*128;
    const int tid = threadIdx.x, w = tid>>5, lane = tid&31;
    const int g = lane>>2, j = lane&3, wrow = w*16;
    const uint32_t oA = laneA(lane, 20), oB = laneB(lane, 20);

    float sf[8][4];
    #pragma unroll
    for (int nt=0;nt<8;nt++){ sf[nt][0]=sf[nt][1]=sf[nt][2]=sf[nt][3]=0.f; }

    #pragma unroll
    for (int i=0;i<2;i++){
        int idx = tid + i*256, m = idx>>2, seg = idx&3;
        cp16(smem_u32(&Wsu[0][m*20 + seg*4]), W + (size_t)(m0+m)*128 + seg*4);
    }
    {   int r = tid>>2, seg = tid&3;
        cp16(smem_u32(&Xsu[0][r*20 + seg*4]), Xp + (size_t)r*128 + seg*4);
    }
    CP_COMMIT;

    for (int c = 0; c < 8; c++) {
        int cur = c & 1;
        CP_WAIT0;
        __syncthreads();
        if (c < 7) {
            #pragma unroll
            for (int i=0;i<2;i++){
                int idx = tid + i*256, m = idx>>2, seg = idx&3;
                cp16(smem_u32(&Wsu[cur^1][m*20 + seg*4]),
                     W + (size_t)(m0+m)*128 + (c+1)*16 + seg*4);
            }
            {   int r = tid>>2, seg = tid&3;
                cp16(smem_u32(&Xsu[cur^1][r*20 + seg*4]),
                     Xp + (size_t)r*128 + (c+1)*16 + seg*4);
            }
            CP_COMMIT;
        }
        const uint32_t wbase = smem_u32(Wsu[cur]) + wrow*20*4 + oA;
        const uint32_t xbase = smem_u32(Xsu[cur]) + oB;
        uint32_t a0[4], a1[4], bb[4];
        ldsm4(a0, wbase);
        ldsm4(a1, wbase + 8*4);
        #pragma unroll
        for (int ntp = 0; ntp < 4; ntp++) {
            ldsm4(bb, xbase + (ntp*16*20)*4);
            mma4(sf[2*ntp],   a0, bb[0], bb[1]);
            mma4(sf[2*ntp+1], a0, bb[2], bb[3]);
            ldsm4(bb, xbase + (ntp*16*20 + 8)*4);
            mma4(sf[2*ntp],   a1, bb[0], bb[1]);
            mma4(sf[2*ntp+1], a1, bb[2], bb[3]);
        }
    }
    __syncthreads();

    if (sel == 2) {
        size_t basew = ((size_t)b*FF + m0)*1024 + (n0>>1);
        #pragma unroll
        for (int nt=0; nt<8; nt++) {
            Vb[basew + (size_t)(wrow+g  )*1024 + nt*4 + j] = pack_bf16(sf[nt][0], sf[nt][1]);
            Vb[basew + (size_t)(wrow+g+8)*1024 + nt*4 + j] = pack_bf16(sf[nt][2], sf[nt][3]);
        }
    } else {
        const float scale = (sel==0) ? INV_TEMP : 1.f;
        __nv_bfloat16* tileh = (__nv_bfloat16*)&Wsu[0][0];
        #pragma unroll
        for (int nt=0; nt<8; nt++) {
            int c = nt*8 + 2*j;
            tileh[(c  )*136 + wrow+g  ] = __float2bfloat16(sf[nt][0]*scale);
            tileh[(c+1)*136 + wrow+g  ] = __float2bfloat16(sf[nt][1]*scale);
            tileh[(c  )*136 + wrow+g+8] = __float2bfloat16(sf[nt][2]*scale);
            tileh[(c+1)*136 + wrow+g+8] = __float2bfloat16(sf[nt][3]*scale);
        }
        __syncthreads();
        uint32_t* C = (sel==0) ? Kb : Qb;
        const uint32_t* tw = (const uint32_t*)tileh;
        int cc = tid>>2, seg = tid&3;
        size_t dstw = ((size_t)b*NTOK + n0 + cc)*256 + (m0>>1) + seg*16;
        #pragma unroll
        for (int q=0; q<4; q++) {
            uint4 v = *(const uint4*)(tw + cc*68 + seg*16 + q*4);
            *(uint4*)(C + dstw + q*4) = v;
        }
    }
}

// ---------------- proj: grid (32,2,2) ------------------------------------
__global__ __launch_bounds__(256) void proj_kernel(
    const uint32_t* __restrict__ Vo,
    const float* __restrict__ bias, const float* __restrict__ skip,
    float* __restrict__ Y)
{
    __shared__ __align__(16) uint32_t Wsu[2][128*20];
    __shared__ __align__(16) uint32_t Xsu[2][64*20];
    const int b = blockIdx.z, m0 = blockIdx.y*128, n0 = blockIdx.x*64;
    const int tid = threadIdx.x, w = tid>>5, lane = tid&31;
    const int g = lane>>2, j = lane&3, wrow = w*16;
    const uint32_t* W  = g_Wb + 3*65536;
    const uint32_t* Vp = Vo + ((size_t)b*NTOK + n0)*256;
    const uint32_t oA = laneA(lane, 20), oB = laneB(lane, 20);

    float sf[8][4];
    #pragma unroll
    for (int nt=0;nt<8;nt++){ sf[nt][0]=sf[nt][1]=sf[nt][2]=sf[nt][3]=0.f; }

    #pragma unroll
    for (int i=0;i<2;i++){
        int idx = tid + i*256, m = idx>>2, seg = idx&3;
        cp16(smem_u32(&Wsu[0][m*20 + seg*4]), W + (size_t)(m0+m)*256 + seg*4);
    }
    {   int r = tid>>2, seg = tid&3;
        cp16(smem_u32(&Xsu[0][r*20 + seg*4]), Vp + (size_t)r*256 + seg*4);
    }
    CP_COMMIT;

    for (int c = 0; c < 16; c++) {
        int cur = c & 1;
        CP_WAIT0;
        __syncthreads();
        if (c < 15) {
            #pragma unroll
            for (int i=0;i<2;i++){
                int idx = tid + i*256, m = idx>>2, seg = idx&3;
                cp16(smem_u32(&Wsu[cur^1][m*20 + seg*4]),
                     W + (size_t)(m0+m)*256 + (c+1)*16 + seg*4);
            }
            {   int r = tid>>2, seg = tid&3;
                cp16(smem_u32(&Xsu[cur^1][r*20 + seg*4]),
                     Vp + (size_t)r*256 + (c+1)*16 + seg*4);
            }
            CP_COMMIT;
        }
        const uint32_t wbase = smem_u32(Wsu[cur]) + wrow*20*4 + oA;
        const uint32_t xbase = smem_u32(Xsu[cur]) + oB;
        uint32_t a0[4], a1[4], bb[4];
        ldsm4(a0, wbase);
        ldsm4(a1, wbase + 8*4);
        #pragma unroll
        for (int ntp = 0; ntp < 4; ntp++) {
            ldsm4(bb, xbase + (ntp*16*20)*4);
            mma4(sf[2*ntp],   a0, bb[0], bb[1]);
            mma4(sf[2*ntp+1], a0, bb[2], bb[3]);
            ldsm4(bb, xbase + (ntp*16*20 + 8)*4);
            mma4(sf[2*ntp],   a1, bb[0], bb[1]);
            mma4(sf[2*ntp+1], a1, bb[2], bb[3]);
        }
    }

    const int row0 = m0 + wrow + g, row1 = row0 + 8;
    const float b0v = bias[row0], b1v = bias[row1];
    const size_t ybase = (size_t)b*COUT*NTOK;
    float s0=0.f,q0=0.f,s1=0.f,q1=0.f;
    #pragma unroll
    for (int nt=0; nt<8; nt++) {
        int col = n0 + nt*8 + 2*j;
        float2 sk0 = *(const float2*)(skip + ybase + (size_t)row0*NTOK + col);
        float2 sk1 = *(const float2*)(skip + ybase + (size_t)row1*NTOK + col);
        float2 y0 = { fmaxf(sf[nt][0]+b0v,0.f)+sk0.x, fmaxf(sf[nt][1]+b0v,0.f)+sk0.y };
        float2 y1 = { fmaxf(sf[nt][2]+b1v,0.f)+sk1.x, fmaxf(sf[nt][3]+b1v,0.f)+sk1.y };
        *(float2*)(Y + ybase + (size_t)row0*NTOK + col) = y0;
        *(float2*)(Y + ybase + (size_t)row1*NTOK + col) = y1;
        s0 += y0.x + y0.y;  q0 += y0.x*y0.x + y0.y*y0.y;
        s1 += y1.x + y1.y;  q1 += y1.x*y1.x + y1.y*y1.y;
    }
    s0 += __shfl_xor_sync(0xffffffffu, s0, 1); s0 += __shfl_xor_sync(0xffffffffu, s0, 2);
    q0 += __shfl_xor_sync(0xffffffffu, q0, 1); q0 += __shfl_xor_sync(0xffffffffu, q0, 2);
    s1 += __shfl_xor_sync(0xffffffffu, s1, 1); s1 += __shfl_xor_sync(0xffffffffu, s1, 2);
    q1 += __shfl_xor_sync(0xffffffffu, q1, 1); q1 += __shfl_xor_sync(0xffffffffu, q1, 2);
    if (j == 0) {
        int part = b*32 + blockIdx.x;
        g_ps[row0*64 + part] = s0;  g_pq[row0*64 + part] = q0;
        g_ps[row1*64 + part] = s1;  g_pq[row1*64 + part] = q1;
    }
}

// ---------------- attention: flat grid 640 -------------------------------
__global__ __launch_bounds__(256, 2) void attn_kernel(
    const uint32_t* __restrict__ Kb, const uint32_t* __restrict__ Qb,
    const uint32_t* __restrict__ Vb, uint32_t* __restrict__ Vo)
{
    extern __shared__ __align__(16) uint32_t smu[];
    uint32_t* Ksu = smu;
    uint32_t* Qsu = Ksu + 128*36;
    uint32_t* Vsu = Qsu + 2*128*36;
    uint32_t* Psu = Vsu + 2*64*68;

    const int ux = blockIdx.x;
    const int unit = ux >> 4, bh = ux & 15;
    const int b = bh >> 3, h = bh & 7;
    const int it = U_IT[unit], ch = U_CH[unit];
    const int i0 = it*TB;
    const int jlo = ch*4;
    const int jhi = (jlo+3 < it) ? jlo+3 : it;

    const int tid = threadIdx.x, w = tid>>5, lane = tid&31;
    const int g = lane>>2, j = lane&3, wrow = w*16;
    uint32_t* Pwu = Psu + w*16*36;
    const uint32_t oA36 = laneA(lane, 36);
    const uint32_t oB36 = laneB(lane, 36);
    const uint32_t oB68 = laneB(lane, 68);

    const size_t rowKQ = (size_t)b*NTOK*256 + h*32;
    const size_t rowV  = ((size_t)b*FF + h*64)*1024;

    #pragma unroll
    for (int i=0;i<4;i++){
        int idx = tid + i*256, r = idx>>3, seg = idx&7;
        cp16(smem_u32(Ksu + r*36 + seg*4), Kb + rowKQ + (size_t)(i0+r)*256 + seg*4);
    }
    {
        int j0 = jlo*TB;
        #pragma unroll
        for (int i=0;i<4;i++){
            int idx = tid + i*256, r = idx>>3, seg = idx&7;
            cp16(smem_u32(Qsu + r*36 + seg*4), Qb + rowKQ + (size_t)(j0+r)*256 + seg*4);
        }
        #pragma unroll
        for (int i=0;i<4;i++){
            int idx = tid + i*256, d = idx>>4, seg = idx&15;
            cp16(smem_u32(Vsu + d*68 + seg*4), Vb + rowV + (size_t)d*1024 + (j0>>1) + seg*4);
        }
    }
    CP_COMMIT;

    float l0 = 0.f, l1 = 0.f;
    float ot[8][4];
    #pragma unroll
    for (int nt=0;nt<8;nt++){ ot[nt][0]=ot[nt][1]=ot[nt][2]=ot[nt][3]=0.f; }

    for (int jt = jlo; jt <= jhi; jt++) {
        const int cur = (jt - jlo) & 1;
        const uint32_t* Qc = Qsu + cur*128*36;
        const uint32_t* Vc = Vsu + cur*64*68;
        CP_WAIT0;
        __syncthreads();
        if (jt < jhi) {
            uint32_t* Qn = Qsu + (cur^1)*128*36;
            uint32_t* Vn = Vsu + (cur^1)*64*68;
            int j0n = (jt+1)*TB;
            #pragma unroll
            for (int i=0;i<4;i++){
                int idx = tid + i*256, r = idx>>3, seg = idx&7;
                cp16(smem_u32(Qn + r*36 + seg*4), Qb + rowKQ + (size_t)(j0n+r)*256 + seg*4);
            }
            #pragma unroll
            for (int i=0;i<4;i++){
                int idx = tid + i*256, d = idx>>4, seg = idx&15;
                cp16(smem_u32(Vn + d*68 + seg*4), Vb + rowV + (size_t)d*1024 + (j0n>>1) + seg*4);
            }
            CP_COMMIT;
        }

        const uint32_t kbase = smem_u32(Ksu) + wrow*36*4 + oA36;
        const uint32_t pbase = smem_u32(Pwu) + oA36;

        #pragma unroll
        for (int h2 = 0; h2 < 2; h2++) {
            const int chh = h2*64;
            const uint32_t qbase = smem_u32(Qc) + chh*36*4 + oB36;
            const uint32_t vbase = smem_u32(Vc) + h2*32*4 + oB68;

            float sf[8][4];
            #pragma unroll
            for (int nt=0;nt<8;nt++){ sf[nt][0]=sf[nt][1]=sf[nt][2]=sf[nt][3]=0.f; }
            #pragma unroll
            for (int kg = 0; kg < 4; kg++) {
                uint32_t aa[4], bb[4];
                ldsm4(aa, kbase + kg*8*4);
                #pragma unroll
                for (int ntp = 0; ntp < 4; ntp++) {
                    ldsm4(bb, qbase + (ntp*16*36 + kg*8)*4);
                    mma4(sf[2*ntp],   aa, bb[0], bb[1]);
                    mma4(sf[2*ntp+1], aa, bb[2], bb[3]);
                }
            }
            #pragma unroll
            for (int nt=0; nt<8; nt++) {
                sf[nt][0] = __expf(sf[nt][0]);
                sf[nt][1] = __expf(sf[nt][1]);
                sf[nt][2] = __expf(sf[nt][2]);
                sf[nt][3] = __expf(sf[nt][3]);
                l0 += sf[nt][0] + sf[nt][1];
                l1 += sf[nt][2] + sf[nt][3];
                Pwu[(g  )*36 + nt*4+j] = pack_bf16(sf[nt][0], sf[nt][1]);
                Pwu[(g+8)*36 + nt*4+j] = pack_bf16(sf[nt][2], sf[nt][3]);
            }
            __syncwarp();
            #pragma unroll
            for (int kg = 0; kg < 4; kg++) {
                uint32_t aa[4], bb[4];
                ldsm4(aa, pbase + kg*8*4);
                #pragma unroll
                for (int ntp = 0; ntp < 4; ntp++) {
                    ldsm4(bb, vbase + (ntp*16*68 + kg*8)*4);
                    mma4(ot[2*ntp],   aa, bb[0], bb[1]);
                    mma4(ot[2*ntp+1], aa, bb[2], bb[3]);
                }
            }
            __syncwarp();
        }
    }

    l0 += __shfl_xor_sync(0xffffffffu, l0, 1);
    l0 += __shfl_xor_sync(0xffffffffu, l0, 2);
    l1 += __shfl_xor_sync(0xffffffffu, l1, 1);
    l1 += __shfl_xor_sync(0xffffffffu, l1, 2);

    if (it < 4) {
        float inv0 = 1.0f/l0, inv1 = 1.0f/l1;
        size_t d0 = ((size_t)b*NTOK + i0 + wrow + g)*256 + h*32;
        size_t d1 = ((size_t)b*NTOK + i0 + wrow + g + 8)*256 + h*32;
        #pragma unroll
        for (int nt=0; nt<8; nt++) {
            Vo[d0 + nt*4 + j] = pack_bf16(ot[nt][0]*inv0, ot[nt][1]*inv0);
            Vo[d1 + nt*4 + j] = pack_bf16(ot[nt][2]*inv1, ot[nt][3]*inv1);
        }
    } else {
        const int p = ((b*NH + h)*12 + (it-4))*4 + ch;
        uint32_t* op = g_Opb + (size_t)p*TB*32;
        #pragma unroll
        for (int nt=0; nt<8; nt++) {
            op[(wrow+g  )*32 + nt*4 + j] = pack_bf16(ot[nt][0], ot[nt][1]);
            op[(wrow+g+8)*32 + nt*4 + j] = pack_bf16(ot[nt][2], ot[nt][3]);
        }
        if (j == 0) {
            g_lp[p*TB + wrow+g  ] = l0;
            g_lp[p*TB + wrow+g+8] = l1;
        }
    }
}

// ---------------- attention merge: grid 768 ------------------------------
__global__ __launch_bounds__(256) void attn_merge_kernel(uint32_t* __restrict__ Vo)
{
    const int m = blockIdx.x;
    const int grp = m & 3, mm = m >> 2;
    const int itx = mm >> 4, bh = mm & 15;
    const int b = bh >> 3, h = bh & 7;
    const int it = 4 + itx;
    const int nch = it/4 + 1;
    const int pbase = ((b*NH + h)*12 + itx)*4;
    const int t = threadIdx.x;
    const int r  = grp*32 + (t >> 3);
    const int wq = (t & 7) * 4;

    float acc[8] = {0,0,0,0,0,0,0,0};
    float l = 0.f;
    #pragma unroll 4
    for (int c = 0; c < nch; c++) {
        uint4 v = *(const uint4*)(g_Opb + (size_t)(pbase+c)*TB*32 + r*32 + wq);
        l += g_lp[(pbase+c)*TB + r];
        acc[0] += __uint_as_float(v.x << 16);
        acc[1] += __uint_as_float(v.x & 0xffff0000u);
        acc[2] += __uint_as_float(v.y << 16);
        acc[3] += __uint_as_float(v.y & 0xffff0000u);
        acc[4] += __uint_as_float(v.z << 16);
        acc[5] += __uint_as_float(v.z & 0xffff0000u);
        acc[6] += __uint_as_float(v.w << 16);
        acc[7] += __uint_as_float(v.w & 0xffff0000u);
    }
    float inv = 1.0f/l;
    uint4 o;
    o.x = pack_bf16(acc[0]*inv, acc[1]*inv);
    o.y = pack_bf16(acc[2]*inv, acc[3]*inv);
    o.z = pack_bf16(acc[4]*inv, acc[5]*inv);
    o.w = pack_bf16(acc[6]*inv, acc[7]*inv);
    *(uint4*)(Vo + ((size_t)b*NTOK + it*TB + r)*256 + h*32 + wq) = o;
}

// ---------------- BN finalize + apply ----------------
__global__ void bn_finalize_kernel() {
    const int c = blockIdx.x, t = threadIdx.x;
    float s = g_ps[c*64 + t] + g_ps[c*64 + 32 + t];
    float q = g_pq[c*64 + t] + g_pq[c*64 + 32 + t];
    #pragma unroll
    for (int o = 16; o; o >>= 1) {
        s += __shfl_xor_sync(0xffffffffu, s, o);
        q += __shfl_xor_sync(0xffffffffu, q, o);
    }
    if (t == 0) {
        float mean = s / (float)(Bb*NTOK);
        float var  = q / (float)(Bb*NTOK) - mean*mean;
        g_mean[c] = mean;
        g_istd[c] = rsqrtf(var + BN_EPS);
    }
}

__global__ __launch_bounds__(256) void bn_apply_kernel(
    const float* __restrict__ gamma, const float* __restrict__ beta,
    float* __restrict__ out)
{
    int idx = blockIdx.x*256 + threadIdx.x;
    int i0 = idx, i1 = idx + 131072;
    int c0 = (i0 >> 9) & (COUT-1);
    int c1 = (i1 >> 9) & (COUT-1);
    float4 v0 = *((const float4*)g_y + i0);
    float4 v1 = *((const float4*)g_y + i1);
    float mu0 = g_mean[c0], is0 = g_istd[c0]*gamma[c0], be0 = beta[c0];
    float mu1 = g_mean[c1], is1 = g_istd[c1]*gamma[c1], be1 = beta[c1];
    float4 o0, o1;
    o0.x = (v0.x-mu0)*is0 + be0; o0.y = (v0.y-mu0)*is0 + be0;
    o0.z = (v0.z-mu0)*is0 + be0; o0.w = (v0.w-mu0)*is0 + be0;
    o1.x = (v1.x-mu1)*is1 + be1; o1.y = (v1.y-mu1)*is1 + be1;
    o1.z = (v1.z-mu1)*is1 + be1; o1.w = (v1.w-mu1)*is1 + be1;
    *((float4*)out + i0) = o0;
    *((float4*)out + i1) = o1;
}

// ---------------- launch ----------------
extern "C" void kernel_launch(void* const* d_in, const int* in_sizes, int n_in,
                              void* d_out, int out_size)
{
    const float* x     = (const float*)d_in[0];
    const float* WK    = (const float*)d_in[1];
    const float* WQ    = (const float*)d_in[2];
    const float* WV    = (const float*)d_in[3];
    const float* Wo    = (const float*)d_in[4];
    const float* bo    = (const float*)d_in[5];
    const float* gamma = (const float*)d_in[6];
    const float* beta  = (const float*)d_in[7];
    float* out = (float*)d_out;

    uint32_t *pK, *pQ, *pV, *pVo;
    float *pY;
    cudaGetSymbolAddress((void**)&pK,  g_Kb);
    cudaGetSymbolAddress((void**)&pQ,  g_Qb);
    cudaGetSymbolAddress((void**)&pV,  g_Vb);
    cudaGetSymbolAddress((void**)&pVo, g_Vo);
    cudaGetSymbolAddress((void**)&pY,  g_y);

    prep_kernel<<<768, 256>>>(WK, WQ, WV, Wo, x);

    dim3 gq(NTOK/64, 12, Bb);
    qkv_kernel<<<gq, 256>>>(pK, pQ, pV);

    size_t smem = (size_t)(128*36 + 2*128*36 + 2*64*68 + 8*16*36) * 4;
    cudaFuncSetAttribute(attn_kernel, cudaFuncAttributeMaxDynamicSharedMemorySize, (int)smem);
    attn_kernel<<<640, 256, smem>>>(pK, pQ, pV, pVo);

    attn_merge_kernel<<<768, 256>>>(pVo);

    dim3 gp(NTOK/64, COUT/128, Bb);
    proj_kernel<<<gp, 256>>>(pVo, bo, x, pY);

    bn_finalize_kernel<<<COUT, 32>>>();
    bn_apply_kernel<<<512, 256>>>(gamma, beta, out);
}

// round 9
// speedup vs baseline: 10.2644x; 1.0611x over previous
#include <cuda_runtime.h>
#include <cuda_bf16.h>
#include <math.h>
#include <stdint.h>

#define Bb    2
#define CIN   256
#define FF    512
#define COUT  256
#define NH    8
#define DH    64
#define NTOK  2048
#define TB    128
#define Tt    16
#define KSCALE (0.08654104f)   // log2(e)/16
#define BN_EPS 1e-5f

// ---------------- scratch (bf16 packed in uint32 words) ----------------
__device__ uint32_t g_Wb[4*65536];        // WK,WQ,WV rows 128w; Wo rows 256w
__device__ uint32_t g_Xt[Bb*NTOK*(CIN/2)];// [b][n][c/2]
__device__ uint32_t g_Kb[Bb*NTOK*FF/2];   // [b][n][f/2]  (pre-scaled log2e/16)
__device__ uint32_t g_Qb[Bb*NTOK*FF/2];   // [b][n][f/2]
__device__ uint32_t g_Vb[Bb*FF*NTOK/2];   // [b][f][n/2]
__device__ uint32_t g_Vo[Bb*NTOK*FF/2];   // [b][n][f/2]
__device__ float g_y [Bb*COUT*NTOK];      // [b][c][n]
__device__ uint32_t g_Opb[Bb*NH*12*4*TB*(DH/2)];
__device__ float g_lp[Bb*NH*12*4*TB];
__device__ float g_ps[COUT*64];
__device__ float g_pq[COUT*64];
__device__ float g_mean[COUT];
__device__ float g_istd[COUT];

__constant__ int8_t U_IT[40] = {3,4,5,6,7,7,8,8,9,9,10,10,11,11,11,12,12,12,
                                13,13,13,14,14,14,15,15,15,15,
                                2,6,10,14, 1,5,9,13, 0,4,8,12};
__constant__ int8_t U_CH[40] = {0,0,0,0,0,1,0,1,0,1,0,1,0,1,2,0,1,2,
                                0,1,2,0,1,2,0,1,2,3,
                                0,1,2,3, 0,1,2,3, 0,1,2,3};

// ---------------- helpers ----------------
__device__ __forceinline__ uint32_t pack_bf16(float lo, float hi) {
    uint32_t r;
    asm("cvt.rn.bf16x2.f32 %0, %1, %2;" : "=r"(r) : "f"(hi), "f"(lo));
    return r;
}
__device__ __forceinline__ float ex2f(float x) {
    float y;
    asm("ex2.approx.f32 %0, %1;" : "=f"(y) : "f"(x));
    return y;
}
__device__ __forceinline__ void mma4(float d[4], const uint32_t a[4],
                                     uint32_t b0, uint32_t b1)
{
    asm volatile(
      "mma.sync.aligned.m16n8k16.row.col.f32.bf16.bf16.f32 "
      "{%0,%1,%2,%3}, {%4,%5,%6,%7}, {%8,%9}, {%0,%1,%2,%3};"
      : "+f"(d[0]), "+f"(d[1]), "+f"(d[2]), "+f"(d[3])
      : "r"(a[0]), "r"(a[1]), "r"(a[2]), "r"(a[3]), "r"(b0), "r"(b1));
}
__device__ __forceinline__ void ldsm4(uint32_t r[4], uint32_t addr) {
    asm volatile("ldmatrix.sync.aligned.m8n8.x4.shared.b16 {%0,%1,%2,%3}, [%4];"
        : "=r"(r[0]), "=r"(r[1]), "=r"(r[2]), "=r"(r[3]) : "r"(addr));
}
__device__ __forceinline__ uint32_t smem_u32(const void* p) {
    return (uint32_t)__cvta_generic_to_shared(p);
}
__device__ __forceinline__ void cp16(uint32_t s, const void* g) {
    asm volatile("cp.async.cg.shared.global [%0], [%1], 16;" :: "r"(s), "l"(g));
}
#define CP_COMMIT asm volatile("cp.async.commit_group;")
#define CP_WAIT0  asm volatile("cp.async.wait_group 0;")

__device__ __forceinline__ uint32_t laneA(int l, int S) {
    return (uint32_t)((((l&7) + ((l>>3)&1)*8)*S + (l>>4)*4) * 4);
}
__device__ __forceinline__ uint32_t laneB(int l, int S) {
    return (uint32_t)((((l&7) + ((l>>4)&1)*8)*S + ((l>>3)&1)*4) * 4);
}

// ---------------- prep: weights -> bf16; X -> bf16 transposed ------------
__global__ __launch_bounds__(256) void prep_kernel(
    const float* __restrict__ WK, const float* __restrict__ WQ,
    const float* __restrict__ WV, const float* __restrict__ Wo,
    const float* __restrict__ X)
{
    const int tid = threadIdx.x;
    if (blockIdx.x < 256) {
        int e8 = blockIdx.x*256 + tid;
        int e  = e8*8;
        const float* src; int off;
        if      (e < 131072) { src = WK; off = e; }
        else if (e < 262144) { src = WQ; off = e - 131072; }
        else if (e < 393216) { src = WV; off = e - 262144; }
        else                 { src = Wo; off = e - 393216; }
        float4 a = *(const float4*)(src + off);
        float4 c = *(const float4*)(src + off + 4);
        uint4 o;
        o.x = pack_bf16(a.x, a.y); o.y = pack_bf16(a.z, a.w);
        o.z = pack_bf16(c.x, c.y); o.w = pack_bf16(c.z, c.w);
        *(uint4*)(g_Wb + e8*4) = o;
    } else {
        __shared__ float ts[32][68];
        int bx = blockIdx.x - 256;
        int b  = bx >> 8;
        int t8 = bx & 255;
        int n0 = (t8 >> 3) * 64;
        int c0 = (t8 & 7) * 32;
        const float* Xb = X + (size_t)b*CIN*NTOK;
        #pragma unroll
        for (int i = 0; i < 2; i++) {
            int c = (tid>>4) + i*16, n4 = (tid&15)*4;
            float4 v = *(const float4*)(Xb + (size_t)(c0+c)*NTOK + n0 + n4);
            *(float4*)&ts[c][n4] = v;
        }
        __syncthreads();
        int n = tid>>2, w0 = tid&3;
        size_t dst = ((size_t)b*NTOK + n0 + n)*128 + (c0>>1);
        #pragma unroll
        for (int ii = 0; ii < 4; ii++) {
            int w = w0 + 4*ii;
            g_Xt[dst + w] = pack_bf16(ts[2*w][n], ts[2*w+1][n]);
        }
    }
}

// ---------------- fused QKV GEMM: grid (32,12,2) -------------------------
__global__ __launch_bounds__(256) void qkv_kernel(
    uint32_t* __restrict__ Kb, uint32_t* __restrict__ Qb,
    uint32_t* __restrict__ Vb)
{
    __shared__ __align__(16) uint32_t Wsu[2][128*20];
    __shared__ __align__(16) uint32_t Xsu[2][64*20];
    const int b = blockIdx.z, mb = blockIdx.y, n0 = blockIdx.x*64;
    const int sel = mb >> 2, m0 = (mb & 3)*128;
    const uint32_t* W  = g_Wb + sel*65536;
    const uint32_t* Xp = g_Xt + ((size_t)b*NTOK + n0)*128;
    const int tid = threadIdx.x, w = tid>>5, lane = tid&31;
    const int g = lane>>2, j = lane&3, wrow = w*16;
    const uint32_t oA = laneA(lane, 20), oB = laneB(lane, 20);

    float sf[8][4];
    #pragma unroll
    for (int nt=0;nt<8;nt++){ sf[nt][0]=sf[nt][1]=sf[nt][2]=sf[nt][3]=0.f; }

    #pragma unroll
    for (int i=0;i<2;i++){
        int idx = tid + i*256, m = idx>>2, seg = idx&3;
        cp16(smem_u32(&Wsu[0][m*20 + seg*4]), W + (size_t)(m0+m)*128 + seg*4);
    }
    {   int r = tid>>2, seg = tid&3;
        cp16(smem_u32(&Xsu[0][r*20 + seg*4]), Xp + (size_t)r*128 + seg*4);
    }
    CP_COMMIT;

    for (int c = 0; c < 8; c++) {
        int cur = c & 1;
        CP_WAIT0;
        __syncthreads();
        if (c < 7) {
            #pragma unroll
            for (int i=0;i<2;i++){
                int idx = tid + i*256, m = idx>>2, seg = idx&3;
                cp16(smem_u32(&Wsu[cur^1][m*20 + seg*4]),
                     W + (size_t)(m0+m)*128 + (c+1)*16 + seg*4);
            }
            {   int r = tid>>2, seg = tid&3;
                cp16(smem_u32(&Xsu[cur^1][r*20 + seg*4]),
                     Xp + (size_t)r*128 + (c+1)*16 + seg*4);
            }
            CP_COMMIT;
        }
        const uint32_t wbase = smem_u32(Wsu[cur]) + wrow*20*4 + oA;
        const uint32_t xbase = smem_u32(Xsu[cur]) + oB;
        uint32_t a0[4], a1[4], bb[4];
        ldsm4(a0, wbase);
        ldsm4(a1, wbase + 8*4);
        #pragma unroll
        for (int ntp = 0; ntp < 4; ntp++) {
            ldsm4(bb, xbase + (ntp*16*20)*4);
            mma4(sf[2*ntp],   a0, bb[0], bb[1]);
            mma4(sf[2*ntp+1], a0, bb[2], bb[3]);
            ldsm4(bb, xbase + (ntp*16*20 + 8)*4);
            mma4(sf[2*ntp],   a1, bb[0], bb[1]);
            mma4(sf[2*ntp+1], a1, bb[2], bb[3]);
        }
    }
    __syncthreads();

    if (sel == 2) {
        size_t basew = ((size_t)b*FF + m0)*1024 + (n0>>1);
        #pragma unroll
        for (int nt=0; nt<8; nt++) {
            Vb[basew + (size_t)(wrow+g  )*1024 + nt*4 + j] = pack_bf16(sf[nt][0], sf[nt][1]);
            Vb[basew + (size_t)(wrow+g+8)*1024 + nt*4 + j] = pack_bf16(sf[nt][2], sf[nt][3]);
        }
    } else {
        const float scale = (sel==0) ? KSCALE : 1.f;
        __nv_bfloat16* tileh = (__nv_bfloat16*)&Wsu[0][0];
        #pragma unroll
        for (int nt=0; nt<8; nt++) {
            int c = nt*8 + 2*j;
            tileh[(c  )*136 + wrow+g  ] = __float2bfloat16(sf[nt][0]*scale);
            tileh[(c+1)*136 + wrow+g  ] = __float2bfloat16(sf[nt][1]*scale);
            tileh[(c  )*136 + wrow+g+8] = __float2bfloat16(sf[nt][2]*scale);
            tileh[(c+1)*136 + wrow+g+8] = __float2bfloat16(sf[nt][3]*scale);
        }
        __syncthreads();
        uint32_t* C = (sel==0) ? Kb : Qb;
        const uint32_t* tw = (const uint32_t*)tileh;
        int cc = tid>>2, seg = tid&3;
        size_t dstw = ((size_t)b*NTOK + n0 + cc)*256 + (m0>>1) + seg*16;
        #pragma unroll
        for (int q=0; q<4; q++) {
            uint4 v = *(const uint4*)(tw + cc*68 + seg*16 + q*4);
            *(uint4*)(C + dstw + q*4) = v;
        }
    }
}

// ---------------- proj: grid (32,2,2) ------------------------------------
__global__ __launch_bounds__(256) void proj_kernel(
    const uint32_t* __restrict__ Vo,
    const float* __restrict__ bias, const float* __restrict__ skip,
    float* __restrict__ Y)
{
    __shared__ __align__(16) uint32_t Wsu[2][128*20];
    __shared__ __align__(16) uint32_t Xsu[2][64*20];
    const int b = blockIdx.z, m0 = blockIdx.y*128, n0 = blockIdx.x*64;
    const int tid = threadIdx.x, w = tid>>5, lane = tid&31;
    const int g = lane>>2, j = lane&3, wrow = w*16;
    const uint32_t* W  = g_Wb + 3*65536;
    const uint32_t* Vp = Vo + ((size_t)b*NTOK + n0)*256;
    const uint32_t oA = laneA(lane, 20), oB = laneB(lane, 20);

    float sf[8][4];
    #pragma unroll
    for (int nt=0;nt<8;nt++){ sf[nt][0]=sf[nt][1]=sf[nt][2]=sf[nt][3]=0.f; }

    #pragma unroll
    for (int i=0;i<2;i++){
        int idx = tid + i*256, m = idx>>2, seg = idx&3;
        cp16(smem_u32(&Wsu[0][m*20 + seg*4]), W + (size_t)(m0+m)*256 + seg*4);
    }
    {   int r = tid>>2, seg = tid&3;
        cp16(smem_u32(&Xsu[0][r*20 + seg*4]), Vp + (size_t)r*256 + seg*4);
    }
    CP_COMMIT;

    for (int c = 0; c < 16; c++) {
        int cur = c & 1;
        CP_WAIT0;
        __syncthreads();
        if (c < 15) {
            #pragma unroll
            for (int i=0;i<2;i++){
                int idx = tid + i*256, m = idx>>2, seg = idx&3;
                cp16(smem_u32(&Wsu[cur^1][m*20 + seg*4]),
                     W + (size_t)(m0+m)*256 + (c+1)*16 + seg*4);
            }
            {   int r = tid>>2, seg = tid&3;
                cp16(smem_u32(&Xsu[cur^1][r*20 + seg*4]),
                     Vp + (size_t)r*256 + (c+1)*16 + seg*4);
            }
            CP_COMMIT;
        }
        const uint32_t wbase = smem_u32(Wsu[cur]) + wrow*20*4 + oA;
        const uint32_t xbase = smem_u32(Xsu[cur]) + oB;
        uint32_t a0[4], a1[4], bb[4];
        ldsm4(a0, wbase);
        ldsm4(a1, wbase + 8*4);
        #pragma unroll
        for (int ntp = 0; ntp < 4; ntp++) {
            ldsm4(bb, xbase + (ntp*16*20)*4);
            mma4(sf[2*ntp],   a0, bb[0], bb[1]);
            mma4(sf[2*ntp+1], a0, bb[2], bb[3]);
            ldsm4(bb, xbase + (ntp*16*20 + 8)*4);
            mma4(sf[2*ntp],   a1, bb[0], bb[1]);
            mma4(sf[2*ntp+1], a1, bb[2], bb[3]);
        }
    }

    const int row0 = m0 + wrow + g, row1 = row0 + 8;
    const float b0v = bias[row0], b1v = bias[row1];
    const size_t ybase = (size_t)b*COUT*NTOK;
    float s0=0.f,q0=0.f,s1=0.f,q1=0.f;
    #pragma unroll
    for (int nt=0; nt<8; nt++) {
        int col = n0 + nt*8 + 2*j;
        float2 sk0 = *(const float2*)(skip + ybase + (size_t)row0*NTOK + col);
        float2 sk1 = *(const float2*)(skip + ybase + (size_t)row1*NTOK + col);
        float2 y0 = { fmaxf(sf[nt][0]+b0v,0.f)+sk0.x, fmaxf(sf[nt][1]+b0v,0.f)+sk0.y };
        float2 y1 = { fmaxf(sf[nt][2]+b1v,0.f)+sk1.x, fmaxf(sf[nt][3]+b1v,0.f)+sk1.y };
        *(float2*)(Y + ybase + (size_t)row0*NTOK + col) = y0;
        *(float2*)(Y + ybase + (size_t)row1*NTOK + col) = y1;
        s0 += y0.x + y0.y;  q0 += y0.x*y0.x + y0.y*y0.y;
        s1 += y1.x + y1.y;  q1 += y1.x*y1.x + y1.y*y1.y;
    }
    s0 += __shfl_xor_sync(0xffffffffu, s0, 1); s0 += __shfl_xor_sync(0xffffffffu, s0, 2);
    q0 += __shfl_xor_sync(0xffffffffu, q0, 1); q0 += __shfl_xor_sync(0xffffffffu, q0, 2);
    s1 += __shfl_xor_sync(0xffffffffu, s1, 1); s1 += __shfl_xor_sync(0xffffffffu, s1, 2);
    q1 += __shfl_xor_sync(0xffffffffu, q1, 1); q1 += __shfl_xor_sync(0xffffffffu, q1, 2);
    if (j == 0) {
        int part = b*32 + blockIdx.x;
        g_ps[row0*64 + part] = s0;  g_pq[row0*64 + part] = q0;
        g_ps[row1*64 + part] = s1;  g_pq[row1*64 + part] = q1;
    }
}

// ---------------- attention: flat grid 640, P kept in registers ----------
__global__ __launch_bounds__(256, 2) void attn_kernel(
    const uint32_t* __restrict__ Kb, const uint32_t* __restrict__ Qb,
    const uint32_t* __restrict__ Vb, uint32_t* __restrict__ Vo)
{
    extern __shared__ __align__(16) uint32_t smu[];
    uint32_t* Ksu = smu;                 // [128 r][36]
    uint32_t* Qsu = Ksu + 128*36;        // [2][128 c][36]
    uint32_t* Vsu = Qsu + 2*128*36;      // [2][64 d][68]

    const int ux = blockIdx.x;
    const int unit = ux >> 4, bh = ux & 15;
    const int b = bh >> 3, h = bh & 7;
    const int it = U_IT[unit], ch = U_CH[unit];
    const int i0 = it*TB;
    const int jlo = ch*4;
    const int jhi = (jlo+3 < it) ? jlo+3 : it;

    const int tid = threadIdx.x, w = tid>>5, lane = tid&31;
    const int g = lane>>2, j = lane&3, wrow = w*16;
    const uint32_t oA36 = laneA(lane, 36);
    const uint32_t oB36 = laneB(lane, 36);
    const uint32_t oB68 = laneB(lane, 68);

    const size_t rowKQ = (size_t)b*NTOK*256 + h*32;
    const size_t rowV  = ((size_t)b*FF + h*64)*1024;

    #pragma unroll
    for (int i=0;i<4;i++){
        int idx = tid + i*256, r = idx>>3, seg = idx&7;
        cp16(smem_u32(Ksu + r*36 + seg*4), Kb + rowKQ + (size_t)(i0+r)*256 + seg*4);
    }
    {
        int j0 = jlo*TB;
        #pragma unroll
        for (int i=0;i<4;i++){
            int idx = tid + i*256, r = idx>>3, seg = idx&7;
            cp16(smem_u32(Qsu + r*36 + seg*4), Qb + rowKQ + (size_t)(j0+r)*256 + seg*4);
        }
        #pragma unroll
        for (int i=0;i<4;i++){
            int idx = tid + i*256, d = idx>>4, seg = idx&15;
            cp16(smem_u32(Vsu + d*68 + seg*4), Vb + rowV + (size_t)d*1024 + (j0>>1) + seg*4);
        }
    }
    CP_COMMIT;

    float l0 = 0.f, l1 = 0.f;
    float ot[8][4];
    #pragma unroll
    for (int nt=0;nt<8;nt++){ ot[nt][0]=ot[nt][1]=ot[nt][2]=ot[nt][3]=0.f; }

    for (int jt = jlo; jt <= jhi; jt++) {
        const int cur = (jt - jlo) & 1;
        const uint32_t* Qc = Qsu + cur*128*36;
        const uint32_t* Vc = Vsu + cur*64*68;
        CP_WAIT0;
        __syncthreads();
        if (jt < jhi) {
            uint32_t* Qn = Qsu + (cur^1)*128*36;
            uint32_t* Vn = Vsu + (cur^1)*64*68;
            int j0n = (jt+1)*TB;
            #pragma unroll
            for (int i=0;i<4;i++){
                int idx = tid + i*256, r = idx>>3, seg = idx&7;
                cp16(smem_u32(Qn + r*36 + seg*4), Qb + rowKQ + (size_t)(j0n+r)*256 + seg*4);
            }
            #pragma unroll
            for (int i=0;i<4;i++){
                int idx = tid + i*256, d = idx>>4, seg = idx&15;
                cp16(smem_u32(Vn + d*68 + seg*4), Vb + rowV + (size_t)d*1024 + (j0n>>1) + seg*4);
            }
            CP_COMMIT;
        }

        const uint32_t kbase = smem_u32(Ksu) + wrow*36*4 + oA36;

        #pragma unroll
        for (int h2 = 0; h2 < 2; h2++) {
            const int chh = h2*64;
            const uint32_t qbase = smem_u32(Qc) + chh*36*4 + oB36;
            const uint32_t vbase = smem_u32(Vc) + h2*32*4 + oB68;

            // ---- S = K.Q ----
            float sf[8][4];
            #pragma unroll
            for (int nt=0;nt<8;nt++){ sf[nt][0]=sf[nt][1]=sf[nt][2]=sf[nt][3]=0.f; }
            #pragma unroll
            for (int kg = 0; kg < 4; kg++) {
                uint32_t aa[4], bb[4];
                ldsm4(aa, kbase + kg*8*4);
                #pragma unroll
                for (int ntp = 0; ntp < 4; ntp++) {
                    ldsm4(bb, qbase + (ntp*16*36 + kg*8)*4);
                    mma4(sf[2*ntp],   aa, bb[0], bb[1]);
                    mma4(sf[2*ntp+1], aa, bb[2], bb[3]);
                }
            }
            // ---- P = 2^S (K pre-scaled by log2e/16); accumulate l ----
            #pragma unroll
            for (int nt=0; nt<8; nt++) {
                sf[nt][0] = ex2f(sf[nt][0]);
                sf[nt][1] = ex2f(sf[nt][1]);
                sf[nt][2] = ex2f(sf[nt][2]);
                sf[nt][3] = ex2f(sf[nt][3]);
                l0 += sf[nt][0] + sf[nt][1];
                l1 += sf[nt][2] + sf[nt][3];
            }
            // ---- O += P.V ; P's A-fragment is S's C-fragment (no smem) ----
            #pragma unroll
            for (int kg = 0; kg < 4; kg++) {
                uint32_t aa[4], bb[4];
                aa[0] = pack_bf16(sf[2*kg  ][0], sf[2*kg  ][1]);
                aa[1] = pack_bf16(sf[2*kg  ][2], sf[2*kg  ][3]);
                aa[2] = pack_bf16(sf[2*kg+1][0], sf[2*kg+1][1]);
                aa[3] = pack_bf16(sf[2*kg+1][2], sf[2*kg+1][3]);
                #pragma unroll
                for (int ntp = 0; ntp < 4; ntp++) {
                    ldsm4(bb, vbase + (ntp*16*68 + kg*8)*4);
                    mma4(ot[2*ntp],   aa, bb[0], bb[1]);
                    mma4(ot[2*ntp+1], aa, bb[2], bb[3]);
                }
            }
        }
    }

    l0 += __shfl_xor_sync(0xffffffffu, l0, 1);
    l0 += __shfl_xor_sync(0xffffffffu, l0, 2);
    l1 += __shfl_xor_sync(0xffffffffu, l1, 1);
    l1 += __shfl_xor_sync(0xffffffffu, l1, 2);

    if (it < 4) {
        float inv0 = 1.0f/l0, inv1 = 1.0f/l1;
        size_t d0 = ((size_t)b*NTOK + i0 + wrow + g)*256 + h*32;
        size_t d1 = ((size_t)b*NTOK + i0 + wrow + g + 8)*256 + h*32;
        #pragma unroll
        for (int nt=0; nt<8; nt++) {
            Vo[d0 + nt*4 + j] = pack_bf16(ot[nt][0]*inv0, ot[nt][1]*inv0);
            Vo[d1 + nt*4 + j] = pack_bf16(ot[nt][2]*inv1, ot[nt][3]*inv1);
        }
    } else {
        const int p = ((b*NH + h)*12 + (it-4))*4 + ch;
        uint32_t* op = g_Opb + (size_t)p*TB*32;
        #pragma unroll
        for (int nt=0; nt<8; nt++) {
            op[(wrow+g  )*32 + nt*4 + j] = pack_bf16(ot[nt][0], ot[nt][1]);
            op[(wrow+g+8)*32 + nt*4 + j] = pack_bf16(ot[nt][2], ot[nt][3]);
        }
        if (j == 0) {
            g_lp[p*TB + wrow+g  ] = l0;
            g_lp[p*TB + wrow+g+8] = l1;
        }
    }
}

// ---------------- attention merge: grid 768 ------------------------------
__global__ __launch_bounds__(256) void attn_merge_kernel(uint32_t* __restrict__ Vo)
{
    const int m = blockIdx.x;
    const int grp = m & 3, mm = m >> 2;
    const int itx = mm >> 4, bh = mm & 15;
    const int b = bh >> 3, h = bh & 7;
    const int it = 4 + itx;
    const int nch = it/4 + 1;
    const int pbase = ((b*NH + h)*12 + itx)*4;
    const int t = threadIdx.x;
    const int r  = grp*32 + (t >> 3);
    const int wq = (t & 7) * 4;

    float acc[8] = {0,0,0,0,0,0,0,0};
    float l = 0.f;
    #pragma unroll 4
    for (int c = 0; c < nch; c++) {
        uint4 v = *(const uint4*)(g_Opb + (size_t)(pbase+c)*TB*32 + r*32 + wq);
        l += g_lp[(pbase+c)*TB + r];
        acc[0] += __uint_as_float(v.x << 16);
        acc[1] += __uint_as_float(v.x & 0xffff0000u);
        acc[2] += __uint_as_float(v.y << 16);
        acc[3] += __uint_as_float(v.y & 0xffff0000u);
        acc[4] += __uint_as_float(v.z << 16);
        acc[5] += __uint_as_float(v.z & 0xffff0000u);
        acc[6] += __uint_as_float(v.w << 16);
        acc[7] += __uint_as_float(v.w & 0xffff0000u);
    }
    float inv = 1.0f/l;
    uint4 o;
    o.x = pack_bf16(acc[0]*inv, acc[1]*inv);
    o.y = pack_bf16(acc[2]*inv, acc[3]*inv);
    o.z = pack_bf16(acc[4]*inv, acc[5]*inv);
    o.w = pack_bf16(acc[6]*inv, acc[7]*inv);
    *(uint4*)(Vo + ((size_t)b*NTOK + it*TB + r)*256 + h*32 + wq) = o;
}

// ---------------- BN finalize + apply ----------------
__global__ void bn_finalize_kernel() {
    const int c = blockIdx.x, t = threadIdx.x;
    float s = g_ps[c*64 + t] + g_ps[c*64 + 32 + t];
    float q = g_pq[c*64 + t] + g_pq[c*64 + 32 + t];
    #pragma unroll
    for (int o = 16; o; o >>= 1) {
        s += __shfl_xor_sync(0xffffffffu, s, o);
        q += __shfl_xor_sync(0xffffffffu, q, o);
    }
    if (t == 0) {
        float mean = s / (float)(Bb*NTOK);
        float var  = q / (float)(Bb*NTOK) - mean*mean;
        g_mean[c] = mean;
        g_istd[c] = rsqrtf(var + BN_EPS);
    }
}

__global__ __launch_bounds__(256) void bn_apply_kernel(
    const float* __restrict__ gamma, const float* __restrict__ beta,
    float* __restrict__ out)
{
    int idx = blockIdx.x*256 + threadIdx.x;
    int i0 = idx, i1 = idx + 131072;
    int c0 = (i0 >> 9) & (COUT-1);
    int c1 = (i1 >> 9) & (COUT-1);
    float4 v0 = *((const float4*)g_y + i0);
    float4 v1 = *((const float4*)g_y + i1);
    float mu0 = g_mean[c0], is0 = g_istd[c0]*gamma[c0], be0 = beta[c0];
    float mu1 = g_mean[c1], is1 = g_istd[c1]*gamma[c1], be1 = beta[c1];
    float4 o0, o1;
    o0.x = (v0.x-mu0)*is0 + be0; o0.y = (v0.y-mu0)*is0 + be0;
    o0.z = (v0.z-mu0)*is0 + be0; o0.w = (v0.w-mu0)*is0 + be0;
    o1.x = (v1.x-mu1)*is1 + be1; o1.y = (v1.y-mu1)*is1 + be1;
    o1.z = (v1.z-mu1)*is1 + be1; o1.w = (v1.w-mu1)*is1 + be1;
    *((float4*)out + i0) = o0;
    *((float4*)out + i1) = o1;
}

// ---------------- launch ----------------
extern "C" void kernel_launch(void* const* d_in, const int* in_sizes, int n_in,
                              void* d_out, int out_size)
{
    const float* x     = (const float*)d_in[0];
    const float* WK    = (const float*)d_in[1];
    const float* WQ    = (const float*)d_in[2];
    const float* WV    = (const float*)d_in[3];
    const float* Wo    = (const float*)d_in[4];
    const float* bo    = (const float*)d_in[5];
    const float* gamma = (const float*)d_in[6];
    const float* beta  = (const float*)d_in[7];
    float* out = (float*)d_out;

    uint32_t *pK, *pQ, *pV, *pVo;
    float *pY;
    cudaGetSymbolAddress((void**)&pK,  g_Kb);
    cudaGetSymbolAddress((void**)&pQ,  g_Qb);
    cudaGetSymbolAddress((void**)&pV,  g_Vb);
    cudaGetSymbolAddress((void**)&pVo, g_Vo);
    cudaGetSymbolAddress((void**)&pY,  g_y);

    prep_kernel<<<768, 256>>>(WK, WQ, WV, Wo, x);

    dim3 gq(NTOK/64, 12, Bb);
    qkv_kernel<<<gq, 256>>>(pK, pQ, pV);

    size_t smem = (size_t)(128*36 + 2*128*36 + 2*64*68) * 4;
    cudaFuncSetAttribute(attn_kernel, cudaFuncAttributeMaxDynamicSharedMemorySize, (int)smem);
    attn_kernel<<<640, 256, smem>>>(pK, pQ, pV, pVo);

    attn_merge_kernel<<<768, 256>>>(pVo);

    dim3 gp(NTOK/64, COUT/128, Bb);
    proj_kernel<<<gp, 256>>>(pVo, bo, x, pY);

    bn_finalize_kernel<<<COUT, 32>>>();
    bn_apply_kernel<<<512, 256>>>(gamma, beta, out);
}